// round 1
// baseline (speedup 1.0000x reference)
#include <cuda_runtime.h>
#include <cstdint>

#define NB   2
#define NS   2048
#define NDIM 1024
#define NH   16
#define NHD  64
#define NM   (NB * NS)   // 4096

// Scratch (allocation-free rule: __device__ globals)
__device__ float g_q[NB * NH * NS * NHD];
__device__ float g_k[NB * NH * NS * NHD];
__device__ float g_v[NB * NH * NS * NHD];
__device__ float g_o[(size_t)NM * NDIM];

// ---------------------------------------------------------------------------
// Fused QKV projection GEMM.
// C[m, h*64+e] = sum_d x[m,d] * W{q,k,v}[h,d,e] + b{q,k,v}[h,e]
// grid = (NM/64, 48): blockIdx.y -> {mat in 0..2} x {head 0..15}
// Output scattered to [B, H, S, HD] layout for the attention stage.
// ---------------------------------------------------------------------------
__global__ __launch_bounds__(256) void qkv_gemm_kernel(
    const float* __restrict__ x,
    const float* __restrict__ Wq, const float* __restrict__ bq,
    const float* __restrict__ Wk, const float* __restrict__ bk,
    const float* __restrict__ Wv, const float* __restrict__ bv)
{
    __shared__ float As[64][16];   // As[m][k]
    __shared__ float Bs[16][64];   // Bs[k][n]

    const int tid = threadIdx.x;
    const int m0  = blockIdx.x * 64;
    const int by  = blockIdx.y;
    const int mat = by >> 4;
    const int h   = by & 15;

    const float* W;
    const float* bias;
    float* out;
    if (mat == 0)      { W = Wq; bias = bq; out = g_q; }
    else if (mat == 1) { W = Wk; bias = bk; out = g_k; }
    else               { W = Wv; bias = bv; out = g_v; }
    W    += (size_t)h * NDIM * NHD;   // [1024, 64] row-major slice for this head
    bias += h * NHD;

    const int ty = tid >> 4, tx = tid & 15;
    const int am = tid >> 2, ak = (tid & 3) * 4;      // A loads: 64 rows x 16 cols
    const int br = tid >> 4, bc = (tid & 15) * 4;     // B loads: 16 rows x 64 cols

    float acc[4][4] = {};

    for (int k0 = 0; k0 < NDIM; k0 += 16) {
        float4 av  = *(const float4*)&x[(size_t)(m0 + am) * NDIM + k0 + ak];
        float4 bv4 = *(const float4*)&W[(size_t)(k0 + br) * NHD + bc];
        *(float4*)&As[am][ak] = av;
        *(float4*)&Bs[br][bc] = bv4;
        __syncthreads();

        #pragma unroll
        for (int kk = 0; kk < 16; kk++) {
            float a[4];
            #pragma unroll
            for (int i = 0; i < 4; i++) a[i] = As[ty * 4 + i][kk];
            float4 b = *(float4*)&Bs[kk][tx * 4];
            #pragma unroll
            for (int i = 0; i < 4; i++) {
                acc[i][0] += a[i] * b.x;
                acc[i][1] += a[i] * b.y;
                acc[i][2] += a[i] * b.z;
                acc[i][3] += a[i] * b.w;
            }
        }
        __syncthreads();
    }

    float4 bb = *(const float4*)&bias[tx * 4];
    #pragma unroll
    for (int i = 0; i < 4; i++) {
        int gm = m0 + ty * 4 + i;
        int b_ = gm >> 11;        // / NS
        int s_ = gm & (NS - 1);
        float4 r;
        r.x = acc[i][0] + bb.x;
        r.y = acc[i][1] + bb.y;
        r.z = acc[i][2] + bb.z;
        r.w = acc[i][3] + bb.w;
        size_t off = ((((size_t)b_ * NH + h) * NS + s_) * NHD) + tx * 4;
        *(float4*)&out[off] = r;
    }
}

// ---------------------------------------------------------------------------
// Causal flash attention, fp32, 64x64 tiles. grid = (NS/64, NB*NH).
// Online softmax; K stored transposed in smem for conflict-free score reads;
// P staged through smem for the PV product. Output written as [B, S, H*HD].
// ---------------------------------------------------------------------------
__global__ __launch_bounds__(256) void flash_kernel()
{
    extern __shared__ float sm[];
    float* Qs  = sm;                  // [64][64]
    float* Kts = sm + 64 * 64;        // [64][68] k-major: Kts[k*68 + c]
    float* Vs  = Kts + 64 * 68;       // [64][64]
    float* Ps  = Vs + 64 * 64;        // [64][64]

    const int tid = threadIdx.x;
    const int ty = tid >> 4, tx = tid & 15;
    const int qt = blockIdx.x;
    const int bh = blockIdx.y;

    const float* Qb = g_q + (size_t)bh * NS * NHD + (size_t)qt * 64 * NHD;
    const float* Kb = g_k + (size_t)bh * NS * NHD;
    const float* Vb = g_v + (size_t)bh * NS * NHD;

    #pragma unroll
    for (int it = 0; it < 4; it++) {
        int idx = tid + it * 256;
        int r = idx >> 4, c4 = (idx & 15) * 4;
        *(float4*)&Qs[r * 64 + c4] = *(const float4*)&Qb[r * 64 + c4];
    }

    float m_run[4], l_run[4], acc[4][4];
    #pragma unroll
    for (int i = 0; i < 4; i++) {
        m_run[i] = -1e30f;
        l_run[i] = 0.0f;
        #pragma unroll
        for (int jj = 0; jj < 4; jj++) acc[i][jj] = 0.0f;
    }

    for (int j = 0; j <= qt; j++) {
        __syncthreads();   // previous tile's PV reads done before overwrite
        #pragma unroll
        for (int it = 0; it < 4; it++) {
            int idx = tid + it * 256;
            int r = idx >> 4, c4 = (idx & 15) * 4;
            float4 kv = *(const float4*)&Kb[(size_t)(j * 64 + r) * NHD + c4];
            Kts[(c4 + 0) * 68 + r] = kv.x;
            Kts[(c4 + 1) * 68 + r] = kv.y;
            Kts[(c4 + 2) * 68 + r] = kv.z;
            Kts[(c4 + 3) * 68 + r] = kv.w;
            *(float4*)&Vs[r * 64 + c4] =
                *(const float4*)&Vb[(size_t)(j * 64 + r) * NHD + c4];
        }
        __syncthreads();

        // Scores: s[r][c] = sum_k Q[r][k] * K[c][k]
        float s[4][4] = {};
        #pragma unroll 8
        for (int k = 0; k < 64; k++) {
            float a[4];
            #pragma unroll
            for (int i = 0; i < 4; i++) a[i] = Qs[(ty * 4 + i) * 64 + k];
            float4 b = *(float4*)&Kts[k * 68 + tx * 4];
            #pragma unroll
            for (int i = 0; i < 4; i++) {
                s[i][0] += a[i] * b.x;
                s[i][1] += a[i] * b.y;
                s[i][2] += a[i] * b.z;
                s[i][3] += a[i] * b.w;
            }
        }

        const float sc = 0.125f;   // 1/sqrt(64)
        #pragma unroll
        for (int i = 0; i < 4; i++)
            #pragma unroll
            for (int jj = 0; jj < 4; jj++) s[i][jj] *= sc;

        if (j == qt) {   // diagonal tile: apply causal mask
            #pragma unroll
            for (int i = 0; i < 4; i++)
                #pragma unroll
                for (int jj = 0; jj < 4; jj++)
                    if (tx * 4 + jj > ty * 4 + i) s[i][jj] = -1e30f;
        }

        float p[4][4];
        #pragma unroll
        for (int i = 0; i < 4; i++) {
            float mt = fmaxf(fmaxf(s[i][0], s[i][1]), fmaxf(s[i][2], s[i][3]));
            #pragma unroll
            for (int o = 8; o >= 1; o >>= 1)
                mt = fmaxf(mt, __shfl_xor_sync(0xffffffffu, mt, o));
            float mnew = fmaxf(m_run[i], mt);
            float rs = 0.0f;
            #pragma unroll
            for (int jj = 0; jj < 4; jj++) {
                p[i][jj] = __expf(s[i][jj] - mnew);
                rs += p[i][jj];
            }
            #pragma unroll
            for (int o = 8; o >= 1; o >>= 1)
                rs += __shfl_xor_sync(0xffffffffu, rs, o);
            float alpha = __expf(m_run[i] - mnew);
            l_run[i] = l_run[i] * alpha + rs;
            m_run[i] = mnew;
            #pragma unroll
            for (int jj = 0; jj < 4; jj++) acc[i][jj] *= alpha;
        }

        #pragma unroll
        for (int i = 0; i < 4; i++)
            *(float4*)&Ps[(ty * 4 + i) * 64 + tx * 4] =
                make_float4(p[i][0], p[i][1], p[i][2], p[i][3]);
        __syncthreads();

        // acc[r][hd] += sum_c P[r][c] * V[c][hd]
        #pragma unroll 8
        for (int c = 0; c < 64; c++) {
            float4 v = *(float4*)&Vs[c * 64 + tx * 4];
            #pragma unroll
            for (int i = 0; i < 4; i++) {
                float pr = Ps[(ty * 4 + i) * 64 + c];
                acc[i][0] += pr * v.x;
                acc[i][1] += pr * v.y;
                acc[i][2] += pr * v.z;
                acc[i][3] += pr * v.w;
            }
        }
    }

    const int b_ = bh >> 4, h = bh & 15;
    #pragma unroll
    for (int i = 0; i < 4; i++) {
        float inv = 1.0f / l_run[i];
        int s_ = qt * 64 + ty * 4 + i;
        size_t gm = (size_t)b_ * NS + s_;
        float4 r = make_float4(acc[i][0] * inv, acc[i][1] * inv,
                               acc[i][2] * inv, acc[i][3] * inv);
        *(float4*)&g_o[gm * NDIM + h * 64 + tx * 4] = r;
    }
}

// ---------------------------------------------------------------------------
// Output projection: out[m,n] = sum_k g_o[m,k] * Wo[k,n] + bo[n]
// grid = (NM/64, NDIM/64)
// ---------------------------------------------------------------------------
__global__ __launch_bounds__(256) void proj_gemm_kernel(
    const float* __restrict__ Wo, const float* __restrict__ bo,
    float* __restrict__ out)
{
    __shared__ float As[64][16];
    __shared__ float Bs[16][64];

    const int tid = threadIdx.x;
    const int m0 = blockIdx.x * 64;
    const int n0 = blockIdx.y * 64;

    const int ty = tid >> 4, tx = tid & 15;
    const int am = tid >> 2, ak = (tid & 3) * 4;
    const int br = tid >> 4, bc = (tid & 15) * 4;

    float acc[4][4] = {};

    for (int k0 = 0; k0 < NDIM; k0 += 16) {
        float4 av  = *(const float4*)&g_o[(size_t)(m0 + am) * NDIM + k0 + ak];
        float4 bv4 = *(const float4*)&Wo[(size_t)(k0 + br) * NDIM + n0 + bc];
        *(float4*)&As[am][ak] = av;
        *(float4*)&Bs[br][bc] = bv4;
        __syncthreads();

        #pragma unroll
        for (int kk = 0; kk < 16; kk++) {
            float a[4];
            #pragma unroll
            for (int i = 0; i < 4; i++) a[i] = As[ty * 4 + i][kk];
            float4 b = *(float4*)&Bs[kk][tx * 4];
            #pragma unroll
            for (int i = 0; i < 4; i++) {
                acc[i][0] += a[i] * b.x;
                acc[i][1] += a[i] * b.y;
                acc[i][2] += a[i] * b.z;
                acc[i][3] += a[i] * b.w;
            }
        }
        __syncthreads();
    }

    float4 bb = *(const float4*)&bo[n0 + tx * 4];
    #pragma unroll
    for (int i = 0; i < 4; i++) {
        int gm = m0 + ty * 4 + i;
        float4 r;
        r.x = acc[i][0] + bb.x;
        r.y = acc[i][1] + bb.y;
        r.z = acc[i][2] + bb.z;
        r.w = acc[i][3] + bb.w;
        *(float4*)&out[(size_t)gm * NDIM + n0 + tx * 4] = r;
    }
}

extern "C" void kernel_launch(void* const* d_in, const int* in_sizes, int n_in,
                              void* d_out, int out_size)
{
    const float* x  = (const float*)d_in[0];
    const float* Wq = (const float*)d_in[1];
    const float* bq = (const float*)d_in[2];
    const float* Wk = (const float*)d_in[3];
    const float* bk = (const float*)d_in[4];
    const float* Wv = (const float*)d_in[5];
    const float* bv = (const float*)d_in[6];
    const float* Wo = (const float*)d_in[7];
    const float* bo = (const float*)d_in[8];
    float* out = (float*)d_out;

    // 66560 B dynamic smem for flash (> 48KB default): Qs + Kts(padded) + Vs + Ps
    const int flash_smem = (64 * 64 + 64 * 68 + 64 * 64 + 64 * 64) * (int)sizeof(float);
    cudaFuncSetAttribute(flash_kernel,
                         cudaFuncAttributeMaxDynamicSharedMemorySize, flash_smem);

    qkv_gemm_kernel<<<dim3(NM / 64, 48), 256>>>(x, Wq, bq, Wk, bk, Wv, bv);
    flash_kernel<<<dim3(NS / 64, NB * NH), 256, flash_smem>>>();
    proj_gemm_kernel<<<dim3(NM / 64, NDIM / 64), 256>>>(Wo, bo, out);
}

// round 3
// speedup vs baseline: 1.3842x; 1.3842x over previous
#include <cuda_runtime.h>
#include <cuda_bf16.h>
#include <cstdint>

#define NB   2
#define NS   2048
#define NDIM 1024
#define NH   16
#define NHD  64
#define NM   (NB * NS)     // 4096
#define NQKV 3072          // 3 * NH * NHD

// ---------------------------------------------------------------------------
// Scratch (__device__ globals; allocation-free rule)
// ---------------------------------------------------------------------------
__device__ float g_q[NB * NH * NS * NHD];
__device__ float g_k[NB * NH * NS * NHD];
__device__ float g_v[NB * NH * NS * NHD];
__device__ float g_o[(size_t)NM * NDIM];

__device__ __nv_bfloat16 g_xh[(size_t)NM * NDIM];
__device__ __nv_bfloat16 g_xl[(size_t)NM * NDIM];
__device__ __nv_bfloat16 g_oh[(size_t)NM * NDIM];
__device__ __nv_bfloat16 g_ol[(size_t)NM * NDIM];
__device__ __nv_bfloat16 g_wqh[(size_t)NQKV * NDIM];   // QKV weights, K-major [3072][1024]
__device__ __nv_bfloat16 g_wql[(size_t)NQKV * NDIM];
__device__ __nv_bfloat16 g_woh[(size_t)NDIM * NDIM];   // Wo transposed, K-major [1024][1024]
__device__ __nv_bfloat16 g_wol[(size_t)NDIM * NDIM];
__device__ float g_bqkv[NQKV];

__device__ __forceinline__ uint32_t smem_to_u32(const void* p) {
    uint32_t a;
    asm("{ .reg .u64 t; cvta.to.shared.u64 t, %1; cvt.u32.u64 %0, t; }"
        : "=r"(a) : "l"(p));
    return a;
}

// ---------------------------------------------------------------------------
// Conversion kernels
// ---------------------------------------------------------------------------
__global__ void split_kernel(const float4* __restrict__ src,
                             __nv_bfloat162* __restrict__ dh,
                             __nv_bfloat162* __restrict__ dl, int n4)
{
    int i = blockIdx.x * blockDim.x + threadIdx.x;
    if (i >= n4) return;
    float4 v = src[i];
    __nv_bfloat16 hx = __float2bfloat16(v.x), hy = __float2bfloat16(v.y);
    __nv_bfloat16 hz = __float2bfloat16(v.z), hw = __float2bfloat16(v.w);
    __nv_bfloat16 lx = __float2bfloat16(v.x - __bfloat162float(hx));
    __nv_bfloat16 ly = __float2bfloat16(v.y - __bfloat162float(hy));
    __nv_bfloat16 lz = __float2bfloat16(v.z - __bfloat162float(hz));
    __nv_bfloat16 lw = __float2bfloat16(v.w - __bfloat162float(hw));
    dh[2 * i]     = __halves2bfloat162(hx, hy);
    dh[2 * i + 1] = __halves2bfloat162(hz, hw);
    dl[2 * i]     = __halves2bfloat162(lx, ly);
    dl[2 * i + 1] = __halves2bfloat162(lz, lw);
}

// W{q,k,v}[h][d][e] -> g_wq{h,l}[(mat*16+h)*64+e][d]  (K-major, split), + bias concat
__global__ void qkv_w_transpose(const float* __restrict__ Wq, const float* __restrict__ Wk,
                                const float* __restrict__ Wv, const float* __restrict__ bq,
                                const float* __restrict__ bk, const float* __restrict__ bv)
{
    __shared__ float sm[32][33];
    int z = blockIdx.z, mat = z >> 4, h = z & 15;
    const float* W = (mat == 0 ? Wq : mat == 1 ? Wk : Wv) + (size_t)h * NDIM * NHD;
    const float* bias = (mat == 0 ? bq : mat == 1 ? bk : bv) + h * NHD;
    int d0 = blockIdx.x * 32, e0 = blockIdx.y * 32;
    int tx = threadIdx.x, ty = threadIdx.y;
    sm[ty][tx] = W[(size_t)(d0 + ty) * NHD + e0 + tx];
    __syncthreads();
    float v = sm[tx][ty];
    __nv_bfloat16 hv = __float2bfloat16(v);
    __nv_bfloat16 lv = __float2bfloat16(v - __bfloat162float(hv));
    size_t row = (size_t)z * 64 + e0 + ty;
    g_wqh[row * NDIM + d0 + tx] = hv;
    g_wql[row * NDIM + d0 + tx] = lv;
    if (blockIdx.x == 0 && tx == 0) g_bqkv[z * 64 + e0 + ty] = bias[e0 + ty];
}

// Wo[k][n] -> g_wo{h,l}[n][k]
__global__ void wo_transpose(const float* __restrict__ Wo)
{
    __shared__ float sm[32][33];
    int k0 = blockIdx.x * 32, n0 = blockIdx.y * 32;
    int tx = threadIdx.x, ty = threadIdx.y;
    sm[ty][tx] = Wo[(size_t)(k0 + ty) * NDIM + n0 + tx];
    __syncthreads();
    float v = sm[tx][ty];
    __nv_bfloat16 hv = __float2bfloat16(v);
    __nv_bfloat16 lv = __float2bfloat16(v - __bfloat162float(hv));
    g_woh[(size_t)(n0 + ty) * NDIM + k0 + tx] = hv;
    g_wol[(size_t)(n0 + ty) * NDIM + k0 + tx] = lv;
}

// ---------------------------------------------------------------------------
// HMMA (mma.sync m16n8k16 bf16) split GEMM.
// C[m,n] = sum_k A[m,k]*B[n,k]  with A = Ah+Al, B = Bh+Bl; 3 products.
// Block tile 128x128, 8 warps (2x4), warp tile 64x32, K-tile 32.
// mode 0: A = x (split), B = QKV weights -> scatter to g_q/g_k/g_v (+g_bqkv)
// mode 1: A = attn out (split), B = Wo^T -> out (+bias)
// ---------------------------------------------------------------------------
#define KT   32
#define SPAD 40   // smem K stride (bf16 elems): conflict-free ldmatrix, 16B-aligned

__device__ __forceinline__ void ldsm_x4(uint32_t* r, uint32_t addr) {
    asm volatile("ldmatrix.sync.aligned.m8n8.x4.shared.b16 {%0,%1,%2,%3}, [%4];"
        : "=r"(r[0]), "=r"(r[1]), "=r"(r[2]), "=r"(r[3]) : "r"(addr));
}
__device__ __forceinline__ void ldsm_x2(uint32_t* r, uint32_t addr) {
    asm volatile("ldmatrix.sync.aligned.m8n8.x2.shared.b16 {%0,%1}, [%2];"
        : "=r"(r[0]), "=r"(r[1]) : "r"(addr));
}
__device__ __forceinline__ void mma_bf16(float* c, const uint32_t* a, const uint32_t* b) {
    asm volatile(
        "mma.sync.aligned.m16n8k16.row.col.f32.bf16.bf16.f32 "
        "{%0,%1,%2,%3}, {%4,%5,%6,%7}, {%8,%9}, {%0,%1,%2,%3};"
        : "+f"(c[0]), "+f"(c[1]), "+f"(c[2]), "+f"(c[3])
        : "r"(a[0]), "r"(a[1]), "r"(a[2]), "r"(a[3]), "r"(b[0]), "r"(b[1]));
}

__global__ __launch_bounds__(256) void gemm_mma_kernel(const float* __restrict__ bias,
                                                       float* __restrict__ out, int mode)
{
    __shared__ __align__(16) __nv_bfloat16 As[128 * SPAD];
    __shared__ __align__(16) __nv_bfloat16 Bs[128 * SPAD];

    const int tid = threadIdx.x, wid = tid >> 5, lane = tid & 31;
    const int m0 = blockIdx.x * 128, n0 = blockIdx.y * 128;
    const int warp_m0 = (wid >> 2) * 64;    // 0 / 64
    const int warp_n0 = (wid & 3) * 32;     // 0 / 32 / 64 / 96

    const __nv_bfloat16 *Ah, *Al, *Bh, *Bl;
    if (mode == 0) { Ah = g_xh; Al = g_xl; Bh = g_wqh; Bl = g_wql; }
    else           { Ah = g_oh; Al = g_ol; Bh = g_woh; Bl = g_wol; }
    const __nv_bfloat16* Aseg[3] = {Ah, Ah, Al};
    const __nv_bfloat16* Bseg[3] = {Bh, Bl, Bh};

    // gmem load mapping: 512 16B-chunks per tile; thread covers chunks tid, tid+256
    const int rowA = tid >> 2;            // 0..63 (and +64)
    const int col8 = (tid & 3) * 8;       // bf16 col within 32

    // smem store offsets (bf16 elems)
    const uint32_t stoff0 = rowA * SPAD + col8;
    const uint32_t stoff1 = (rowA + 64) * SPAD + col8;

    // ldmatrix address bases
    const uint32_t sA = smem_to_u32(As);
    const uint32_t sB = smem_to_u32(Bs);
    const int lm = lane & 15, lq = lane >> 4;      // A: row-within, k-half
    const int l8 = lane & 7,  lb = (lane >> 3) & 1; // B: n-row, k-half
    const uint32_t aBase = sA + ((warp_m0 + lm) * SPAD + lq * 8) * 2;
    const uint32_t bBase = sB + ((warp_n0 + l8) * SPAD + lb * 8) * 2;

    float acc[4][4][4];
    #pragma unroll
    for (int i = 0; i < 4; i++)
        #pragma unroll
        for (int j = 0; j < 4; j++)
            #pragma unroll
            for (int q = 0; q < 4; q++) acc[i][j][q] = 0.0f;

    // prefetch iter 0
    uint4 ra0, ra1, rb0, rb1;
    {
        const __nv_bfloat16* pa = Aseg[0];
        const __nv_bfloat16* pb = Bseg[0];
        ra0 = *(const uint4*)(pa + (size_t)(m0 + rowA) * NDIM + col8);
        ra1 = *(const uint4*)(pa + (size_t)(m0 + rowA + 64) * NDIM + col8);
        rb0 = *(const uint4*)(pb + (size_t)(n0 + rowA) * NDIM + col8);
        rb1 = *(const uint4*)(pb + (size_t)(n0 + rowA + 64) * NDIM + col8);
    }

    const int NIT = 3 * (NDIM / KT);   // 96
    for (int it = 0; it < NIT; ++it) {
        __syncthreads();   // previous tile fully consumed
        *(uint4*)(As + stoff0) = ra0;
        *(uint4*)(As + stoff1) = ra1;
        *(uint4*)(Bs + stoff0) = rb0;
        *(uint4*)(Bs + stoff1) = rb1;
        __syncthreads();

        if (it + 1 < NIT) {
            const int nx = it + 1;
            const int seg = nx >> 5;
            const int k0 = (nx & 31) * KT;
            const __nv_bfloat16* pa = Aseg[seg];
            const __nv_bfloat16* pb = Bseg[seg];
            ra0 = *(const uint4*)(pa + (size_t)(m0 + rowA) * NDIM + k0 + col8);
            ra1 = *(const uint4*)(pa + (size_t)(m0 + rowA + 64) * NDIM + k0 + col8);
            rb0 = *(const uint4*)(pb + (size_t)(n0 + rowA) * NDIM + k0 + col8);
            rb1 = *(const uint4*)(pb + (size_t)(n0 + rowA + 64) * NDIM + k0 + col8);
        }

        #pragma unroll
        for (int kk = 0; kk < 2; ++kk) {
            uint32_t a[4][4], b[4][2];
            #pragma unroll
            for (int mt = 0; mt < 4; ++mt)
                ldsm_x4(a[mt], aBase + (mt * 16 * SPAD + kk * 16) * 2);
            #pragma unroll
            for (int nt = 0; nt < 4; ++nt)
                ldsm_x2(b[nt], bBase + (nt * 8 * SPAD + kk * 16) * 2);
            #pragma unroll
            for (int mt = 0; mt < 4; ++mt)
                #pragma unroll
                for (int nt = 0; nt < 4; ++nt)
                    mma_bf16(acc[mt][nt], a[mt], b[nt]);
        }
    }

    // Epilogue: direct float2 stores with bias (+ QKV scatter for mode 0)
    const int mrow = lane >> 2;              // 0..7
    const int ncol = (lane & 3) * 2;
    #pragma unroll
    for (int nt = 0; nt < 4; ++nt) {
        const int gn = n0 + warp_n0 + nt * 8 + ncol;
        float2 bb;
        if (mode == 0) bb = *(const float2*)&g_bqkv[gn];
        else           bb = *(const float2*)&bias[gn];
        #pragma unroll
        for (int mt = 0; mt < 4; ++mt) {
            #pragma unroll
            for (int half = 0; half < 2; ++half) {
                const int m = m0 + warp_m0 + mt * 16 + mrow + half * 8;
                float2 v;
                v.x = acc[mt][nt][half * 2 + 0] + bb.x;
                v.y = acc[mt][nt][half * 2 + 1] + bb.y;
                if (mode == 0) {
                    const int slot = gn >> 6;           // mat*16 + h
                    const int mat = slot >> 4, h = slot & 15, e = gn & 63;
                    const int b_ = m >> 11, s_ = m & (NS - 1);
                    float* dst = (mat == 0 ? g_q : mat == 1 ? g_k : g_v);
                    *(float2*)&dst[((((size_t)b_ * NH + h) * NS + s_) * NHD) + e] = v;
                } else {
                    *(float2*)&out[(size_t)m * NDIM + gn] = v;
                }
            }
        }
    }
}

// ---------------------------------------------------------------------------
// Causal flash attention, fp32, 64x64 tiles (unchanged, known-good from R1).
// ---------------------------------------------------------------------------
__global__ __launch_bounds__(256) void flash_kernel()
{
    extern __shared__ float sm[];
    float* Qs  = sm;
    float* Kts = sm + 64 * 64;
    float* Vs  = Kts + 64 * 68;
    float* Ps  = Vs + 64 * 64;

    const int tid = threadIdx.x;
    const int ty = tid >> 4, tx = tid & 15;
    const int qt = blockIdx.x;
    const int bh = blockIdx.y;

    const float* Qb = g_q + (size_t)bh * NS * NHD + (size_t)qt * 64 * NHD;
    const float* Kb = g_k + (size_t)bh * NS * NHD;
    const float* Vb = g_v + (size_t)bh * NS * NHD;

    #pragma unroll
    for (int it = 0; it < 4; it++) {
        int idx = tid + it * 256;
        int r = idx >> 4, c4 = (idx & 15) * 4;
        *(float4*)&Qs[r * 64 + c4] = *(const float4*)&Qb[r * 64 + c4];
    }

    float m_run[4], l_run[4], acc[4][4];
    #pragma unroll
    for (int i = 0; i < 4; i++) {
        m_run[i] = -1e30f; l_run[i] = 0.0f;
        #pragma unroll
        for (int jj = 0; jj < 4; jj++) acc[i][jj] = 0.0f;
    }

    for (int j = 0; j <= qt; j++) {
        __syncthreads();
        #pragma unroll
        for (int it = 0; it < 4; it++) {
            int idx = tid + it * 256;
            int r = idx >> 4, c4 = (idx & 15) * 4;
            float4 kv = *(const float4*)&Kb[(size_t)(j * 64 + r) * NHD + c4];
            Kts[(c4 + 0) * 68 + r] = kv.x;
            Kts[(c4 + 1) * 68 + r] = kv.y;
            Kts[(c4 + 2) * 68 + r] = kv.z;
            Kts[(c4 + 3) * 68 + r] = kv.w;
            *(float4*)&Vs[r * 64 + c4] =
                *(const float4*)&Vb[(size_t)(j * 64 + r) * NHD + c4];
        }
        __syncthreads();

        float s[4][4] = {};
        #pragma unroll 8
        for (int k = 0; k < 64; k++) {
            float a[4];
            #pragma unroll
            for (int i = 0; i < 4; i++) a[i] = Qs[(ty * 4 + i) * 64 + k];
            float4 b = *(float4*)&Kts[k * 68 + tx * 4];
            #pragma unroll
            for (int i = 0; i < 4; i++) {
                s[i][0] += a[i] * b.x; s[i][1] += a[i] * b.y;
                s[i][2] += a[i] * b.z; s[i][3] += a[i] * b.w;
            }
        }

        const float sc = 0.125f;
        #pragma unroll
        for (int i = 0; i < 4; i++)
            #pragma unroll
            for (int jj = 0; jj < 4; jj++) s[i][jj] *= sc;

        if (j == qt) {
            #pragma unroll
            for (int i = 0; i < 4; i++)
                #pragma unroll
                for (int jj = 0; jj < 4; jj++)
                    if (tx * 4 + jj > ty * 4 + i) s[i][jj] = -1e30f;
        }

        float p[4][4];
        #pragma unroll
        for (int i = 0; i < 4; i++) {
            float mt = fmaxf(fmaxf(s[i][0], s[i][1]), fmaxf(s[i][2], s[i][3]));
            #pragma unroll
            for (int o = 8; o >= 1; o >>= 1)
                mt = fmaxf(mt, __shfl_xor_sync(0xffffffffu, mt, o));
            float mnew = fmaxf(m_run[i], mt);
            float rs = 0.0f;
            #pragma unroll
            for (int jj = 0; jj < 4; jj++) {
                p[i][jj] = __expf(s[i][jj] - mnew);
                rs += p[i][jj];
            }
            #pragma unroll
            for (int o = 8; o >= 1; o >>= 1)
                rs += __shfl_xor_sync(0xffffffffu, rs, o);
            float alpha = __expf(m_run[i] - mnew);
            l_run[i] = l_run[i] * alpha + rs;
            m_run[i] = mnew;
            #pragma unroll
            for (int jj = 0; jj < 4; jj++) acc[i][jj] *= alpha;
        }

        #pragma unroll
        for (int i = 0; i < 4; i++)
            *(float4*)&Ps[(ty * 4 + i) * 64 + tx * 4] =
                make_float4(p[i][0], p[i][1], p[i][2], p[i][3]);
        __syncthreads();

        #pragma unroll 8
        for (int c = 0; c < 64; c++) {
            float4 v = *(float4*)&Vs[c * 64 + tx * 4];
            #pragma unroll
            for (int i = 0; i < 4; i++) {
                float pr = Ps[(ty * 4 + i) * 64 + c];
                acc[i][0] += pr * v.x; acc[i][1] += pr * v.y;
                acc[i][2] += pr * v.z; acc[i][3] += pr * v.w;
            }
        }
    }

    const int b_ = bh >> 4, h = bh & 15;
    #pragma unroll
    for (int i = 0; i < 4; i++) {
        float inv = 1.0f / l_run[i];
        int s_ = qt * 64 + ty * 4 + i;
        size_t gm = (size_t)b_ * NS + s_;
        float4 r = make_float4(acc[i][0] * inv, acc[i][1] * inv,
                               acc[i][2] * inv, acc[i][3] * inv);
        *(float4*)&g_o[gm * NDIM + h * 64 + tx * 4] = r;
    }
}

// ---------------------------------------------------------------------------
extern "C" void kernel_launch(void* const* d_in, const int* in_sizes, int n_in,
                              void* d_out, int out_size)
{
    const float* x  = (const float*)d_in[0];
    const float* Wq = (const float*)d_in[1];
    const float* bq = (const float*)d_in[2];
    const float* Wk = (const float*)d_in[3];
    const float* bk = (const float*)d_in[4];
    const float* Wv = (const float*)d_in[5];
    const float* bv = (const float*)d_in[6];
    const float* Wo = (const float*)d_in[7];
    const float* bo = (const float*)d_in[8];
    float* out = (float*)d_out;

    const int flash_smem = (64 * 64 + 64 * 68 + 64 * 64 + 64 * 64) * (int)sizeof(float);
    cudaFuncSetAttribute(flash_kernel,
                         cudaFuncAttributeMaxDynamicSharedMemorySize, flash_smem);

    __nv_bfloat162 *xh2, *xl2, *oh2, *ol2;
    float* go;
    cudaGetSymbolAddress((void**)&xh2, g_xh);
    cudaGetSymbolAddress((void**)&xl2, g_xl);
    cudaGetSymbolAddress((void**)&oh2, g_oh);
    cudaGetSymbolAddress((void**)&ol2, g_ol);
    cudaGetSymbolAddress((void**)&go, g_o);

    const int n4 = NM * NDIM / 4;   // 1048576
    split_kernel<<<n4 / 256, 256>>>((const float4*)x, xh2, xl2, n4);
    qkv_w_transpose<<<dim3(32, 2, 48), dim3(32, 32)>>>(Wq, Wk, Wv, bq, bk, bv);
    wo_transpose<<<dim3(32, 32), dim3(32, 32)>>>(Wo);

    gemm_mma_kernel<<<dim3(NM / 128, NQKV / 128), 256>>>(nullptr, nullptr, 0);
    flash_kernel<<<dim3(NS / 64, NB * NH), 256, flash_smem>>>();
    split_kernel<<<n4 / 256, 256>>>((const float4*)go, oh2, ol2, n4);
    gemm_mma_kernel<<<dim3(NM / 128, NDIM / 128), 256>>>(bo, out, 1);
}

// round 4
// speedup vs baseline: 2.3222x; 1.6777x over previous
#include <cuda_runtime.h>
#include <cuda_bf16.h>
#include <cstdint>

#define NB   2
#define NS   2048
#define NDIM 1024
#define NH   16
#define NHD  64
#define NM   (NB * NS)     // 4096
#define NQKV 3072          // 3 * NH * NHD

// ---------------------------------------------------------------------------
// Scratch (__device__ globals; allocation-free rule)
// ---------------------------------------------------------------------------
__device__ __nv_bfloat16 g_qh[NB * NH * NS * NHD];
__device__ __nv_bfloat16 g_ql[NB * NH * NS * NHD];
__device__ __nv_bfloat16 g_kh[NB * NH * NS * NHD];
__device__ __nv_bfloat16 g_kl[NB * NH * NS * NHD];
__device__ __nv_bfloat16 g_vh[NB * NH * NS * NHD];
__device__ __nv_bfloat16 g_vl[NB * NH * NS * NHD];

__device__ __nv_bfloat16 g_xh[(size_t)NM * NDIM];
__device__ __nv_bfloat16 g_xl[(size_t)NM * NDIM];
__device__ __nv_bfloat16 g_oh[(size_t)NM * NDIM];
__device__ __nv_bfloat16 g_ol[(size_t)NM * NDIM];
__device__ __nv_bfloat16 g_wqh[(size_t)NQKV * NDIM];   // QKV weights, K-major [3072][1024]
__device__ __nv_bfloat16 g_wql[(size_t)NQKV * NDIM];
__device__ __nv_bfloat16 g_woh[(size_t)NDIM * NDIM];   // Wo transposed, K-major [1024][1024]
__device__ __nv_bfloat16 g_wol[(size_t)NDIM * NDIM];
__device__ float g_bqkv[NQKV];

__device__ __forceinline__ uint32_t smem_to_u32(const void* p) {
    uint32_t a;
    asm("{ .reg .u64 t; cvta.to.shared.u64 t, %1; cvt.u32.u64 %0, t; }"
        : "=r"(a) : "l"(p));
    return a;
}

__device__ __forceinline__ void ldsm_x4(uint32_t* r, uint32_t addr) {
    asm volatile("ldmatrix.sync.aligned.m8n8.x4.shared.b16 {%0,%1,%2,%3}, [%4];"
        : "=r"(r[0]), "=r"(r[1]), "=r"(r[2]), "=r"(r[3]) : "r"(addr));
}
__device__ __forceinline__ void ldsm_x4_t(uint32_t* r, uint32_t addr) {
    asm volatile("ldmatrix.sync.aligned.m8n8.x4.trans.shared.b16 {%0,%1,%2,%3}, [%4];"
        : "=r"(r[0]), "=r"(r[1]), "=r"(r[2]), "=r"(r[3]) : "r"(addr));
}
__device__ __forceinline__ void ldsm_x2(uint32_t* r, uint32_t addr) {
    asm volatile("ldmatrix.sync.aligned.m8n8.x2.shared.b16 {%0,%1}, [%2];"
        : "=r"(r[0]), "=r"(r[1]) : "r"(addr));
}
__device__ __forceinline__ void mma_bf16(float* c, const uint32_t* a, const uint32_t* b) {
    asm volatile(
        "mma.sync.aligned.m16n8k16.row.col.f32.bf16.bf16.f32 "
        "{%0,%1,%2,%3}, {%4,%5,%6,%7}, {%8,%9}, {%0,%1,%2,%3};"
        : "+f"(c[0]), "+f"(c[1]), "+f"(c[2]), "+f"(c[3])
        : "r"(a[0]), "r"(a[1]), "r"(a[2]), "r"(a[3]), "r"(b[0]), "r"(b[1]));
}

__device__ __forceinline__ uint32_t pack_bf2(float x, float y) {
    __nv_bfloat162 h = __halves2bfloat162(__float2bfloat16(x), __float2bfloat16(y));
    return *(uint32_t*)&h;
}

// ---------------------------------------------------------------------------
// Conversion kernels
// ---------------------------------------------------------------------------
__global__ void split_kernel(const float4* __restrict__ src,
                             __nv_bfloat162* __restrict__ dh,
                             __nv_bfloat162* __restrict__ dl, int n4)
{
    int i = blockIdx.x * blockDim.x + threadIdx.x;
    if (i >= n4) return;
    float4 v = src[i];
    __nv_bfloat16 hx = __float2bfloat16(v.x), hy = __float2bfloat16(v.y);
    __nv_bfloat16 hz = __float2bfloat16(v.z), hw = __float2bfloat16(v.w);
    __nv_bfloat16 lx = __float2bfloat16(v.x - __bfloat162float(hx));
    __nv_bfloat16 ly = __float2bfloat16(v.y - __bfloat162float(hy));
    __nv_bfloat16 lz = __float2bfloat16(v.z - __bfloat162float(hz));
    __nv_bfloat16 lw = __float2bfloat16(v.w - __bfloat162float(hw));
    dh[2 * i]     = __halves2bfloat162(hx, hy);
    dh[2 * i + 1] = __halves2bfloat162(hz, hw);
    dl[2 * i]     = __halves2bfloat162(lx, ly);
    dl[2 * i + 1] = __halves2bfloat162(lz, lw);
}

// W{q,k,v}[h][d][e] -> g_wq{h,l}[(mat*16+h)*64+e][d]  (K-major, split), + bias concat
__global__ void qkv_w_transpose(const float* __restrict__ Wq, const float* __restrict__ Wk,
                                const float* __restrict__ Wv, const float* __restrict__ bq,
                                const float* __restrict__ bk, const float* __restrict__ bv)
{
    __shared__ float sm[32][33];
    int z = blockIdx.z, mat = z >> 4, h = z & 15;
    const float* W = (mat == 0 ? Wq : mat == 1 ? Wk : Wv) + (size_t)h * NDIM * NHD;
    const float* bias = (mat == 0 ? bq : mat == 1 ? bk : bv) + h * NHD;
    int d0 = blockIdx.x * 32, e0 = blockIdx.y * 32;
    int tx = threadIdx.x, ty = threadIdx.y;
    sm[ty][tx] = W[(size_t)(d0 + ty) * NHD + e0 + tx];
    __syncthreads();
    float v = sm[tx][ty];
    __nv_bfloat16 hv = __float2bfloat16(v);
    __nv_bfloat16 lv = __float2bfloat16(v - __bfloat162float(hv));
    size_t row = (size_t)z * 64 + e0 + ty;
    g_wqh[row * NDIM + d0 + tx] = hv;
    g_wql[row * NDIM + d0 + tx] = lv;
    if (blockIdx.x == 0 && tx == 0) g_bqkv[z * 64 + e0 + ty] = bias[e0 + ty];
}

// Wo[k][n] -> g_wo{h,l}[n][k]
__global__ void wo_transpose(const float* __restrict__ Wo)
{
    __shared__ float sm[32][33];
    int k0 = blockIdx.x * 32, n0 = blockIdx.y * 32;
    int tx = threadIdx.x, ty = threadIdx.y;
    sm[ty][tx] = Wo[(size_t)(k0 + ty) * NDIM + n0 + tx];
    __syncthreads();
    float v = sm[tx][ty];
    __nv_bfloat16 hv = __float2bfloat16(v);
    __nv_bfloat16 lv = __float2bfloat16(v - __bfloat162float(hv));
    g_woh[(size_t)(n0 + ty) * NDIM + k0 + tx] = hv;
    g_wol[(size_t)(n0 + ty) * NDIM + k0 + tx] = lv;
}

// ---------------------------------------------------------------------------
// HMMA split GEMM. Block tile 128x128, 8 warps, warp tile 64x32, K-tile 32.
// mode 0: A = x, B = QKV weights -> scatter split bf16 into g_{q,k,v}{h,l}
//         (Q scaled by 1/8 = 1/sqrt(HD)); mode 1: A = attn out, B = Wo^T -> out
// ---------------------------------------------------------------------------
#define KT   32
#define SPAD 40

__global__ __launch_bounds__(256) void gemm_mma_kernel(const float* __restrict__ bias,
                                                       float* __restrict__ out, int mode)
{
    __shared__ __align__(16) __nv_bfloat16 As[128 * SPAD];
    __shared__ __align__(16) __nv_bfloat16 Bs[128 * SPAD];

    const int tid = threadIdx.x, wid = tid >> 5, lane = tid & 31;
    const int m0 = blockIdx.x * 128, n0 = blockIdx.y * 128;
    const int warp_m0 = (wid >> 2) * 64;
    const int warp_n0 = (wid & 3) * 32;

    const __nv_bfloat16 *Ah, *Al, *Bh, *Bl;
    if (mode == 0) { Ah = g_xh; Al = g_xl; Bh = g_wqh; Bl = g_wql; }
    else           { Ah = g_oh; Al = g_ol; Bh = g_woh; Bl = g_wol; }
    const __nv_bfloat16* Aseg[3] = {Ah, Ah, Al};
    const __nv_bfloat16* Bseg[3] = {Bh, Bl, Bh};

    const int rowA = tid >> 2;
    const int col8 = (tid & 3) * 8;
    const uint32_t stoff0 = rowA * SPAD + col8;
    const uint32_t stoff1 = (rowA + 64) * SPAD + col8;

    const uint32_t sA = smem_to_u32(As);
    const uint32_t sB = smem_to_u32(Bs);
    const int lm = lane & 15, lq = lane >> 4;
    const int l8 = lane & 7,  lb = (lane >> 3) & 1;
    const uint32_t aBase = sA + ((warp_m0 + lm) * SPAD + lq * 8) * 2;
    const uint32_t bBase = sB + ((warp_n0 + l8) * SPAD + lb * 8) * 2;

    float acc[4][4][4];
    #pragma unroll
    for (int i = 0; i < 4; i++)
        #pragma unroll
        for (int j = 0; j < 4; j++)
            #pragma unroll
            for (int q = 0; q < 4; q++) acc[i][j][q] = 0.0f;

    uint4 ra0, ra1, rb0, rb1;
    {
        const __nv_bfloat16* pa = Aseg[0];
        const __nv_bfloat16* pb = Bseg[0];
        ra0 = *(const uint4*)(pa + (size_t)(m0 + rowA) * NDIM + col8);
        ra1 = *(const uint4*)(pa + (size_t)(m0 + rowA + 64) * NDIM + col8);
        rb0 = *(const uint4*)(pb + (size_t)(n0 + rowA) * NDIM + col8);
        rb1 = *(const uint4*)(pb + (size_t)(n0 + rowA + 64) * NDIM + col8);
    }

    const int NIT = 3 * (NDIM / KT);   // 96
    for (int it = 0; it < NIT; ++it) {
        __syncthreads();
        *(uint4*)(As + stoff0) = ra0;
        *(uint4*)(As + stoff1) = ra1;
        *(uint4*)(Bs + stoff0) = rb0;
        *(uint4*)(Bs + stoff1) = rb1;
        __syncthreads();

        if (it + 1 < NIT) {
            const int nx = it + 1;
            const int seg = nx >> 5;
            const int k0 = (nx & 31) * KT;
            const __nv_bfloat16* pa = Aseg[seg];
            const __nv_bfloat16* pb = Bseg[seg];
            ra0 = *(const uint4*)(pa + (size_t)(m0 + rowA) * NDIM + k0 + col8);
            ra1 = *(const uint4*)(pa + (size_t)(m0 + rowA + 64) * NDIM + k0 + col8);
            rb0 = *(const uint4*)(pb + (size_t)(n0 + rowA) * NDIM + k0 + col8);
            rb1 = *(const uint4*)(pb + (size_t)(n0 + rowA + 64) * NDIM + k0 + col8);
        }

        #pragma unroll
        for (int kk = 0; kk < 2; ++kk) {
            uint32_t a[4][4], b[4][2];
            #pragma unroll
            for (int mt = 0; mt < 4; ++mt)
                ldsm_x4(a[mt], aBase + (mt * 16 * SPAD + kk * 16) * 2);
            #pragma unroll
            for (int nt = 0; nt < 4; ++nt)
                ldsm_x2(b[nt], bBase + (nt * 8 * SPAD + kk * 16) * 2);
            #pragma unroll
            for (int mt = 0; mt < 4; ++mt)
                #pragma unroll
                for (int nt = 0; nt < 4; ++nt)
                    mma_bf16(acc[mt][nt], a[mt], b[nt]);
        }
    }

    const int mrow = lane >> 2;
    const int ncol = (lane & 3) * 2;
    #pragma unroll
    for (int nt = 0; nt < 4; ++nt) {
        const int gn = n0 + warp_n0 + nt * 8 + ncol;
        float2 bb;
        if (mode == 0) bb = *(const float2*)&g_bqkv[gn];
        else           bb = *(const float2*)&bias[gn];
        #pragma unroll
        for (int mt = 0; mt < 4; ++mt) {
            #pragma unroll
            for (int half = 0; half < 2; ++half) {
                const int m = m0 + warp_m0 + mt * 16 + mrow + half * 8;
                float vx = acc[mt][nt][half * 2 + 0] + bb.x;
                float vy = acc[mt][nt][half * 2 + 1] + bb.y;
                if (mode == 0) {
                    const int slot = gn >> 6;
                    const int mat = slot >> 4, h = slot & 15, e = gn & 63;
                    const int b_ = m >> 11, s_ = m & (NS - 1);
                    if (mat == 0) { vx *= 0.125f; vy *= 0.125f; }   // fold 1/sqrt(64)
                    __nv_bfloat16* dh_ = (mat == 0 ? g_qh : mat == 1 ? g_kh : g_vh);
                    __nv_bfloat16* dl_ = (mat == 0 ? g_ql : mat == 1 ? g_kl : g_vl);
                    __nv_bfloat16 hx = __float2bfloat16(vx);
                    __nv_bfloat16 hy = __float2bfloat16(vy);
                    float lxf = vx - __bfloat162float(hx);
                    float lyf = vy - __bfloat162float(hy);
                    size_t idx = (((size_t)(b_ * NH + h)) * NS + s_) * NHD + e;
                    __nv_bfloat162 hp = __halves2bfloat162(hx, hy);
                    __nv_bfloat162 lp = __halves2bfloat162(__float2bfloat16(lxf),
                                                           __float2bfloat16(lyf));
                    *(uint32_t*)&dh_[idx] = *(uint32_t*)&hp;
                    *(uint32_t*)&dl_[idx] = *(uint32_t*)&lp;
                } else {
                    float2 v = make_float2(vx, vy);
                    *(float2*)&out[(size_t)m * NDIM + gn] = v;
                }
            }
        }
    }
}

// ---------------------------------------------------------------------------
// Flash attention with split-bf16 HMMA. Block: 128 thr (4 warps), 64 q rows.
// grid = (NS/64, NB*NH). Scores fp32 accum; P kept in registers (C->A frag).
// Emits O directly as hi/lo bf16 split to g_oh/g_ol in [m][h*64+e] layout.
// ---------------------------------------------------------------------------
#define FPAD 72   // smem row stride (bf16) for 64-wide tiles
#define FT   (64 * FPAD)

__global__ __launch_bounds__(128) void flash_mma_kernel()
{
    extern __shared__ __align__(16) __nv_bfloat16 smf[];
    __nv_bfloat16* QH = smf;
    __nv_bfloat16* QL = smf + FT;
    __nv_bfloat16* KH = smf + 2 * FT;
    __nv_bfloat16* KL = smf + 3 * FT;
    __nv_bfloat16* VH = smf + 4 * FT;
    __nv_bfloat16* VL = smf + 5 * FT;

    const int tid = threadIdx.x, wid = tid >> 5, lane = tid & 31;
    const int qt = blockIdx.x, bh = blockIdx.y;
    const size_t base = (size_t)bh * NS * NHD;

    // load Q (hi/lo) once
    {
        const __nv_bfloat16* qsrc[2] = {g_qh + base + (size_t)qt * 64 * NHD,
                                        g_ql + base + (size_t)qt * 64 * NHD};
        __nv_bfloat16* qdst[2] = {QH, QL};
        #pragma unroll
        for (int a = 0; a < 2; a++)
            #pragma unroll
            for (int it = 0; it < 4; it++) {
                int ch = tid + it * 128;
                int r = ch >> 3, c8 = (ch & 7) * 8;
                *(uint4*)&qdst[a][r * FPAD + c8] = *(const uint4*)&qsrc[a][r * 64 + c8];
            }
    }

    const int lm = lane & 15, lq = lane >> 4;
    const int l8 = lane & 7;
    const int sel1 = (lane >> 3) & 1;   // k-half selector
    const int sel2 = lane >> 4;         // n-half selector
    const int r_  = lane >> 2;          // row within m8
    const int qc  = lane & 3;

    const uint32_t aBaseH = smem_to_u32(QH) + ((wid * 16 + lm) * FPAD + lq * 8) * 2;
    const uint32_t aBaseL = smem_to_u32(QL) + ((wid * 16 + lm) * FPAD + lq * 8) * 2;
    const uint32_t kBaseH = smem_to_u32(KH) + ((sel2 * 8 + l8) * FPAD + sel1 * 8) * 2;
    const uint32_t kBaseL = smem_to_u32(KL) + ((sel2 * 8 + l8) * FPAD + sel1 * 8) * 2;
    const uint32_t vBaseH = smem_to_u32(VH) + ((sel1 * 8 + l8) * FPAD + sel2 * 8) * 2;
    const uint32_t vBaseL = smem_to_u32(VL) + ((sel1 * 8 + l8) * FPAD + sel2 * 8) * 2;

    float cO[8][4];
    #pragma unroll
    for (int i = 0; i < 8; i++)
        #pragma unroll
        for (int j = 0; j < 4; j++) cO[i][j] = 0.0f;
    float m0r = -1e30f, m1r = -1e30f, l0 = 0.0f, l1 = 0.0f;

    for (int j = 0; j <= qt; ++j) {
        __syncthreads();
        {
            const size_t off = base + (size_t)j * 64 * NHD;
            const __nv_bfloat16* src[4] = {g_kh + off, g_kl + off, g_vh + off, g_vl + off};
            __nv_bfloat16* dst[4] = {KH, KL, VH, VL};
            #pragma unroll
            for (int a = 0; a < 4; a++)
                #pragma unroll
                for (int it = 0; it < 4; it++) {
                    int ch = tid + it * 128;
                    int r = ch >> 3, c8 = (ch & 7) * 8;
                    *(uint4*)&dst[a][r * FPAD + c8] = *(const uint4*)&src[a][r * 64 + c8];
                }
        }
        __syncthreads();

        // ---- scores: c = Qh*Kh + Ql*Kh + Qh*Kl ----
        float c[8][4];
        #pragma unroll
        for (int i = 0; i < 8; i++)
            #pragma unroll
            for (int q = 0; q < 4; q++) c[i][q] = 0.0f;

        #pragma unroll
        for (int kt = 0; kt < 4; ++kt) {
            uint32_t aH[4], aL[4];
            ldsm_x4(aH, aBaseH + kt * 16 * 2);
            ldsm_x4(aL, aBaseL + kt * 16 * 2);
            #pragma unroll
            for (int np = 0; np < 4; ++np) {
                uint32_t b[4];
                ldsm_x4(b, kBaseH + (np * 16 * FPAD + kt * 16) * 2);
                mma_bf16(c[2 * np],     aH, b);
                mma_bf16(c[2 * np + 1], aH, b + 2);
                mma_bf16(c[2 * np],     aL, b);
                mma_bf16(c[2 * np + 1], aL, b + 2);
            }
            #pragma unroll
            for (int np = 0; np < 4; ++np) {
                uint32_t b[4];
                ldsm_x4(b, kBaseL + (np * 16 * FPAD + kt * 16) * 2);
                mma_bf16(c[2 * np],     aH, b);
                mma_bf16(c[2 * np + 1], aH, b + 2);
            }
        }

        // ---- causal mask on diagonal tile ----
        if (j == qt) {
            const int row0 = wid * 16 + r_;
            #pragma unroll
            for (int n8 = 0; n8 < 8; ++n8) {
                const int col = n8 * 8 + qc * 2;
                if (col     > row0)     c[n8][0] = -1e30f;
                if (col + 1 > row0)     c[n8][1] = -1e30f;
                if (col     > row0 + 8) c[n8][2] = -1e30f;
                if (col + 1 > row0 + 8) c[n8][3] = -1e30f;
            }
        }

        // ---- online softmax (rows r_ and r_+8) ----
        float mt0 = -1e30f, mt1 = -1e30f;
        #pragma unroll
        for (int n8 = 0; n8 < 8; ++n8) {
            mt0 = fmaxf(mt0, fmaxf(c[n8][0], c[n8][1]));
            mt1 = fmaxf(mt1, fmaxf(c[n8][2], c[n8][3]));
        }
        mt0 = fmaxf(mt0, __shfl_xor_sync(0xffffffffu, mt0, 1));
        mt0 = fmaxf(mt0, __shfl_xor_sync(0xffffffffu, mt0, 2));
        mt1 = fmaxf(mt1, __shfl_xor_sync(0xffffffffu, mt1, 1));
        mt1 = fmaxf(mt1, __shfl_xor_sync(0xffffffffu, mt1, 2));
        const float mn0 = fmaxf(m0r, mt0);
        const float mn1 = fmaxf(m1r, mt1);
        const float al0 = __expf(m0r - mn0);
        const float al1 = __expf(m1r - mn1);
        float s0 = 0.0f, s1 = 0.0f;
        #pragma unroll
        for (int n8 = 0; n8 < 8; ++n8) {
            c[n8][0] = __expf(c[n8][0] - mn0); s0 += c[n8][0];
            c[n8][1] = __expf(c[n8][1] - mn0); s0 += c[n8][1];
            c[n8][2] = __expf(c[n8][2] - mn1); s1 += c[n8][2];
            c[n8][3] = __expf(c[n8][3] - mn1); s1 += c[n8][3];
        }
        s0 += __shfl_xor_sync(0xffffffffu, s0, 1);
        s0 += __shfl_xor_sync(0xffffffffu, s0, 2);
        s1 += __shfl_xor_sync(0xffffffffu, s1, 1);
        s1 += __shfl_xor_sync(0xffffffffu, s1, 2);
        l0 = l0 * al0 + s0;  m0r = mn0;
        l1 = l1 * al1 + s1;  m1r = mn1;
        #pragma unroll
        for (int n8 = 0; n8 < 8; ++n8) {
            cO[n8][0] *= al0; cO[n8][1] *= al0;
            cO[n8][2] *= al1; cO[n8][3] *= al1;
        }

        // ---- pack P into A-frags (hi/lo) ----
        uint32_t pH[4][4], pL[4][4];
        #pragma unroll
        for (int kt = 0; kt < 4; ++kt) {
            const int ja = 2 * kt, jb = 2 * kt + 1;
            float h00, h01, h10, h11;
            h00 = __bfloat162float(__float2bfloat16(c[ja][0]));
            h01 = __bfloat162float(__float2bfloat16(c[ja][1]));
            pH[kt][0] = pack_bf2(c[ja][0], c[ja][1]);
            pL[kt][0] = pack_bf2(c[ja][0] - h00, c[ja][1] - h01);
            h10 = __bfloat162float(__float2bfloat16(c[ja][2]));
            h11 = __bfloat162float(__float2bfloat16(c[ja][3]));
            pH[kt][1] = pack_bf2(c[ja][2], c[ja][3]);
            pL[kt][1] = pack_bf2(c[ja][2] - h10, c[ja][3] - h11);
            h00 = __bfloat162float(__float2bfloat16(c[jb][0]));
            h01 = __bfloat162float(__float2bfloat16(c[jb][1]));
            pH[kt][2] = pack_bf2(c[jb][0], c[jb][1]);
            pL[kt][2] = pack_bf2(c[jb][0] - h00, c[jb][1] - h01);
            h10 = __bfloat162float(__float2bfloat16(c[jb][2]));
            h11 = __bfloat162float(__float2bfloat16(c[jb][3]));
            pH[kt][3] = pack_bf2(c[jb][2], c[jb][3]);
            pL[kt][3] = pack_bf2(c[jb][2] - h10, c[jb][3] - h11);
        }

        // ---- O += Ph*Vh + Pl*Vh + Ph*Vl ----
        #pragma unroll
        for (int kt = 0; kt < 4; ++kt) {
            #pragma unroll
            for (int np = 0; np < 4; ++np) {
                uint32_t b[4];
                ldsm_x4_t(b, vBaseH + (kt * 16 * FPAD + np * 16) * 2);
                mma_bf16(cO[2 * np],     pH[kt], b);
                mma_bf16(cO[2 * np + 1], pH[kt], b + 2);
                mma_bf16(cO[2 * np],     pL[kt], b);
                mma_bf16(cO[2 * np + 1], pL[kt], b + 2);
            }
        }
        #pragma unroll
        for (int kt = 0; kt < 4; ++kt) {
            #pragma unroll
            for (int np = 0; np < 4; ++np) {
                uint32_t b[4];
                ldsm_x4_t(b, vBaseL + (kt * 16 * FPAD + np * 16) * 2);
                mma_bf16(cO[2 * np],     pH[kt], b);
                mma_bf16(cO[2 * np + 1], pH[kt], b + 2);
            }
        }
    }

    // ---- epilogue: O/l -> split bf16 into [m][h*64+e] ----
    const int b_ = bh >> 4, h = bh & 15;
    const float i0 = 1.0f / l0, i1 = 1.0f / l1;
    const int mrow0 = qt * 64 + wid * 16 + r_;
    #pragma unroll
    for (int n8 = 0; n8 < 8; ++n8) {
        const int e = n8 * 8 + qc * 2;
        #pragma unroll
        for (int half = 0; half < 2; ++half) {
            const float inv = half ? i1 : i0;
            const float vx = cO[n8][half * 2 + 0] * inv;
            const float vy = cO[n8][half * 2 + 1] * inv;
            const int m = mrow0 + half * 8;
            __nv_bfloat16 hx = __float2bfloat16(vx);
            __nv_bfloat16 hy = __float2bfloat16(vy);
            __nv_bfloat162 hp = __halves2bfloat162(hx, hy);
            __nv_bfloat162 lp = __halves2bfloat162(
                __float2bfloat16(vx - __bfloat162float(hx)),
                __float2bfloat16(vy - __bfloat162float(hy)));
            size_t idx = ((size_t)b_ * NS + m) * NDIM + h * 64 + e;
            *(uint32_t*)&g_oh[idx] = *(uint32_t*)&hp;
            *(uint32_t*)&g_ol[idx] = *(uint32_t*)&lp;
        }
    }
}

// ---------------------------------------------------------------------------
extern "C" void kernel_launch(void* const* d_in, const int* in_sizes, int n_in,
                              void* d_out, int out_size)
{
    const float* x  = (const float*)d_in[0];
    const float* Wq = (const float*)d_in[1];
    const float* bq = (const float*)d_in[2];
    const float* Wk = (const float*)d_in[3];
    const float* bk = (const float*)d_in[4];
    const float* Wv = (const float*)d_in[5];
    const float* bv = (const float*)d_in[6];
    const float* Wo = (const float*)d_in[7];
    const float* bo = (const float*)d_in[8];
    float* out = (float*)d_out;

    const int flash_smem = 6 * FT * (int)sizeof(__nv_bfloat16);   // 55296
    cudaFuncSetAttribute(flash_mma_kernel,
                         cudaFuncAttributeMaxDynamicSharedMemorySize, flash_smem);

    __nv_bfloat162 *xh2, *xl2;
    cudaGetSymbolAddress((void**)&xh2, g_xh);
    cudaGetSymbolAddress((void**)&xl2, g_xl);

    const int n4 = NM * NDIM / 4;
    split_kernel<<<n4 / 256, 256>>>((const float4*)x, xh2, xl2, n4);
    qkv_w_transpose<<<dim3(32, 2, 48), dim3(32, 32)>>>(Wq, Wk, Wv, bq, bk, bv);
    wo_transpose<<<dim3(32, 32), dim3(32, 32)>>>(Wo);

    gemm_mma_kernel<<<dim3(NM / 128, NQKV / 128), 256>>>(nullptr, nullptr, 0);
    flash_mma_kernel<<<dim3(NS / 64, NB * NH), 128, flash_smem>>>();
    gemm_mma_kernel<<<dim3(NM / 128, NDIM / 128), 256>>>(bo, out, 1);
}

// round 5
// speedup vs baseline: 2.4947x; 1.0743x over previous
#include <cuda_runtime.h>
#include <cuda_bf16.h>
#include <cstdint>

#define NB   2
#define NS   2048
#define NDIM 1024
#define NH   16
#define NHD  64
#define NM   (NB * NS)     // 4096
#define NQKV 3072          // 3 * NH * NHD

// ---------------------------------------------------------------------------
// Scratch (__device__ globals; allocation-free rule)
// ---------------------------------------------------------------------------
__device__ __nv_bfloat16 g_qh[NB * NH * NS * NHD];
__device__ __nv_bfloat16 g_ql[NB * NH * NS * NHD];
__device__ __nv_bfloat16 g_kh[NB * NH * NS * NHD];
__device__ __nv_bfloat16 g_kl[NB * NH * NS * NHD];
__device__ __nv_bfloat16 g_vh[NB * NH * NS * NHD];
__device__ __nv_bfloat16 g_vl[NB * NH * NS * NHD];

__device__ __nv_bfloat16 g_xh[(size_t)NM * NDIM];
__device__ __nv_bfloat16 g_xl[(size_t)NM * NDIM];
__device__ __nv_bfloat16 g_oh[(size_t)NM * NDIM];
__device__ __nv_bfloat16 g_ol[(size_t)NM * NDIM];
__device__ __nv_bfloat16 g_wqh[(size_t)NQKV * NDIM];   // QKV weights, K-major [3072][1024]
__device__ __nv_bfloat16 g_wql[(size_t)NQKV * NDIM];
__device__ __nv_bfloat16 g_woh[(size_t)NDIM * NDIM];   // Wo transposed, K-major [1024][1024]
__device__ __nv_bfloat16 g_wol[(size_t)NDIM * NDIM];
__device__ float g_bqkv[NQKV];

__device__ __forceinline__ uint32_t smem_to_u32(const void* p) {
    uint32_t a;
    asm("{ .reg .u64 t; cvta.to.shared.u64 t, %1; cvt.u32.u64 %0, t; }"
        : "=r"(a) : "l"(p));
    return a;
}

__device__ __forceinline__ void ldsm_x4(uint32_t* r, uint32_t addr) {
    asm volatile("ldmatrix.sync.aligned.m8n8.x4.shared.b16 {%0,%1,%2,%3}, [%4];"
        : "=r"(r[0]), "=r"(r[1]), "=r"(r[2]), "=r"(r[3]) : "r"(addr));
}
__device__ __forceinline__ void ldsm_x4_t(uint32_t* r, uint32_t addr) {
    asm volatile("ldmatrix.sync.aligned.m8n8.x4.trans.shared.b16 {%0,%1,%2,%3}, [%4];"
        : "=r"(r[0]), "=r"(r[1]), "=r"(r[2]), "=r"(r[3]) : "r"(addr));
}
__device__ __forceinline__ void ldsm_x2(uint32_t* r, uint32_t addr) {
    asm volatile("ldmatrix.sync.aligned.m8n8.x2.shared.b16 {%0,%1}, [%2];"
        : "=r"(r[0]), "=r"(r[1]) : "r"(addr));
}
__device__ __forceinline__ void mma_bf16(float* c, const uint32_t* a, const uint32_t* b) {
    asm volatile(
        "mma.sync.aligned.m16n8k16.row.col.f32.bf16.bf16.f32 "
        "{%0,%1,%2,%3}, {%4,%5,%6,%7}, {%8,%9}, {%0,%1,%2,%3};"
        : "+f"(c[0]), "+f"(c[1]), "+f"(c[2]), "+f"(c[3])
        : "r"(a[0]), "r"(a[1]), "r"(a[2]), "r"(a[3]), "r"(b[0]), "r"(b[1]));
}
__device__ __forceinline__ void cpasync16(uint32_t s, const void* g) {
    asm volatile("cp.async.cg.shared.global [%0], [%1], 16;" :: "r"(s), "l"(g));
}
#define CP_COMMIT() asm volatile("cp.async.commit_group;" ::: "memory")
#define CP_WAIT(n)  asm volatile("cp.async.wait_group %0;" :: "n"(n) : "memory")

__device__ __forceinline__ uint32_t pack_bf2(float x, float y) {
    __nv_bfloat162 h = __halves2bfloat162(__float2bfloat16(x), __float2bfloat16(y));
    return *(uint32_t*)&h;
}

// ---------------------------------------------------------------------------
// Conversion kernels
// ---------------------------------------------------------------------------
__global__ void split_kernel(const float4* __restrict__ src,
                             __nv_bfloat162* __restrict__ dh,
                             __nv_bfloat162* __restrict__ dl, int n4)
{
    int i = blockIdx.x * blockDim.x + threadIdx.x;
    if (i >= n4) return;
    float4 v = src[i];
    __nv_bfloat16 hx = __float2bfloat16(v.x), hy = __float2bfloat16(v.y);
    __nv_bfloat16 hz = __float2bfloat16(v.z), hw = __float2bfloat16(v.w);
    __nv_bfloat16 lx = __float2bfloat16(v.x - __bfloat162float(hx));
    __nv_bfloat16 ly = __float2bfloat16(v.y - __bfloat162float(hy));
    __nv_bfloat16 lz = __float2bfloat16(v.z - __bfloat162float(hz));
    __nv_bfloat16 lw = __float2bfloat16(v.w - __bfloat162float(hw));
    dh[2 * i]     = __halves2bfloat162(hx, hy);
    dh[2 * i + 1] = __halves2bfloat162(hz, hw);
    dl[2 * i]     = __halves2bfloat162(lx, ly);
    dl[2 * i + 1] = __halves2bfloat162(lz, lw);
}

// W{q,k,v}[h][d][e] -> g_wq{h,l}[(mat*16+h)*64+e][d]  (K-major, split), + bias concat
__global__ void qkv_w_transpose(const float* __restrict__ Wq, const float* __restrict__ Wk,
                                const float* __restrict__ Wv, const float* __restrict__ bq,
                                const float* __restrict__ bk, const float* __restrict__ bv)
{
    __shared__ float sm[32][33];
    int z = blockIdx.z, mat = z >> 4, h = z & 15;
    const float* W = (mat == 0 ? Wq : mat == 1 ? Wk : Wv) + (size_t)h * NDIM * NHD;
    const float* bias = (mat == 0 ? bq : mat == 1 ? bk : bv) + h * NHD;
    int d0 = blockIdx.x * 32, e0 = blockIdx.y * 32;
    int tx = threadIdx.x, ty = threadIdx.y;
    sm[ty][tx] = W[(size_t)(d0 + ty) * NHD + e0 + tx];
    __syncthreads();
    float v = sm[tx][ty];
    __nv_bfloat16 hv = __float2bfloat16(v);
    __nv_bfloat16 lv = __float2bfloat16(v - __bfloat162float(hv));
    size_t row = (size_t)z * 64 + e0 + ty;
    g_wqh[row * NDIM + d0 + tx] = hv;
    g_wql[row * NDIM + d0 + tx] = lv;
    if (blockIdx.x == 0 && tx == 0) g_bqkv[z * 64 + e0 + ty] = bias[e0 + ty];
}

// Wo[k][n] -> g_wo{h,l}[n][k]
__global__ void wo_transpose(const float* __restrict__ Wo)
{
    __shared__ float sm[32][33];
    int k0 = blockIdx.x * 32, n0 = blockIdx.y * 32;
    int tx = threadIdx.x, ty = threadIdx.y;
    sm[ty][tx] = Wo[(size_t)(k0 + ty) * NDIM + n0 + tx];
    __syncthreads();
    float v = sm[tx][ty];
    __nv_bfloat16 hv = __float2bfloat16(v);
    __nv_bfloat16 lv = __float2bfloat16(v - __bfloat162float(hv));
    g_woh[(size_t)(n0 + ty) * NDIM + k0 + tx] = hv;
    g_wol[(size_t)(n0 + ty) * NDIM + k0 + tx] = lv;
}

// ---------------------------------------------------------------------------
// HMMA split GEMM, shared-k-tile 3-product + cp.async double buffering.
// Block 128x128, 8 warps (2x4), warp tile 64x32, K-tile 32, 32 k-iterations.
// Per k-tile smem holds Ah, Al, Bh, Bl; products Ah*Bh + Ah*Bl + Al*Bh.
// mode 0: A = x, B = QKV weights -> split bf16 g_{q,k,v}{h,l} (Q scaled 1/8)
// mode 1: A = attn out, B = Wo^T -> out (+bias)
// ---------------------------------------------------------------------------
#define KT     32
#define SPAD   40
#define TILE_B (128 * SPAD * 2)   // 10240 bytes per tile
#define BUF_B  (4 * TILE_B)       // 40960 bytes per stage
#define GSMEM  (2 * BUF_B)        // 81920 bytes

__global__ __launch_bounds__(256) void gemm_mma_kernel(const float* __restrict__ bias,
                                                       float* __restrict__ out, int mode)
{
    extern __shared__ __align__(16) char smg[];
    const uint32_t smb = smem_to_u32(smg);

    const int tid = threadIdx.x, wid = tid >> 5, lane = tid & 31;
    const int m0 = blockIdx.x * 128, n0 = blockIdx.y * 128;
    const int warp_m0 = (wid >> 2) * 64;
    const int warp_n0 = (wid & 3) * 32;

    const __nv_bfloat16 *Ah, *Al, *Bh, *Bl;
    if (mode == 0) { Ah = g_xh; Al = g_xl; Bh = g_wqh; Bl = g_wql; }
    else           { Ah = g_oh; Al = g_ol; Bh = g_woh; Bl = g_wol; }

    const int rowA = tid >> 2;            // 0..63 (+64)
    const int col8 = (tid & 3) * 8;
    const uint32_t st0 = (rowA * SPAD + col8) * 2;
    const uint32_t st1 = ((rowA + 64) * SPAD + col8) * 2;

    // gmem row bases (element offsets advance by k0 each tile)
    const __nv_bfloat16* gA0h = Ah + (size_t)(m0 + rowA) * NDIM + col8;
    const __nv_bfloat16* gA1h = Ah + (size_t)(m0 + rowA + 64) * NDIM + col8;
    const __nv_bfloat16* gA0l = Al + (size_t)(m0 + rowA) * NDIM + col8;
    const __nv_bfloat16* gA1l = Al + (size_t)(m0 + rowA + 64) * NDIM + col8;
    const __nv_bfloat16* gB0h = Bh + (size_t)(n0 + rowA) * NDIM + col8;
    const __nv_bfloat16* gB1h = Bh + (size_t)(n0 + rowA + 64) * NDIM + col8;
    const __nv_bfloat16* gB0l = Bl + (size_t)(n0 + rowA) * NDIM + col8;
    const __nv_bfloat16* gB1l = Bl + (size_t)(n0 + rowA + 64) * NDIM + col8;

    // ldmatrix lane mapping
    const int lm = lane & 15, lq = lane >> 4;
    const int l8 = lane & 7,  lb = (lane >> 3) & 1;
    const uint32_t aOffH = ((warp_m0 + lm) * SPAD + lq * 8) * 2;             // in AH tile
    const uint32_t bOffH = 2 * TILE_B + ((warp_n0 + l8) * SPAD + lb * 8) * 2; // in BH tile

    float acc[4][4][4];
    #pragma unroll
    for (int i = 0; i < 4; i++)
        #pragma unroll
        for (int j = 0; j < 4; j++)
            #pragma unroll
            for (int q = 0; q < 4; q++) acc[i][j][q] = 0.0f;

    const int NT = NDIM / KT;   // 32

    // issue tile 0 into buffer 0
    {
        const uint32_t b = smb;
        cpasync16(b + st0, gA0h);               cpasync16(b + st1, gA1h);
        cpasync16(b + TILE_B + st0, gA0l);      cpasync16(b + TILE_B + st1, gA1l);
        cpasync16(b + 2 * TILE_B + st0, gB0h);  cpasync16(b + 2 * TILE_B + st1, gB1h);
        cpasync16(b + 3 * TILE_B + st0, gB0l);  cpasync16(b + 3 * TILE_B + st1, gB1l);
        CP_COMMIT();
    }

    for (int t = 0; t < NT; ++t) {
        if (t + 1 < NT) {
            const uint32_t b = smb + ((t + 1) & 1) * BUF_B;
            const int k1 = (t + 1) * KT;
            cpasync16(b + st0, gA0h + k1);               cpasync16(b + st1, gA1h + k1);
            cpasync16(b + TILE_B + st0, gA0l + k1);      cpasync16(b + TILE_B + st1, gA1l + k1);
            cpasync16(b + 2 * TILE_B + st0, gB0h + k1);  cpasync16(b + 2 * TILE_B + st1, gB1h + k1);
            cpasync16(b + 3 * TILE_B + st0, gB0l + k1);  cpasync16(b + 3 * TILE_B + st1, gB1l + k1);
            CP_COMMIT();
            CP_WAIT(1);
        } else {
            CP_WAIT(0);
        }
        __syncthreads();

        const uint32_t buf = smb + (t & 1) * BUF_B;
        const uint32_t aH = buf + aOffH;
        const uint32_t aL = aH + TILE_B;
        const uint32_t bH = buf + bOffH;
        const uint32_t bL = bH + TILE_B;

        #pragma unroll
        for (int kk = 0; kk < 2; ++kk) {
            uint32_t a[4][4];
            // pass 1: Ah * (Bh + Bl)
            #pragma unroll
            for (int mt = 0; mt < 4; ++mt)
                ldsm_x4(a[mt], aH + (mt * 16 * SPAD + kk * 16) * 2);
            #pragma unroll
            for (int nt = 0; nt < 4; ++nt) {
                uint32_t bh2[2], bl2[2];
                ldsm_x2(bh2, bH + (nt * 8 * SPAD + kk * 16) * 2);
                ldsm_x2(bl2, bL + (nt * 8 * SPAD + kk * 16) * 2);
                #pragma unroll
                for (int mt = 0; mt < 4; ++mt) {
                    mma_bf16(acc[mt][nt], a[mt], bh2);
                    mma_bf16(acc[mt][nt], a[mt], bl2);
                }
            }
            // pass 2: Al * Bh
            #pragma unroll
            for (int mt = 0; mt < 4; ++mt)
                ldsm_x4(a[mt], aL + (mt * 16 * SPAD + kk * 16) * 2);
            #pragma unroll
            for (int nt = 0; nt < 4; ++nt) {
                uint32_t bh2[2];
                ldsm_x2(bh2, bH + (nt * 8 * SPAD + kk * 16) * 2);
                #pragma unroll
                for (int mt = 0; mt < 4; ++mt)
                    mma_bf16(acc[mt][nt], a[mt], bh2);
            }
        }
        __syncthreads();   // all reads of this buffer done before overwrite at t+2
    }

    // ---- epilogue ----
    const int mrow = lane >> 2;
    const int ncol = (lane & 3) * 2;
    #pragma unroll
    for (int nt = 0; nt < 4; ++nt) {
        const int gn = n0 + warp_n0 + nt * 8 + ncol;
        float2 bb;
        if (mode == 0) bb = *(const float2*)&g_bqkv[gn];
        else           bb = *(const float2*)&bias[gn];
        #pragma unroll
        for (int mt = 0; mt < 4; ++mt) {
            #pragma unroll
            for (int half = 0; half < 2; ++half) {
                const int m = m0 + warp_m0 + mt * 16 + mrow + half * 8;
                float vx = acc[mt][nt][half * 2 + 0] + bb.x;
                float vy = acc[mt][nt][half * 2 + 1] + bb.y;
                if (mode == 0) {
                    const int slot = gn >> 6;
                    const int mat = slot >> 4, h = slot & 15, e = gn & 63;
                    const int b_ = m >> 11, s_ = m & (NS - 1);
                    if (mat == 0) { vx *= 0.125f; vy *= 0.125f; }   // fold 1/sqrt(64)
                    __nv_bfloat16* dh_ = (mat == 0 ? g_qh : mat == 1 ? g_kh : g_vh);
                    __nv_bfloat16* dl_ = (mat == 0 ? g_ql : mat == 1 ? g_kl : g_vl);
                    __nv_bfloat16 hx = __float2bfloat16(vx);
                    __nv_bfloat16 hy = __float2bfloat16(vy);
                    float lxf = vx - __bfloat162float(hx);
                    float lyf = vy - __bfloat162float(hy);
                    size_t idx = (((size_t)(b_ * NH + h)) * NS + s_) * NHD + e;
                    __nv_bfloat162 hp = __halves2bfloat162(hx, hy);
                    __nv_bfloat162 lp = __halves2bfloat162(__float2bfloat16(lxf),
                                                           __float2bfloat16(lyf));
                    *(uint32_t*)&dh_[idx] = *(uint32_t*)&hp;
                    *(uint32_t*)&dl_[idx] = *(uint32_t*)&lp;
                } else {
                    float2 v = make_float2(vx, vy);
                    *(float2*)&out[(size_t)m * NDIM + gn] = v;
                }
            }
        }
    }
}

// ---------------------------------------------------------------------------
// Flash attention with split-bf16 HMMA (unchanged from R4).
// ---------------------------------------------------------------------------
#define FPAD 72
#define FT   (64 * FPAD)

__global__ __launch_bounds__(128) void flash_mma_kernel()
{
    extern __shared__ __align__(16) __nv_bfloat16 smf[];
    __nv_bfloat16* QH = smf;
    __nv_bfloat16* QL = smf + FT;
    __nv_bfloat16* KH = smf + 2 * FT;
    __nv_bfloat16* KL = smf + 3 * FT;
    __nv_bfloat16* VH = smf + 4 * FT;
    __nv_bfloat16* VL = smf + 5 * FT;

    const int tid = threadIdx.x, wid = tid >> 5, lane = tid & 31;
    const int qt = blockIdx.x, bh = blockIdx.y;
    const size_t base = (size_t)bh * NS * NHD;

    {
        const __nv_bfloat16* qsrc[2] = {g_qh + base + (size_t)qt * 64 * NHD,
                                        g_ql + base + (size_t)qt * 64 * NHD};
        __nv_bfloat16* qdst[2] = {QH, QL};
        #pragma unroll
        for (int a = 0; a < 2; a++)
            #pragma unroll
            for (int it = 0; it < 4; it++) {
                int ch = tid + it * 128;
                int r = ch >> 3, c8 = (ch & 7) * 8;
                *(uint4*)&qdst[a][r * FPAD + c8] = *(const uint4*)&qsrc[a][r * 64 + c8];
            }
    }

    const int lm = lane & 15, lq = lane >> 4;
    const int l8 = lane & 7;
    const int sel1 = (lane >> 3) & 1;
    const int sel2 = lane >> 4;
    const int r_  = lane >> 2;
    const int qc  = lane & 3;

    const uint32_t aBaseH = smem_to_u32(QH) + ((wid * 16 + lm) * FPAD + lq * 8) * 2;
    const uint32_t aBaseL = smem_to_u32(QL) + ((wid * 16 + lm) * FPAD + lq * 8) * 2;
    const uint32_t kBaseH = smem_to_u32(KH) + ((sel2 * 8 + l8) * FPAD + sel1 * 8) * 2;
    const uint32_t kBaseL = smem_to_u32(KL) + ((sel2 * 8 + l8) * FPAD + sel1 * 8) * 2;
    const uint32_t vBaseH = smem_to_u32(VH) + ((sel1 * 8 + l8) * FPAD + sel2 * 8) * 2;
    const uint32_t vBaseL = smem_to_u32(VL) + ((sel1 * 8 + l8) * FPAD + sel2 * 8) * 2;

    float cO[8][4];
    #pragma unroll
    for (int i = 0; i < 8; i++)
        #pragma unroll
        for (int j = 0; j < 4; j++) cO[i][j] = 0.0f;
    float m0r = -1e30f, m1r = -1e30f, l0 = 0.0f, l1 = 0.0f;

    for (int j = 0; j <= qt; ++j) {
        __syncthreads();
        {
            const size_t off = base + (size_t)j * 64 * NHD;
            const __nv_bfloat16* src[4] = {g_kh + off, g_kl + off, g_vh + off, g_vl + off};
            __nv_bfloat16* dst[4] = {KH, KL, VH, VL};
            #pragma unroll
            for (int a = 0; a < 4; a++)
                #pragma unroll
                for (int it = 0; it < 4; it++) {
                    int ch = tid + it * 128;
                    int r = ch >> 3, c8 = (ch & 7) * 8;
                    *(uint4*)&dst[a][r * FPAD + c8] = *(const uint4*)&src[a][r * 64 + c8];
                }
        }
        __syncthreads();

        float c[8][4];
        #pragma unroll
        for (int i = 0; i < 8; i++)
            #pragma unroll
            for (int q = 0; q < 4; q++) c[i][q] = 0.0f;

        #pragma unroll
        for (int kt = 0; kt < 4; ++kt) {
            uint32_t aH[4], aL[4];
            ldsm_x4(aH, aBaseH + kt * 16 * 2);
            ldsm_x4(aL, aBaseL + kt * 16 * 2);
            #pragma unroll
            for (int np = 0; np < 4; ++np) {
                uint32_t b[4];
                ldsm_x4(b, kBaseH + (np * 16 * FPAD + kt * 16) * 2);
                mma_bf16(c[2 * np],     aH, b);
                mma_bf16(c[2 * np + 1], aH, b + 2);
                mma_bf16(c[2 * np],     aL, b);
                mma_bf16(c[2 * np + 1], aL, b + 2);
            }
            #pragma unroll
            for (int np = 0; np < 4; ++np) {
                uint32_t b[4];
                ldsm_x4(b, kBaseL + (np * 16 * FPAD + kt * 16) * 2);
                mma_bf16(c[2 * np],     aH, b);
                mma_bf16(c[2 * np + 1], aH, b + 2);
            }
        }

        if (j == qt) {
            const int row0 = wid * 16 + r_;
            #pragma unroll
            for (int n8 = 0; n8 < 8; ++n8) {
                const int col = n8 * 8 + qc * 2;
                if (col     > row0)     c[n8][0] = -1e30f;
                if (col + 1 > row0)     c[n8][1] = -1e30f;
                if (col     > row0 + 8) c[n8][2] = -1e30f;
                if (col + 1 > row0 + 8) c[n8][3] = -1e30f;
            }
        }

        float mt0 = -1e30f, mt1 = -1e30f;
        #pragma unroll
        for (int n8 = 0; n8 < 8; ++n8) {
            mt0 = fmaxf(mt0, fmaxf(c[n8][0], c[n8][1]));
            mt1 = fmaxf(mt1, fmaxf(c[n8][2], c[n8][3]));
        }
        mt0 = fmaxf(mt0, __shfl_xor_sync(0xffffffffu, mt0, 1));
        mt0 = fmaxf(mt0, __shfl_xor_sync(0xffffffffu, mt0, 2));
        mt1 = fmaxf(mt1, __shfl_xor_sync(0xffffffffu, mt1, 1));
        mt1 = fmaxf(mt1, __shfl_xor_sync(0xffffffffu, mt1, 2));
        const float mn0 = fmaxf(m0r, mt0);
        const float mn1 = fmaxf(m1r, mt1);
        const float al0 = __expf(m0r - mn0);
        const float al1 = __expf(m1r - mn1);
        float s0 = 0.0f, s1 = 0.0f;
        #pragma unroll
        for (int n8 = 0; n8 < 8; ++n8) {
            c[n8][0] = __expf(c[n8][0] - mn0); s0 += c[n8][0];
            c[n8][1] = __expf(c[n8][1] - mn0); s0 += c[n8][1];
            c[n8][2] = __expf(c[n8][2] - mn1); s1 += c[n8][2];
            c[n8][3] = __expf(c[n8][3] - mn1); s1 += c[n8][3];
        }
        s0 += __shfl_xor_sync(0xffffffffu, s0, 1);
        s0 += __shfl_xor_sync(0xffffffffu, s0, 2);
        s1 += __shfl_xor_sync(0xffffffffu, s1, 1);
        s1 += __shfl_xor_sync(0xffffffffu, s1, 2);
        l0 = l0 * al0 + s0;  m0r = mn0;
        l1 = l1 * al1 + s1;  m1r = mn1;
        #pragma unroll
        for (int n8 = 0; n8 < 8; ++n8) {
            cO[n8][0] *= al0; cO[n8][1] *= al0;
            cO[n8][2] *= al1; cO[n8][3] *= al1;
        }

        uint32_t pH[4][4], pL[4][4];
        #pragma unroll
        for (int kt = 0; kt < 4; ++kt) {
            const int ja = 2 * kt, jb = 2 * kt + 1;
            float h00, h01, h10, h11;
            h00 = __bfloat162float(__float2bfloat16(c[ja][0]));
            h01 = __bfloat162float(__float2bfloat16(c[ja][1]));
            pH[kt][0] = pack_bf2(c[ja][0], c[ja][1]);
            pL[kt][0] = pack_bf2(c[ja][0] - h00, c[ja][1] - h01);
            h10 = __bfloat162float(__float2bfloat16(c[ja][2]));
            h11 = __bfloat162float(__float2bfloat16(c[ja][3]));
            pH[kt][1] = pack_bf2(c[ja][2], c[ja][3]);
            pL[kt][1] = pack_bf2(c[ja][2] - h10, c[ja][3] - h11);
            h00 = __bfloat162float(__float2bfloat16(c[jb][0]));
            h01 = __bfloat162float(__float2bfloat16(c[jb][1]));
            pH[kt][2] = pack_bf2(c[jb][0], c[jb][1]);
            pL[kt][2] = pack_bf2(c[jb][0] - h00, c[jb][1] - h01);
            h10 = __bfloat162float(__float2bfloat16(c[jb][2]));
            h11 = __bfloat162float(__float2bfloat16(c[jb][3]));
            pH[kt][3] = pack_bf2(c[jb][2], c[jb][3]);
            pL[kt][3] = pack_bf2(c[jb][2] - h10, c[jb][3] - h11);
        }

        #pragma unroll
        for (int kt = 0; kt < 4; ++kt) {
            #pragma unroll
            for (int np = 0; np < 4; ++np) {
                uint32_t b[4];
                ldsm_x4_t(b, vBaseH + (kt * 16 * FPAD + np * 16) * 2);
                mma_bf16(cO[2 * np],     pH[kt], b);
                mma_bf16(cO[2 * np + 1], pH[kt], b + 2);
                mma_bf16(cO[2 * np],     pL[kt], b);
                mma_bf16(cO[2 * np + 1], pL[kt], b + 2);
            }
        }
        #pragma unroll
        for (int kt = 0; kt < 4; ++kt) {
            #pragma unroll
            for (int np = 0; np < 4; ++np) {
                uint32_t b[4];
                ldsm_x4_t(b, vBaseL + (kt * 16 * FPAD + np * 16) * 2);
                mma_bf16(cO[2 * np],     pH[kt], b);
                mma_bf16(cO[2 * np + 1], pH[kt], b + 2);
            }
        }
    }

    const int b_ = bh >> 4, h = bh & 15;
    const float i0 = 1.0f / l0, i1 = 1.0f / l1;
    const int mrow0 = qt * 64 + wid * 16 + r_;
    #pragma unroll
    for (int n8 = 0; n8 < 8; ++n8) {
        const int e = n8 * 8 + qc * 2;
        #pragma unroll
        for (int half = 0; half < 2; ++half) {
            const float inv = half ? i1 : i0;
            const float vx = cO[n8][half * 2 + 0] * inv;
            const float vy = cO[n8][half * 2 + 1] * inv;
            const int m = mrow0 + half * 8;
            __nv_bfloat16 hx = __float2bfloat16(vx);
            __nv_bfloat16 hy = __float2bfloat16(vy);
            __nv_bfloat162 hp = __halves2bfloat162(hx, hy);
            __nv_bfloat162 lp = __halves2bfloat162(
                __float2bfloat16(vx - __bfloat162float(hx)),
                __float2bfloat16(vy - __bfloat162float(hy)));
            size_t idx = ((size_t)b_ * NS + m) * NDIM + h * 64 + e;
            *(uint32_t*)&g_oh[idx] = *(uint32_t*)&hp;
            *(uint32_t*)&g_ol[idx] = *(uint32_t*)&lp;
        }
    }
}

// ---------------------------------------------------------------------------
extern "C" void kernel_launch(void* const* d_in, const int* in_sizes, int n_in,
                              void* d_out, int out_size)
{
    const float* x  = (const float*)d_in[0];
    const float* Wq = (const float*)d_in[1];
    const float* bq = (const float*)d_in[2];
    const float* Wk = (const float*)d_in[3];
    const float* bk = (const float*)d_in[4];
    const float* Wv = (const float*)d_in[5];
    const float* bv = (const float*)d_in[6];
    const float* Wo = (const float*)d_in[7];
    const float* bo = (const float*)d_in[8];
    float* out = (float*)d_out;

    const int flash_smem = 6 * FT * (int)sizeof(__nv_bfloat16);   // 55296
    cudaFuncSetAttribute(flash_mma_kernel,
                         cudaFuncAttributeMaxDynamicSharedMemorySize, flash_smem);
    cudaFuncSetAttribute(gemm_mma_kernel,
                         cudaFuncAttributeMaxDynamicSharedMemorySize, GSMEM);

    __nv_bfloat162 *xh2, *xl2;
    cudaGetSymbolAddress((void**)&xh2, g_xh);
    cudaGetSymbolAddress((void**)&xl2, g_xl);

    const int n4 = NM * NDIM / 4;
    split_kernel<<<n4 / 256, 256>>>((const float4*)x, xh2, xl2, n4);
    qkv_w_transpose<<<dim3(32, 2, 48), dim3(32, 32)>>>(Wq, Wk, Wv, bq, bk, bv);
    wo_transpose<<<dim3(32, 32), dim3(32, 32)>>>(Wo);

    gemm_mma_kernel<<<dim3(NM / 128, NQKV / 128), 256, GSMEM>>>(nullptr, nullptr, 0);
    flash_mma_kernel<<<dim3(NS / 64, NB * NH), 128, flash_smem>>>();
    gemm_mma_kernel<<<dim3(NM / 128, NDIM / 128), 256, GSMEM>>>(bo, out, 1);
}

// round 6
// speedup vs baseline: 2.7100x; 1.0863x over previous
#include <cuda_runtime.h>
#include <cuda_bf16.h>
#include <cstdint>

#define NB   2
#define NS   2048
#define NDIM 1024
#define NH   16
#define NHD  64
#define NM   (NB * NS)     // 4096
#define NQKV 3072          // 3 * NH * NHD

// ---------------------------------------------------------------------------
// Scratch (__device__ globals; allocation-free rule)
// ---------------------------------------------------------------------------
__device__ __nv_bfloat16 g_qh[NB * NH * NS * NHD];
__device__ __nv_bfloat16 g_ql[NB * NH * NS * NHD];
__device__ __nv_bfloat16 g_kh[NB * NH * NS * NHD];
__device__ __nv_bfloat16 g_kl[NB * NH * NS * NHD];
__device__ __nv_bfloat16 g_vh[NB * NH * NS * NHD];
__device__ __nv_bfloat16 g_vl[NB * NH * NS * NHD];

__device__ __nv_bfloat16 g_xh[(size_t)NM * NDIM];
__device__ __nv_bfloat16 g_xl[(size_t)NM * NDIM];
__device__ __nv_bfloat16 g_oh[(size_t)NM * NDIM];
__device__ __nv_bfloat16 g_ol[(size_t)NM * NDIM];
__device__ __nv_bfloat16 g_wqh[(size_t)NQKV * NDIM];   // QKV weights, K-major [3072][1024]
__device__ __nv_bfloat16 g_wql[(size_t)NQKV * NDIM];
__device__ __nv_bfloat16 g_woh[(size_t)NDIM * NDIM];   // Wo transposed, K-major [1024][1024]
__device__ __nv_bfloat16 g_wol[(size_t)NDIM * NDIM];
__device__ float g_bqkv[NQKV];

__device__ __forceinline__ uint32_t smem_to_u32(const void* p) {
    uint32_t a;
    asm("{ .reg .u64 t; cvta.to.shared.u64 t, %1; cvt.u32.u64 %0, t; }"
        : "=r"(a) : "l"(p));
    return a;
}

__device__ __forceinline__ void ldsm_x4(uint32_t* r, uint32_t addr) {
    asm volatile("ldmatrix.sync.aligned.m8n8.x4.shared.b16 {%0,%1,%2,%3}, [%4];"
        : "=r"(r[0]), "=r"(r[1]), "=r"(r[2]), "=r"(r[3]) : "r"(addr));
}
__device__ __forceinline__ void ldsm_x4_t(uint32_t* r, uint32_t addr) {
    asm volatile("ldmatrix.sync.aligned.m8n8.x4.trans.shared.b16 {%0,%1,%2,%3}, [%4];"
        : "=r"(r[0]), "=r"(r[1]), "=r"(r[2]), "=r"(r[3]) : "r"(addr));
}
__device__ __forceinline__ void ldsm_x2(uint32_t* r, uint32_t addr) {
    asm volatile("ldmatrix.sync.aligned.m8n8.x2.shared.b16 {%0,%1}, [%2];"
        : "=r"(r[0]), "=r"(r[1]) : "r"(addr));
}
__device__ __forceinline__ void mma_bf16(float* c, const uint32_t* a, const uint32_t* b) {
    asm volatile(
        "mma.sync.aligned.m16n8k16.row.col.f32.bf16.bf16.f32 "
        "{%0,%1,%2,%3}, {%4,%5,%6,%7}, {%8,%9}, {%0,%1,%2,%3};"
        : "+f"(c[0]), "+f"(c[1]), "+f"(c[2]), "+f"(c[3])
        : "r"(a[0]), "r"(a[1]), "r"(a[2]), "r"(a[3]), "r"(b[0]), "r"(b[1]));
}
__device__ __forceinline__ void cpasync16(uint32_t s, const void* g) {
    asm volatile("cp.async.cg.shared.global [%0], [%1], 16;" :: "r"(s), "l"(g));
}
#define CP_COMMIT() asm volatile("cp.async.commit_group;" ::: "memory")
#define CP_WAIT(n)  asm volatile("cp.async.wait_group %0;" :: "n"(n) : "memory")

__device__ __forceinline__ uint32_t pack_bf2(float x, float y) {
    __nv_bfloat162 h = __halves2bfloat162(__float2bfloat16(x), __float2bfloat16(y));
    return *(uint32_t*)&h;
}

// ---------------------------------------------------------------------------
// Conversion kernels
// ---------------------------------------------------------------------------
__global__ void split_kernel(const float4* __restrict__ src,
                             __nv_bfloat162* __restrict__ dh,
                             __nv_bfloat162* __restrict__ dl, int n4)
{
    int i = blockIdx.x * blockDim.x + threadIdx.x;
    if (i >= n4) return;
    float4 v = src[i];
    __nv_bfloat16 hx = __float2bfloat16(v.x), hy = __float2bfloat16(v.y);
    __nv_bfloat16 hz = __float2bfloat16(v.z), hw = __float2bfloat16(v.w);
    __nv_bfloat16 lx = __float2bfloat16(v.x - __bfloat162float(hx));
    __nv_bfloat16 ly = __float2bfloat16(v.y - __bfloat162float(hy));
    __nv_bfloat16 lz = __float2bfloat16(v.z - __bfloat162float(hz));
    __nv_bfloat16 lw = __float2bfloat16(v.w - __bfloat162float(hw));
    dh[2 * i]     = __halves2bfloat162(hx, hy);
    dh[2 * i + 1] = __halves2bfloat162(hz, hw);
    dl[2 * i]     = __halves2bfloat162(lx, ly);
    dl[2 * i + 1] = __halves2bfloat162(lz, lw);
}

// W{q,k,v}[h][d][e] -> g_wq{h,l}[(mat*16+h)*64+e][d]  (K-major, split), + bias concat
__global__ void qkv_w_transpose(const float* __restrict__ Wq, const float* __restrict__ Wk,
                                const float* __restrict__ Wv, const float* __restrict__ bq,
                                const float* __restrict__ bk, const float* __restrict__ bv)
{
    __shared__ float sm[32][33];
    int z = blockIdx.z, mat = z >> 4, h = z & 15;
    const float* W = (mat == 0 ? Wq : mat == 1 ? Wk : Wv) + (size_t)h * NDIM * NHD;
    const float* bias = (mat == 0 ? bq : mat == 1 ? bk : bv) + h * NHD;
    int d0 = blockIdx.x * 32, e0 = blockIdx.y * 32;
    int tx = threadIdx.x, ty = threadIdx.y;
    sm[ty][tx] = W[(size_t)(d0 + ty) * NHD + e0 + tx];
    __syncthreads();
    float v = sm[tx][ty];
    __nv_bfloat16 hv = __float2bfloat16(v);
    __nv_bfloat16 lv = __float2bfloat16(v - __bfloat162float(hv));
    size_t row = (size_t)z * 64 + e0 + ty;
    g_wqh[row * NDIM + d0 + tx] = hv;
    g_wql[row * NDIM + d0 + tx] = lv;
    if (blockIdx.x == 0 && tx == 0) g_bqkv[z * 64 + e0 + ty] = bias[e0 + ty];
}

// Wo[k][n] -> g_wo{h,l}[n][k]
__global__ void wo_transpose(const float* __restrict__ Wo)
{
    __shared__ float sm[32][33];
    int k0 = blockIdx.x * 32, n0 = blockIdx.y * 32;
    int tx = threadIdx.x, ty = threadIdx.y;
    sm[ty][tx] = Wo[(size_t)(k0 + ty) * NDIM + n0 + tx];
    __syncthreads();
    float v = sm[tx][ty];
    __nv_bfloat16 hv = __float2bfloat16(v);
    __nv_bfloat16 lv = __float2bfloat16(v - __bfloat162float(hv));
    g_woh[(size_t)(n0 + ty) * NDIM + k0 + tx] = hv;
    g_wol[(size_t)(n0 + ty) * NDIM + k0 + tx] = lv;
}

// ---------------------------------------------------------------------------
// HMMA split GEMM, shared-k-tile 3-product + cp.async double buffering.
// Block 128x128, 8 warps (2x4), warp tile 64x32, K-tile 32, 32 k-iterations.
// __launch_bounds__(256, 2): cap regs at 128 so 2 blocks/SM co-reside.
// ---------------------------------------------------------------------------
#define KT     32
#define SPAD   40
#define TILE_B (128 * SPAD * 2)   // 10240 bytes per tile
#define BUF_B  (4 * TILE_B)       // 40960 bytes per stage
#define GSMEM  (2 * BUF_B)        // 81920 bytes

__global__ __launch_bounds__(256, 2) void gemm_mma_kernel(const float* __restrict__ bias,
                                                          float* __restrict__ out, int mode)
{
    extern __shared__ __align__(16) char smg[];
    const uint32_t smb = smem_to_u32(smg);

    const int tid = threadIdx.x, wid = tid >> 5, lane = tid & 31;
    const int m0 = blockIdx.x * 128, n0 = blockIdx.y * 128;
    const int warp_m0 = (wid >> 2) * 64;
    const int warp_n0 = (wid & 3) * 32;

    const __nv_bfloat16 *Ah, *Al, *Bh, *Bl;
    if (mode == 0) { Ah = g_xh; Al = g_xl; Bh = g_wqh; Bl = g_wql; }
    else           { Ah = g_oh; Al = g_ol; Bh = g_woh; Bl = g_wol; }

    const int rowA = tid >> 2;            // 0..63 (+64)
    const int col8 = (tid & 3) * 8;
    const uint32_t st0 = (rowA * SPAD + col8) * 2;
    const uint32_t st1 = ((rowA + 64) * SPAD + col8) * 2;

    const __nv_bfloat16* gA0h = Ah + (size_t)(m0 + rowA) * NDIM + col8;
    const __nv_bfloat16* gA1h = Ah + (size_t)(m0 + rowA + 64) * NDIM + col8;
    const __nv_bfloat16* gA0l = Al + (size_t)(m0 + rowA) * NDIM + col8;
    const __nv_bfloat16* gA1l = Al + (size_t)(m0 + rowA + 64) * NDIM + col8;
    const __nv_bfloat16* gB0h = Bh + (size_t)(n0 + rowA) * NDIM + col8;
    const __nv_bfloat16* gB1h = Bh + (size_t)(n0 + rowA + 64) * NDIM + col8;
    const __nv_bfloat16* gB0l = Bl + (size_t)(n0 + rowA) * NDIM + col8;
    const __nv_bfloat16* gB1l = Bl + (size_t)(n0 + rowA + 64) * NDIM + col8;

    const int lm = lane & 15, lq = lane >> 4;
    const int l8 = lane & 7,  lb = (lane >> 3) & 1;
    const uint32_t aOffH = ((warp_m0 + lm) * SPAD + lq * 8) * 2;
    const uint32_t bOffH = 2 * TILE_B + ((warp_n0 + l8) * SPAD + lb * 8) * 2;

    float acc[4][4][4];
    #pragma unroll
    for (int i = 0; i < 4; i++)
        #pragma unroll
        for (int j = 0; j < 4; j++)
            #pragma unroll
            for (int q = 0; q < 4; q++) acc[i][j][q] = 0.0f;

    const int NT = NDIM / KT;   // 32

    {
        const uint32_t b = smb;
        cpasync16(b + st0, gA0h);               cpasync16(b + st1, gA1h);
        cpasync16(b + TILE_B + st0, gA0l);      cpasync16(b + TILE_B + st1, gA1l);
        cpasync16(b + 2 * TILE_B + st0, gB0h);  cpasync16(b + 2 * TILE_B + st1, gB1h);
        cpasync16(b + 3 * TILE_B + st0, gB0l);  cpasync16(b + 3 * TILE_B + st1, gB1l);
        CP_COMMIT();
    }

    for (int t = 0; t < NT; ++t) {
        if (t + 1 < NT) {
            const uint32_t b = smb + ((t + 1) & 1) * BUF_B;
            const int k1 = (t + 1) * KT;
            cpasync16(b + st0, gA0h + k1);               cpasync16(b + st1, gA1h + k1);
            cpasync16(b + TILE_B + st0, gA0l + k1);      cpasync16(b + TILE_B + st1, gA1l + k1);
            cpasync16(b + 2 * TILE_B + st0, gB0h + k1);  cpasync16(b + 2 * TILE_B + st1, gB1h + k1);
            cpasync16(b + 3 * TILE_B + st0, gB0l + k1);  cpasync16(b + 3 * TILE_B + st1, gB1l + k1);
            CP_COMMIT();
            CP_WAIT(1);
        } else {
            CP_WAIT(0);
        }
        __syncthreads();

        const uint32_t buf = smb + (t & 1) * BUF_B;
        const uint32_t aH = buf + aOffH;
        const uint32_t aL = aH + TILE_B;
        const uint32_t bH = buf + bOffH;
        const uint32_t bL = bH + TILE_B;

        #pragma unroll
        for (int kk = 0; kk < 2; ++kk) {
            uint32_t bh2[4][2], bl2[4][2];
            #pragma unroll
            for (int nt = 0; nt < 4; ++nt) {
                ldsm_x2(bh2[nt], bH + (nt * 8 * SPAD + kk * 16) * 2);
                ldsm_x2(bl2[nt], bL + (nt * 8 * SPAD + kk * 16) * 2);
            }
            uint32_t a[4][4];
            // pass 1: Ah * (Bh + Bl)
            #pragma unroll
            for (int mt = 0; mt < 4; ++mt)
                ldsm_x4(a[mt], aH + (mt * 16 * SPAD + kk * 16) * 2);
            #pragma unroll
            for (int nt = 0; nt < 4; ++nt)
                #pragma unroll
                for (int mt = 0; mt < 4; ++mt) {
                    mma_bf16(acc[mt][nt], a[mt], bh2[nt]);
                    mma_bf16(acc[mt][nt], a[mt], bl2[nt]);
                }
            // pass 2: Al * Bh (reuse held Bh frags)
            #pragma unroll
            for (int mt = 0; mt < 4; ++mt)
                ldsm_x4(a[mt], aL + (mt * 16 * SPAD + kk * 16) * 2);
            #pragma unroll
            for (int nt = 0; nt < 4; ++nt)
                #pragma unroll
                for (int mt = 0; mt < 4; ++mt)
                    mma_bf16(acc[mt][nt], a[mt], bh2[nt]);
        }
        __syncthreads();
    }

    // ---- epilogue ----
    const int mrow = lane >> 2;
    const int ncol = (lane & 3) * 2;
    #pragma unroll
    for (int nt = 0; nt < 4; ++nt) {
        const int gn = n0 + warp_n0 + nt * 8 + ncol;
        float2 bb;
        if (mode == 0) bb = *(const float2*)&g_bqkv[gn];
        else           bb = *(const float2*)&bias[gn];
        #pragma unroll
        for (int mt = 0; mt < 4; ++mt) {
            #pragma unroll
            for (int half = 0; half < 2; ++half) {
                const int m = m0 + warp_m0 + mt * 16 + mrow + half * 8;
                float vx = acc[mt][nt][half * 2 + 0] + bb.x;
                float vy = acc[mt][nt][half * 2 + 1] + bb.y;
                if (mode == 0) {
                    const int slot = gn >> 6;
                    const int mat = slot >> 4, h = slot & 15, e = gn & 63;
                    const int b_ = m >> 11, s_ = m & (NS - 1);
                    if (mat == 0) { vx *= 0.125f; vy *= 0.125f; }   // fold 1/sqrt(64)
                    __nv_bfloat16* dh_ = (mat == 0 ? g_qh : mat == 1 ? g_kh : g_vh);
                    __nv_bfloat16* dl_ = (mat == 0 ? g_ql : mat == 1 ? g_kl : g_vl);
                    __nv_bfloat16 hx = __float2bfloat16(vx);
                    __nv_bfloat16 hy = __float2bfloat16(vy);
                    float lxf = vx - __bfloat162float(hx);
                    float lyf = vy - __bfloat162float(hy);
                    size_t idx = (((size_t)(b_ * NH + h)) * NS + s_) * NHD + e;
                    __nv_bfloat162 hp = __halves2bfloat162(hx, hy);
                    __nv_bfloat162 lp = __halves2bfloat162(__float2bfloat16(lxf),
                                                           __float2bfloat16(lyf));
                    *(uint32_t*)&dh_[idx] = *(uint32_t*)&hp;
                    *(uint32_t*)&dl_[idx] = *(uint32_t*)&lp;
                } else {
                    float2 v = make_float2(vx, vy);
                    *(float2*)&out[(size_t)m * NDIM + gn] = v;
                }
            }
        }
    }
}

// ---------------------------------------------------------------------------
// Flash attention with split-bf16 HMMA (unchanged from R4/R5).
// ---------------------------------------------------------------------------
#define FPAD 72
#define FT   (64 * FPAD)

__global__ __launch_bounds__(128) void flash_mma_kernel()
{
    extern __shared__ __align__(16) __nv_bfloat16 smf[];
    __nv_bfloat16* QH = smf;
    __nv_bfloat16* QL = smf + FT;
    __nv_bfloat16* KH = smf + 2 * FT;
    __nv_bfloat16* KL = smf + 3 * FT;
    __nv_bfloat16* VH = smf + 4 * FT;
    __nv_bfloat16* VL = smf + 5 * FT;

    const int tid = threadIdx.x, wid = tid >> 5, lane = tid & 31;
    const int qt = blockIdx.x, bh = blockIdx.y;
    const size_t base = (size_t)bh * NS * NHD;

    {
        const __nv_bfloat16* qsrc[2] = {g_qh + base + (size_t)qt * 64 * NHD,
                                        g_ql + base + (size_t)qt * 64 * NHD};
        __nv_bfloat16* qdst[2] = {QH, QL};
        #pragma unroll
        for (int a = 0; a < 2; a++)
            #pragma unroll
            for (int it = 0; it < 4; it++) {
                int ch = tid + it * 128;
                int r = ch >> 3, c8 = (ch & 7) * 8;
                *(uint4*)&qdst[a][r * FPAD + c8] = *(const uint4*)&qsrc[a][r * 64 + c8];
            }
    }

    const int lm = lane & 15, lq = lane >> 4;
    const int l8 = lane & 7;
    const int sel1 = (lane >> 3) & 1;
    const int sel2 = lane >> 4;
    const int r_  = lane >> 2;
    const int qc  = lane & 3;

    const uint32_t aBaseH = smem_to_u32(QH) + ((wid * 16 + lm) * FPAD + lq * 8) * 2;
    const uint32_t aBaseL = smem_to_u32(QL) + ((wid * 16 + lm) * FPAD + lq * 8) * 2;
    const uint32_t kBaseH = smem_to_u32(KH) + ((sel2 * 8 + l8) * FPAD + sel1 * 8) * 2;
    const uint32_t kBaseL = smem_to_u32(KL) + ((sel2 * 8 + l8) * FPAD + sel1 * 8) * 2;
    const uint32_t vBaseH = smem_to_u32(VH) + ((sel1 * 8 + l8) * FPAD + sel2 * 8) * 2;
    const uint32_t vBaseL = smem_to_u32(VL) + ((sel1 * 8 + l8) * FPAD + sel2 * 8) * 2;

    float cO[8][4];
    #pragma unroll
    for (int i = 0; i < 8; i++)
        #pragma unroll
        for (int j = 0; j < 4; j++) cO[i][j] = 0.0f;
    float m0r = -1e30f, m1r = -1e30f, l0 = 0.0f, l1 = 0.0f;

    for (int j = 0; j <= qt; ++j) {
        __syncthreads();
        {
            const size_t off = base + (size_t)j * 64 * NHD;
            const __nv_bfloat16* src[4] = {g_kh + off, g_kl + off, g_vh + off, g_vl + off};
            __nv_bfloat16* dst[4] = {KH, KL, VH, VL};
            #pragma unroll
            for (int a = 0; a < 4; a++)
                #pragma unroll
                for (int it = 0; it < 4; it++) {
                    int ch = tid + it * 128;
                    int r = ch >> 3, c8 = (ch & 7) * 8;
                    *(uint4*)&dst[a][r * FPAD + c8] = *(const uint4*)&src[a][r * 64 + c8];
                }
        }
        __syncthreads();

        float c[8][4];
        #pragma unroll
        for (int i = 0; i < 8; i++)
            #pragma unroll
            for (int q = 0; q < 4; q++) c[i][q] = 0.0f;

        #pragma unroll
        for (int kt = 0; kt < 4; ++kt) {
            uint32_t aH[4], aL[4];
            ldsm_x4(aH, aBaseH + kt * 16 * 2);
            ldsm_x4(aL, aBaseL + kt * 16 * 2);
            #pragma unroll
            for (int np = 0; np < 4; ++np) {
                uint32_t b[4];
                ldsm_x4(b, kBaseH + (np * 16 * FPAD + kt * 16) * 2);
                mma_bf16(c[2 * np],     aH, b);
                mma_bf16(c[2 * np + 1], aH, b + 2);
                mma_bf16(c[2 * np],     aL, b);
                mma_bf16(c[2 * np + 1], aL, b + 2);
            }
            #pragma unroll
            for (int np = 0; np < 4; ++np) {
                uint32_t b[4];
                ldsm_x4(b, kBaseL + (np * 16 * FPAD + kt * 16) * 2);
                mma_bf16(c[2 * np],     aH, b);
                mma_bf16(c[2 * np + 1], aH, b + 2);
            }
        }

        if (j == qt) {
            const int row0 = wid * 16 + r_;
            #pragma unroll
            for (int n8 = 0; n8 < 8; ++n8) {
                const int col = n8 * 8 + qc * 2;
                if (col     > row0)     c[n8][0] = -1e30f;
                if (col + 1 > row0)     c[n8][1] = -1e30f;
                if (col     > row0 + 8) c[n8][2] = -1e30f;
                if (col + 1 > row0 + 8) c[n8][3] = -1e30f;
            }
        }

        float mt0 = -1e30f, mt1 = -1e30f;
        #pragma unroll
        for (int n8 = 0; n8 < 8; ++n8) {
            mt0 = fmaxf(mt0, fmaxf(c[n8][0], c[n8][1]));
            mt1 = fmaxf(mt1, fmaxf(c[n8][2], c[n8][3]));
        }
        mt0 = fmaxf(mt0, __shfl_xor_sync(0xffffffffu, mt0, 1));
        mt0 = fmaxf(mt0, __shfl_xor_sync(0xffffffffu, mt0, 2));
        mt1 = fmaxf(mt1, __shfl_xor_sync(0xffffffffu, mt1, 1));
        mt1 = fmaxf(mt1, __shfl_xor_sync(0xffffffffu, mt1, 2));
        const float mn0 = fmaxf(m0r, mt0);
        const float mn1 = fmaxf(m1r, mt1);
        const float al0 = __expf(m0r - mn0);
        const float al1 = __expf(m1r - mn1);
        float s0 = 0.0f, s1 = 0.0f;
        #pragma unroll
        for (int n8 = 0; n8 < 8; ++n8) {
            c[n8][0] = __expf(c[n8][0] - mn0); s0 += c[n8][0];
            c[n8][1] = __expf(c[n8][1] - mn0); s0 += c[n8][1];
            c[n8][2] = __expf(c[n8][2] - mn1); s1 += c[n8][2];
            c[n8][3] = __expf(c[n8][3] - mn1); s1 += c[n8][3];
        }
        s0 += __shfl_xor_sync(0xffffffffu, s0, 1);
        s0 += __shfl_xor_sync(0xffffffffu, s0, 2);
        s1 += __shfl_xor_sync(0xffffffffu, s1, 1);
        s1 += __shfl_xor_sync(0xffffffffu, s1, 2);
        l0 = l0 * al0 + s0;  m0r = mn0;
        l1 = l1 * al1 + s1;  m1r = mn1;
        #pragma unroll
        for (int n8 = 0; n8 < 8; ++n8) {
            cO[n8][0] *= al0; cO[n8][1] *= al0;
            cO[n8][2] *= al1; cO[n8][3] *= al1;
        }

        uint32_t pH[4][4], pL[4][4];
        #pragma unroll
        for (int kt = 0; kt < 4; ++kt) {
            const int ja = 2 * kt, jb = 2 * kt + 1;
            float h00, h01, h10, h11;
            h00 = __bfloat162float(__float2bfloat16(c[ja][0]));
            h01 = __bfloat162float(__float2bfloat16(c[ja][1]));
            pH[kt][0] = pack_bf2(c[ja][0], c[ja][1]);
            pL[kt][0] = pack_bf2(c[ja][0] - h00, c[ja][1] - h01);
            h10 = __bfloat162float(__float2bfloat16(c[ja][2]));
            h11 = __bfloat162float(__float2bfloat16(c[ja][3]));
            pH[kt][1] = pack_bf2(c[ja][2], c[ja][3]);
            pL[kt][1] = pack_bf2(c[ja][2] - h10, c[ja][3] - h11);
            h00 = __bfloat162float(__float2bfloat16(c[jb][0]));
            h01 = __bfloat162float(__float2bfloat16(c[jb][1]));
            pH[kt][2] = pack_bf2(c[jb][0], c[jb][1]);
            pL[kt][2] = pack_bf2(c[jb][0] - h00, c[jb][1] - h01);
            h10 = __bfloat162float(__float2bfloat16(c[jb][2]));
            h11 = __bfloat162float(__float2bfloat16(c[jb][3]));
            pH[kt][3] = pack_bf2(c[jb][2], c[jb][3]);
            pL[kt][3] = pack_bf2(c[jb][2] - h10, c[jb][3] - h11);
        }

        #pragma unroll
        for (int kt = 0; kt < 4; ++kt) {
            #pragma unroll
            for (int np = 0; np < 4; ++np) {
                uint32_t b[4];
                ldsm_x4_t(b, vBaseH + (kt * 16 * FPAD + np * 16) * 2);
                mma_bf16(cO[2 * np],     pH[kt], b);
                mma_bf16(cO[2 * np + 1], pH[kt], b + 2);
                mma_bf16(cO[2 * np],     pL[kt], b);
                mma_bf16(cO[2 * np + 1], pL[kt], b + 2);
            }
        }
        #pragma unroll
        for (int kt = 0; kt < 4; ++kt) {
            #pragma unroll
            for (int np = 0; np < 4; ++np) {
                uint32_t b[4];
                ldsm_x4_t(b, vBaseL + (kt * 16 * FPAD + np * 16) * 2);
                mma_bf16(cO[2 * np],     pH[kt], b);
                mma_bf16(cO[2 * np + 1], pH[kt], b + 2);
            }
        }
    }

    const int b_ = bh >> 4, h = bh & 15;
    const float i0 = 1.0f / l0, i1 = 1.0f / l1;
    const int mrow0 = qt * 64 + wid * 16 + r_;
    #pragma unroll
    for (int n8 = 0; n8 < 8; ++n8) {
        const int e = n8 * 8 + qc * 2;
        #pragma unroll
        for (int half = 0; half < 2; ++half) {
            const float inv = half ? i1 : i0;
            const float vx = cO[n8][half * 2 + 0] * inv;
            const float vy = cO[n8][half * 2 + 1] * inv;
            const int m = mrow0 + half * 8;
            __nv_bfloat16 hx = __float2bfloat16(vx);
            __nv_bfloat16 hy = __float2bfloat16(vy);
            __nv_bfloat162 hp = __halves2bfloat162(hx, hy);
            __nv_bfloat162 lp = __halves2bfloat162(
                __float2bfloat16(vx - __bfloat162float(hx)),
                __float2bfloat16(vy - __bfloat162float(hy)));
            size_t idx = ((size_t)b_ * NS + m) * NDIM + h * 64 + e;
            *(uint32_t*)&g_oh[idx] = *(uint32_t*)&hp;
            *(uint32_t*)&g_ol[idx] = *(uint32_t*)&lp;
        }
    }
}

// ---------------------------------------------------------------------------
extern "C" void kernel_launch(void* const* d_in, const int* in_sizes, int n_in,
                              void* d_out, int out_size)
{
    const float* x  = (const float*)d_in[0];
    const float* Wq = (const float*)d_in[1];
    const float* bq = (const float*)d_in[2];
    const float* Wk = (const float*)d_in[3];
    const float* bk = (const float*)d_in[4];
    const float* Wv = (const float*)d_in[5];
    const float* bv = (const float*)d_in[6];
    const float* Wo = (const float*)d_in[7];
    const float* bo = (const float*)d_in[8];
    float* out = (float*)d_out;

    const int flash_smem = 6 * FT * (int)sizeof(__nv_bfloat16);   // 55296
    cudaFuncSetAttribute(flash_mma_kernel,
                         cudaFuncAttributeMaxDynamicSharedMemorySize, flash_smem);
    cudaFuncSetAttribute(gemm_mma_kernel,
                         cudaFuncAttributeMaxDynamicSharedMemorySize, GSMEM);

    __nv_bfloat162 *xh2, *xl2;
    cudaGetSymbolAddress((void**)&xh2, g_xh);
    cudaGetSymbolAddress((void**)&xl2, g_xl);

    const int n4 = NM * NDIM / 4;
    split_kernel<<<n4 / 256, 256>>>((const float4*)x, xh2, xl2, n4);
    qkv_w_transpose<<<dim3(32, 2, 48), dim3(32, 32)>>>(Wq, Wk, Wv, bq, bk, bv);
    wo_transpose<<<dim3(32, 32), dim3(32, 32)>>>(Wo);

    gemm_mma_kernel<<<dim3(NM / 128, NQKV / 128), 256, GSMEM>>>(nullptr, nullptr, 0);
    flash_mma_kernel<<<dim3(NS / 64, NB * NH), 128, flash_smem>>>();
    gemm_mma_kernel<<<dim3(NM / 128, NDIM / 128), 256, GSMEM>>>(bo, out, 1);
}

// round 7
// speedup vs baseline: 2.7174x; 1.0027x over previous
#include <cuda_runtime.h>
#include <cuda_bf16.h>
#include <cstdint>

#define NB   2
#define NS   2048
#define NDIM 1024
#define NH   16
#define NHD  64
#define NM   (NB * NS)     // 4096
#define NQKV 3072          // 3 * NH * NHD

// ---------------------------------------------------------------------------
// Scratch (__device__ globals; allocation-free rule)
// ---------------------------------------------------------------------------
__device__ __nv_bfloat16 g_qh[NB * NH * NS * NHD];
__device__ __nv_bfloat16 g_ql[NB * NH * NS * NHD];
__device__ __nv_bfloat16 g_kh[NB * NH * NS * NHD];
__device__ __nv_bfloat16 g_kl[NB * NH * NS * NHD];
__device__ __nv_bfloat16 g_vh[NB * NH * NS * NHD];
__device__ __nv_bfloat16 g_vl[NB * NH * NS * NHD];

__device__ __nv_bfloat16 g_xh[(size_t)NM * NDIM];
__device__ __nv_bfloat16 g_xl[(size_t)NM * NDIM];
__device__ __nv_bfloat16 g_oh[(size_t)NM * NDIM];
__device__ __nv_bfloat16 g_ol[(size_t)NM * NDIM];
__device__ __nv_bfloat16 g_wqh[(size_t)NQKV * NDIM];   // QKV weights, K-major [3072][1024]
__device__ __nv_bfloat16 g_wql[(size_t)NQKV * NDIM];
__device__ __nv_bfloat16 g_woh[(size_t)NDIM * NDIM];   // Wo transposed, K-major [1024][1024]
__device__ __nv_bfloat16 g_wol[(size_t)NDIM * NDIM];
__device__ float g_bqkv[NQKV];

__device__ __forceinline__ uint32_t smem_to_u32(const void* p) {
    uint32_t a;
    asm("{ .reg .u64 t; cvta.to.shared.u64 t, %1; cvt.u32.u64 %0, t; }"
        : "=r"(a) : "l"(p));
    return a;
}

__device__ __forceinline__ void ldsm_x4(uint32_t* r, uint32_t addr) {
    asm volatile("ldmatrix.sync.aligned.m8n8.x4.shared.b16 {%0,%1,%2,%3}, [%4];"
        : "=r"(r[0]), "=r"(r[1]), "=r"(r[2]), "=r"(r[3]) : "r"(addr));
}
__device__ __forceinline__ void ldsm_x4_t(uint32_t* r, uint32_t addr) {
    asm volatile("ldmatrix.sync.aligned.m8n8.x4.trans.shared.b16 {%0,%1,%2,%3}, [%4];"
        : "=r"(r[0]), "=r"(r[1]), "=r"(r[2]), "=r"(r[3]) : "r"(addr));
}
__device__ __forceinline__ void ldsm_x2(uint32_t* r, uint32_t addr) {
    asm volatile("ldmatrix.sync.aligned.m8n8.x2.shared.b16 {%0,%1}, [%2];"
        : "=r"(r[0]), "=r"(r[1]) : "r"(addr));
}
__device__ __forceinline__ void mma_bf16(float* c, const uint32_t* a, const uint32_t* b) {
    asm volatile(
        "mma.sync.aligned.m16n8k16.row.col.f32.bf16.bf16.f32 "
        "{%0,%1,%2,%3}, {%4,%5,%6,%7}, {%8,%9}, {%0,%1,%2,%3};"
        : "+f"(c[0]), "+f"(c[1]), "+f"(c[2]), "+f"(c[3])
        : "r"(a[0]), "r"(a[1]), "r"(a[2]), "r"(a[3]), "r"(b[0]), "r"(b[1]));
}
__device__ __forceinline__ void cpasync16(uint32_t s, const void* g) {
    asm volatile("cp.async.cg.shared.global [%0], [%1], 16;" :: "r"(s), "l"(g));
}
#define CP_COMMIT() asm volatile("cp.async.commit_group;" ::: "memory")
#define CP_WAIT(n)  asm volatile("cp.async.wait_group %0;" :: "n"(n) : "memory")

__device__ __forceinline__ uint32_t pack_bf2(float x, float y) {
    __nv_bfloat162 h = __halves2bfloat162(__float2bfloat16(x), __float2bfloat16(y));
    return *(uint32_t*)&h;
}

// ---------------------------------------------------------------------------
// Conversion kernels
// ---------------------------------------------------------------------------
__global__ void split_kernel(const float4* __restrict__ src,
                             __nv_bfloat162* __restrict__ dh,
                             __nv_bfloat162* __restrict__ dl, int n4)
{
    int i = blockIdx.x * blockDim.x + threadIdx.x;
    if (i >= n4) return;
    float4 v = src[i];
    __nv_bfloat16 hx = __float2bfloat16(v.x), hy = __float2bfloat16(v.y);
    __nv_bfloat16 hz = __float2bfloat16(v.z), hw = __float2bfloat16(v.w);
    __nv_bfloat16 lx = __float2bfloat16(v.x - __bfloat162float(hx));
    __nv_bfloat16 ly = __float2bfloat16(v.y - __bfloat162float(hy));
    __nv_bfloat16 lz = __float2bfloat16(v.z - __bfloat162float(hz));
    __nv_bfloat16 lw = __float2bfloat16(v.w - __bfloat162float(hw));
    dh[2 * i]     = __halves2bfloat162(hx, hy);
    dh[2 * i + 1] = __halves2bfloat162(hz, hw);
    dl[2 * i]     = __halves2bfloat162(lx, ly);
    dl[2 * i + 1] = __halves2bfloat162(lz, lw);
}

// W{q,k,v}[h][d][e] -> g_wq{h,l}[(mat*16+h)*64+e][d]  (K-major, split), + bias concat
__global__ void qkv_w_transpose(const float* __restrict__ Wq, const float* __restrict__ Wk,
                                const float* __restrict__ Wv, const float* __restrict__ bq,
                                const float* __restrict__ bk, const float* __restrict__ bv)
{
    __shared__ float sm[32][33];
    int z = blockIdx.z, mat = z >> 4, h = z & 15;
    const float* W = (mat == 0 ? Wq : mat == 1 ? Wk : Wv) + (size_t)h * NDIM * NHD;
    const float* bias = (mat == 0 ? bq : mat == 1 ? bk : bv) + h * NHD;
    int d0 = blockIdx.x * 32, e0 = blockIdx.y * 32;
    int tx = threadIdx.x, ty = threadIdx.y;
    sm[ty][tx] = W[(size_t)(d0 + ty) * NHD + e0 + tx];
    __syncthreads();
    float v = sm[tx][ty];
    __nv_bfloat16 hv = __float2bfloat16(v);
    __nv_bfloat16 lv = __float2bfloat16(v - __bfloat162float(hv));
    size_t row = (size_t)z * 64 + e0 + ty;
    g_wqh[row * NDIM + d0 + tx] = hv;
    g_wql[row * NDIM + d0 + tx] = lv;
    if (blockIdx.x == 0 && tx == 0) g_bqkv[z * 64 + e0 + ty] = bias[e0 + ty];
}

// Wo[k][n] -> g_wo{h,l}[n][k]
__global__ void wo_transpose(const float* __restrict__ Wo)
{
    __shared__ float sm[32][33];
    int k0 = blockIdx.x * 32, n0 = blockIdx.y * 32;
    int tx = threadIdx.x, ty = threadIdx.y;
    sm[ty][tx] = Wo[(size_t)(k0 + ty) * NDIM + n0 + tx];
    __syncthreads();
    float v = sm[tx][ty];
    __nv_bfloat16 hv = __float2bfloat16(v);
    __nv_bfloat16 lv = __float2bfloat16(v - __bfloat162float(hv));
    g_woh[(size_t)(n0 + ty) * NDIM + k0 + tx] = hv;
    g_wol[(size_t)(n0 + ty) * NDIM + k0 + tx] = lv;
}

// ---------------------------------------------------------------------------
// HMMA split GEMM (unchanged from R6).
// ---------------------------------------------------------------------------
#define KT     32
#define SPAD   40
#define TILE_B (128 * SPAD * 2)   // 10240 bytes per tile
#define BUF_B  (4 * TILE_B)       // 40960 bytes per stage
#define GSMEM  (2 * BUF_B)        // 81920 bytes

__global__ __launch_bounds__(256, 2) void gemm_mma_kernel(const float* __restrict__ bias,
                                                          float* __restrict__ out, int mode)
{
    extern __shared__ __align__(16) char smg[];
    const uint32_t smb = smem_to_u32(smg);

    const int tid = threadIdx.x, wid = tid >> 5, lane = tid & 31;
    const int m0 = blockIdx.x * 128, n0 = blockIdx.y * 128;
    const int warp_m0 = (wid >> 2) * 64;
    const int warp_n0 = (wid & 3) * 32;

    const __nv_bfloat16 *Ah, *Al, *Bh, *Bl;
    if (mode == 0) { Ah = g_xh; Al = g_xl; Bh = g_wqh; Bl = g_wql; }
    else           { Ah = g_oh; Al = g_ol; Bh = g_woh; Bl = g_wol; }

    const int rowA = tid >> 2;
    const int col8 = (tid & 3) * 8;
    const uint32_t st0 = (rowA * SPAD + col8) * 2;
    const uint32_t st1 = ((rowA + 64) * SPAD + col8) * 2;

    const __nv_bfloat16* gA0h = Ah + (size_t)(m0 + rowA) * NDIM + col8;
    const __nv_bfloat16* gA1h = Ah + (size_t)(m0 + rowA + 64) * NDIM + col8;
    const __nv_bfloat16* gA0l = Al + (size_t)(m0 + rowA) * NDIM + col8;
    const __nv_bfloat16* gA1l = Al + (size_t)(m0 + rowA + 64) * NDIM + col8;
    const __nv_bfloat16* gB0h = Bh + (size_t)(n0 + rowA) * NDIM + col8;
    const __nv_bfloat16* gB1h = Bh + (size_t)(n0 + rowA + 64) * NDIM + col8;
    const __nv_bfloat16* gB0l = Bl + (size_t)(n0 + rowA) * NDIM + col8;
    const __nv_bfloat16* gB1l = Bl + (size_t)(n0 + rowA + 64) * NDIM + col8;

    const int lm = lane & 15, lq = lane >> 4;
    const int l8 = lane & 7,  lb = (lane >> 3) & 1;
    const uint32_t aOffH = ((warp_m0 + lm) * SPAD + lq * 8) * 2;
    const uint32_t bOffH = 2 * TILE_B + ((warp_n0 + l8) * SPAD + lb * 8) * 2;

    float acc[4][4][4];
    #pragma unroll
    for (int i = 0; i < 4; i++)
        #pragma unroll
        for (int j = 0; j < 4; j++)
            #pragma unroll
            for (int q = 0; q < 4; q++) acc[i][j][q] = 0.0f;

    const int NT = NDIM / KT;   // 32

    {
        const uint32_t b = smb;
        cpasync16(b + st0, gA0h);               cpasync16(b + st1, gA1h);
        cpasync16(b + TILE_B + st0, gA0l);      cpasync16(b + TILE_B + st1, gA1l);
        cpasync16(b + 2 * TILE_B + st0, gB0h);  cpasync16(b + 2 * TILE_B + st1, gB1h);
        cpasync16(b + 3 * TILE_B + st0, gB0l);  cpasync16(b + 3 * TILE_B + st1, gB1l);
        CP_COMMIT();
    }

    for (int t = 0; t < NT; ++t) {
        if (t + 1 < NT) {
            const uint32_t b = smb + ((t + 1) & 1) * BUF_B;
            const int k1 = (t + 1) * KT;
            cpasync16(b + st0, gA0h + k1);               cpasync16(b + st1, gA1h + k1);
            cpasync16(b + TILE_B + st0, gA0l + k1);      cpasync16(b + TILE_B + st1, gA1l + k1);
            cpasync16(b + 2 * TILE_B + st0, gB0h + k1);  cpasync16(b + 2 * TILE_B + st1, gB1h + k1);
            cpasync16(b + 3 * TILE_B + st0, gB0l + k1);  cpasync16(b + 3 * TILE_B + st1, gB1l + k1);
            CP_COMMIT();
            CP_WAIT(1);
        } else {
            CP_WAIT(0);
        }
        __syncthreads();

        const uint32_t buf = smb + (t & 1) * BUF_B;
        const uint32_t aH = buf + aOffH;
        const uint32_t aL = aH + TILE_B;
        const uint32_t bH = buf + bOffH;
        const uint32_t bL = bH + TILE_B;

        #pragma unroll
        for (int kk = 0; kk < 2; ++kk) {
            uint32_t bh2[4][2], bl2[4][2];
            #pragma unroll
            for (int nt = 0; nt < 4; ++nt) {
                ldsm_x2(bh2[nt], bH + (nt * 8 * SPAD + kk * 16) * 2);
                ldsm_x2(bl2[nt], bL + (nt * 8 * SPAD + kk * 16) * 2);
            }
            uint32_t a[4][4];
            #pragma unroll
            for (int mt = 0; mt < 4; ++mt)
                ldsm_x4(a[mt], aH + (mt * 16 * SPAD + kk * 16) * 2);
            #pragma unroll
            for (int nt = 0; nt < 4; ++nt)
                #pragma unroll
                for (int mt = 0; mt < 4; ++mt) {
                    mma_bf16(acc[mt][nt], a[mt], bh2[nt]);
                    mma_bf16(acc[mt][nt], a[mt], bl2[nt]);
                }
            #pragma unroll
            for (int mt = 0; mt < 4; ++mt)
                ldsm_x4(a[mt], aL + (mt * 16 * SPAD + kk * 16) * 2);
            #pragma unroll
            for (int nt = 0; nt < 4; ++nt)
                #pragma unroll
                for (int mt = 0; mt < 4; ++mt)
                    mma_bf16(acc[mt][nt], a[mt], bh2[nt]);
        }
        __syncthreads();
    }

    const int mrow = lane >> 2;
    const int ncol = (lane & 3) * 2;
    #pragma unroll
    for (int nt = 0; nt < 4; ++nt) {
        const int gn = n0 + warp_n0 + nt * 8 + ncol;
        float2 bb;
        if (mode == 0) bb = *(const float2*)&g_bqkv[gn];
        else           bb = *(const float2*)&bias[gn];
        #pragma unroll
        for (int mt = 0; mt < 4; ++mt) {
            #pragma unroll
            for (int half = 0; half < 2; ++half) {
                const int m = m0 + warp_m0 + mt * 16 + mrow + half * 8;
                float vx = acc[mt][nt][half * 2 + 0] + bb.x;
                float vy = acc[mt][nt][half * 2 + 1] + bb.y;
                if (mode == 0) {
                    const int slot = gn >> 6;
                    const int mat = slot >> 4, h = slot & 15, e = gn & 63;
                    const int b_ = m >> 11, s_ = m & (NS - 1);
                    if (mat == 0) { vx *= 0.125f; vy *= 0.125f; }
                    __nv_bfloat16* dh_ = (mat == 0 ? g_qh : mat == 1 ? g_kh : g_vh);
                    __nv_bfloat16* dl_ = (mat == 0 ? g_ql : mat == 1 ? g_kl : g_vl);
                    __nv_bfloat16 hx = __float2bfloat16(vx);
                    __nv_bfloat16 hy = __float2bfloat16(vy);
                    float lxf = vx - __bfloat162float(hx);
                    float lyf = vy - __bfloat162float(hy);
                    size_t idx = (((size_t)(b_ * NH + h)) * NS + s_) * NHD + e;
                    __nv_bfloat162 hp = __halves2bfloat162(hx, hy);
                    __nv_bfloat162 lp = __halves2bfloat162(__float2bfloat16(lxf),
                                                           __float2bfloat16(lyf));
                    *(uint32_t*)&dh_[idx] = *(uint32_t*)&hp;
                    *(uint32_t*)&dl_[idx] = *(uint32_t*)&lp;
                } else {
                    float2 v = make_float2(vx, vy);
                    *(float2*)&out[(size_t)m * NDIM + gn] = v;
                }
            }
        }
    }
}

// ---------------------------------------------------------------------------
// Flash attention, split-bf16 HMMA + cp.async double-buffered K/V stages.
// smem: Q (2 tiles) + 2 stages x {KH,KL,VH,VL}. One barrier per kv-tile.
// Heavy-first: qt = 31 - blockIdx.x.
// ---------------------------------------------------------------------------
#define FPAD 72
#define FT   (64 * FPAD)
#define FTB  (FT * 2)                 // 9216 bytes per tile
#define FSTAGE (4 * FTB)              // 36864 bytes per KV stage
#define FSMEM  (2 * FTB + 2 * FSTAGE) // 92160 bytes

__global__ __launch_bounds__(128) void flash_mma_kernel()
{
    extern __shared__ __align__(16) char smfc[];
    const uint32_t smb = smem_to_u32(smfc);
    const uint32_t qBase0 = smb;              // QH, QL
    const uint32_t kvBase = smb + 2 * FTB;    // stages

    const int tid = threadIdx.x, wid = tid >> 5, lane = tid & 31;
    const int qt = (int)gridDim.x - 1 - (int)blockIdx.x;   // heavy blocks first
    const int bh = blockIdx.y;
    const size_t base = (size_t)bh * NS * NHD;

    // per-thread cp.async chunk mapping (4 chunks per 64x64 tile)
    int cr[4], cc[4];
    uint32_t cs[4];
    #pragma unroll
    for (int it = 0; it < 4; it++) {
        int ch = tid + it * 128;
        cr[it] = ch >> 3;
        cc[it] = (ch & 7) * 8;
        cs[it] = (cr[it] * FPAD + cc[it]) * 2;
    }

    // prologue: Q (hi/lo) + KV stage 0, one group
    {
        const __nv_bfloat16* qh = g_qh + base + (size_t)qt * 64 * NHD;
        const __nv_bfloat16* ql = g_ql + base + (size_t)qt * 64 * NHD;
        #pragma unroll
        for (int it = 0; it < 4; it++) {
            cpasync16(qBase0 + cs[it],       qh + cr[it] * 64 + cc[it]);
            cpasync16(qBase0 + FTB + cs[it], ql + cr[it] * 64 + cc[it]);
        }
        const __nv_bfloat16* src[4] = {g_kh + base, g_kl + base, g_vh + base, g_vl + base};
        #pragma unroll
        for (int a = 0; a < 4; a++)
            #pragma unroll
            for (int it = 0; it < 4; it++)
                cpasync16(kvBase + a * FTB + cs[it], src[a] + cr[it] * 64 + cc[it]);
        CP_COMMIT();
    }

    const int lm = lane & 15, lq = lane >> 4;
    const int l8 = lane & 7;
    const int sel1 = (lane >> 3) & 1;
    const int sel2 = lane >> 4;
    const int r_  = lane >> 2;
    const int qc  = lane & 3;

    const uint32_t aBaseH = qBase0 + ((wid * 16 + lm) * FPAD + lq * 8) * 2;
    const uint32_t aBaseL = aBaseH + FTB;
    const uint32_t kOff = ((sel2 * 8 + l8) * FPAD + sel1 * 8) * 2;            // in KH tile
    const uint32_t vOff = ((sel1 * 8 + l8) * FPAD + sel2 * 8) * 2;            // in VH tile

    float cO[8][4];
    #pragma unroll
    for (int i = 0; i < 8; i++)
        #pragma unroll
        for (int j = 0; j < 4; j++) cO[i][j] = 0.0f;
    float m0r = -1e30f, m1r = -1e30f, l0 = 0.0f, l1 = 0.0f;

    for (int j = 0; j <= qt; ++j) {
        CP_WAIT(0);
        __syncthreads();

        if (j < qt) {   // issue stage j+1 (safe: everyone synced past its last read)
            const uint32_t sb = kvBase + ((j + 1) & 1) * FSTAGE;
            const size_t off = base + (size_t)(j + 1) * 64 * NHD;
            const __nv_bfloat16* src[4] = {g_kh + off, g_kl + off, g_vh + off, g_vl + off};
            #pragma unroll
            for (int a = 0; a < 4; a++)
                #pragma unroll
                for (int it = 0; it < 4; it++)
                    cpasync16(sb + a * FTB + cs[it], src[a] + cr[it] * 64 + cc[it]);
            CP_COMMIT();
        }

        const uint32_t stage = kvBase + (j & 1) * FSTAGE;
        const uint32_t kBaseH = stage + kOff;
        const uint32_t kBaseL = stage + FTB + kOff;
        const uint32_t vBaseH = stage + 2 * FTB + vOff;
        const uint32_t vBaseL = stage + 3 * FTB + vOff;

        float c[8][4];
        #pragma unroll
        for (int i = 0; i < 8; i++)
            #pragma unroll
            for (int q = 0; q < 4; q++) c[i][q] = 0.0f;

        #pragma unroll
        for (int kt = 0; kt < 4; ++kt) {
            uint32_t aH[4], aL[4];
            ldsm_x4(aH, aBaseH + kt * 16 * 2);
            ldsm_x4(aL, aBaseL + kt * 16 * 2);
            #pragma unroll
            for (int np = 0; np < 4; ++np) {
                uint32_t b[4];
                ldsm_x4(b, kBaseH + (np * 16 * FPAD + kt * 16) * 2);
                mma_bf16(c[2 * np],     aH, b);
                mma_bf16(c[2 * np + 1], aH, b + 2);
                mma_bf16(c[2 * np],     aL, b);
                mma_bf16(c[2 * np + 1], aL, b + 2);
            }
            #pragma unroll
            for (int np = 0; np < 4; ++np) {
                uint32_t b[4];
                ldsm_x4(b, kBaseL + (np * 16 * FPAD + kt * 16) * 2);
                mma_bf16(c[2 * np],     aH, b);
                mma_bf16(c[2 * np + 1], aH, b + 2);
            }
        }

        if (j == qt) {
            const int row0 = wid * 16 + r_;
            #pragma unroll
            for (int n8 = 0; n8 < 8; ++n8) {
                const int col = n8 * 8 + qc * 2;
                if (col     > row0)     c[n8][0] = -1e30f;
                if (col + 1 > row0)     c[n8][1] = -1e30f;
                if (col     > row0 + 8) c[n8][2] = -1e30f;
                if (col + 1 > row0 + 8) c[n8][3] = -1e30f;
            }
        }

        float mt0 = -1e30f, mt1 = -1e30f;
        #pragma unroll
        for (int n8 = 0; n8 < 8; ++n8) {
            mt0 = fmaxf(mt0, fmaxf(c[n8][0], c[n8][1]));
            mt1 = fmaxf(mt1, fmaxf(c[n8][2], c[n8][3]));
        }
        mt0 = fmaxf(mt0, __shfl_xor_sync(0xffffffffu, mt0, 1));
        mt0 = fmaxf(mt0, __shfl_xor_sync(0xffffffffu, mt0, 2));
        mt1 = fmaxf(mt1, __shfl_xor_sync(0xffffffffu, mt1, 1));
        mt1 = fmaxf(mt1, __shfl_xor_sync(0xffffffffu, mt1, 2));
        const float mn0 = fmaxf(m0r, mt0);
        const float mn1 = fmaxf(m1r, mt1);
        const float al0 = __expf(m0r - mn0);
        const float al1 = __expf(m1r - mn1);
        float s0 = 0.0f, s1 = 0.0f;
        #pragma unroll
        for (int n8 = 0; n8 < 8; ++n8) {
            c[n8][0] = __expf(c[n8][0] - mn0); s0 += c[n8][0];
            c[n8][1] = __expf(c[n8][1] - mn0); s0 += c[n8][1];
            c[n8][2] = __expf(c[n8][2] - mn1); s1 += c[n8][2];
            c[n8][3] = __expf(c[n8][3] - mn1); s1 += c[n8][3];
        }
        s0 += __shfl_xor_sync(0xffffffffu, s0, 1);
        s0 += __shfl_xor_sync(0xffffffffu, s0, 2);
        s1 += __shfl_xor_sync(0xffffffffu, s1, 1);
        s1 += __shfl_xor_sync(0xffffffffu, s1, 2);
        l0 = l0 * al0 + s0;  m0r = mn0;
        l1 = l1 * al1 + s1;  m1r = mn1;
        #pragma unroll
        for (int n8 = 0; n8 < 8; ++n8) {
            cO[n8][0] *= al0; cO[n8][1] *= al0;
            cO[n8][2] *= al1; cO[n8][3] *= al1;
        }

        uint32_t pH[4][4], pL[4][4];
        #pragma unroll
        for (int kt = 0; kt < 4; ++kt) {
            const int ja = 2 * kt, jb = 2 * kt + 1;
            float h00, h01, h10, h11;
            h00 = __bfloat162float(__float2bfloat16(c[ja][0]));
            h01 = __bfloat162float(__float2bfloat16(c[ja][1]));
            pH[kt][0] = pack_bf2(c[ja][0], c[ja][1]);
            pL[kt][0] = pack_bf2(c[ja][0] - h00, c[ja][1] - h01);
            h10 = __bfloat162float(__float2bfloat16(c[ja][2]));
            h11 = __bfloat162float(__float2bfloat16(c[ja][3]));
            pH[kt][1] = pack_bf2(c[ja][2], c[ja][3]);
            pL[kt][1] = pack_bf2(c[ja][2] - h10, c[ja][3] - h11);
            h00 = __bfloat162float(__float2bfloat16(c[jb][0]));
            h01 = __bfloat162float(__float2bfloat16(c[jb][1]));
            pH[kt][2] = pack_bf2(c[jb][0], c[jb][1]);
            pL[kt][2] = pack_bf2(c[jb][0] - h00, c[jb][1] - h01);
            h10 = __bfloat162float(__float2bfloat16(c[jb][2]));
            h11 = __bfloat162float(__float2bfloat16(c[jb][3]));
            pH[kt][3] = pack_bf2(c[jb][2], c[jb][3]);
            pL[kt][3] = pack_bf2(c[jb][2] - h10, c[jb][3] - h11);
        }

        #pragma unroll
        for (int kt = 0; kt < 4; ++kt) {
            #pragma unroll
            for (int np = 0; np < 4; ++np) {
                uint32_t b[4];
                ldsm_x4_t(b, vBaseH + (kt * 16 * FPAD + np * 16) * 2);
                mma_bf16(cO[2 * np],     pH[kt], b);
                mma_bf16(cO[2 * np + 1], pH[kt], b + 2);
                mma_bf16(cO[2 * np],     pL[kt], b);
                mma_bf16(cO[2 * np + 1], pL[kt], b + 2);
            }
        }
        #pragma unroll
        for (int kt = 0; kt < 4; ++kt) {
            #pragma unroll
            for (int np = 0; np < 4; ++np) {
                uint32_t b[4];
                ldsm_x4_t(b, vBaseL + (kt * 16 * FPAD + np * 16) * 2);
                mma_bf16(cO[2 * np],     pH[kt], b);
                mma_bf16(cO[2 * np + 1], pH[kt], b + 2);
            }
        }
    }

    const int b_ = bh >> 4, h = bh & 15;
    const float i0 = 1.0f / l0, i1 = 1.0f / l1;
    const int mrow0 = qt * 64 + wid * 16 + r_;
    #pragma unroll
    for (int n8 = 0; n8 < 8; ++n8) {
        const int e = n8 * 8 + qc * 2;
        #pragma unroll
        for (int half = 0; half < 2; ++half) {
            const float inv = half ? i1 : i0;
            const float vx = cO[n8][half * 2 + 0] * inv;
            const float vy = cO[n8][half * 2 + 1] * inv;
            const int m = mrow0 + half * 8;
            __nv_bfloat16 hx = __float2bfloat16(vx);
            __nv_bfloat16 hy = __float2bfloat16(vy);
            __nv_bfloat162 hp = __halves2bfloat162(hx, hy);
            __nv_bfloat162 lp = __halves2bfloat162(
                __float2bfloat16(vx - __bfloat162float(hx)),
                __float2bfloat16(vy - __bfloat162float(hy)));
            size_t idx = ((size_t)b_ * NS + m) * NDIM + h * 64 + e;
            *(uint32_t*)&g_oh[idx] = *(uint32_t*)&hp;
            *(uint32_t*)&g_ol[idx] = *(uint32_t*)&lp;
        }
    }
}

// ---------------------------------------------------------------------------
extern "C" void kernel_launch(void* const* d_in, const int* in_sizes, int n_in,
                              void* d_out, int out_size)
{
    const float* x  = (const float*)d_in[0];
    const float* Wq = (const float*)d_in[1];
    const float* bq = (const float*)d_in[2];
    const float* Wk = (const float*)d_in[3];
    const float* bk = (const float*)d_in[4];
    const float* Wv = (const float*)d_in[5];
    const float* bv = (const float*)d_in[6];
    const float* Wo = (const float*)d_in[7];
    const float* bo = (const float*)d_in[8];
    float* out = (float*)d_out;

    cudaFuncSetAttribute(flash_mma_kernel,
                         cudaFuncAttributeMaxDynamicSharedMemorySize, FSMEM);
    cudaFuncSetAttribute(gemm_mma_kernel,
                         cudaFuncAttributeMaxDynamicSharedMemorySize, GSMEM);

    __nv_bfloat162 *xh2, *xl2;
    cudaGetSymbolAddress((void**)&xh2, g_xh);
    cudaGetSymbolAddress((void**)&xl2, g_xl);

    const int n4 = NM * NDIM / 4;
    split_kernel<<<n4 / 256, 256>>>((const float4*)x, xh2, xl2, n4);
    qkv_w_transpose<<<dim3(32, 2, 48), dim3(32, 32)>>>(Wq, Wk, Wv, bq, bk, bv);
    wo_transpose<<<dim3(32, 32), dim3(32, 32)>>>(Wo);

    gemm_mma_kernel<<<dim3(NM / 128, NQKV / 128), 256, GSMEM>>>(nullptr, nullptr, 0);
    flash_mma_kernel<<<dim3(NS / 64, NB * NH), 128, FSMEM>>>();
    gemm_mma_kernel<<<dim3(NM / 128, NDIM / 128), 256, GSMEM>>>(bo, out, 1);
}

// round 9
// speedup vs baseline: 3.0483x; 1.1218x over previous
#include <cuda_runtime.h>
#include <cuda_bf16.h>
#include <cstdint>

#define NB   2
#define NS   2048
#define NDIM 1024
#define NH   16
#define NHD  64
#define NM   (NB * NS)     // 4096
#define NQKV 3072          // 3 * NH * NHD

// ---------------------------------------------------------------------------
// Scratch (__device__ globals; allocation-free rule)
// ---------------------------------------------------------------------------
__device__ __nv_bfloat16 g_qh[NB * NH * NS * NHD];
__device__ __nv_bfloat16 g_ql[NB * NH * NS * NHD];
__device__ __nv_bfloat16 g_kh[NB * NH * NS * NHD];
__device__ __nv_bfloat16 g_kl[NB * NH * NS * NHD];
__device__ __nv_bfloat16 g_vh[NB * NH * NS * NHD];
__device__ __nv_bfloat16 g_vl[NB * NH * NS * NHD];

__device__ __nv_bfloat16 g_xh[(size_t)NM * NDIM];
__device__ __nv_bfloat16 g_xl[(size_t)NM * NDIM];
__device__ __nv_bfloat16 g_oh[(size_t)NM * NDIM];
__device__ __nv_bfloat16 g_ol[(size_t)NM * NDIM];
__device__ __nv_bfloat16 g_wqh[(size_t)NQKV * NDIM];   // QKV weights, K-major [3072][1024]
__device__ __nv_bfloat16 g_wql[(size_t)NQKV * NDIM];
__device__ __nv_bfloat16 g_woh[(size_t)NDIM * NDIM];   // Wo transposed, K-major [1024][1024]
__device__ __nv_bfloat16 g_wol[(size_t)NDIM * NDIM];
__device__ float g_bqkv[NQKV];

__device__ __forceinline__ uint32_t smem_to_u32(const void* p) {
    uint32_t a;
    asm("{ .reg .u64 t; cvta.to.shared.u64 t, %1; cvt.u32.u64 %0, t; }"
        : "=r"(a) : "l"(p));
    return a;
}

__device__ __forceinline__ void ldsm_x4(uint32_t* r, uint32_t addr) {
    asm volatile("ldmatrix.sync.aligned.m8n8.x4.shared.b16 {%0,%1,%2,%3}, [%4];"
        : "=r"(r[0]), "=r"(r[1]), "=r"(r[2]), "=r"(r[3]) : "r"(addr));
}
__device__ __forceinline__ void ldsm_x4_t(uint32_t* r, uint32_t addr) {
    asm volatile("ldmatrix.sync.aligned.m8n8.x4.trans.shared.b16 {%0,%1,%2,%3}, [%4];"
        : "=r"(r[0]), "=r"(r[1]), "=r"(r[2]), "=r"(r[3]) : "r"(addr));
}
__device__ __forceinline__ void ldsm_x2(uint32_t* r, uint32_t addr) {
    asm volatile("ldmatrix.sync.aligned.m8n8.x2.shared.b16 {%0,%1}, [%2];"
        : "=r"(r[0]), "=r"(r[1]) : "r"(addr));
}
__device__ __forceinline__ void mma_bf16(float* c, const uint32_t* a, const uint32_t* b) {
    asm volatile(
        "mma.sync.aligned.m16n8k16.row.col.f32.bf16.bf16.f32 "
        "{%0,%1,%2,%3}, {%4,%5,%6,%7}, {%8,%9}, {%0,%1,%2,%3};"
        : "+f"(c[0]), "+f"(c[1]), "+f"(c[2]), "+f"(c[3])
        : "r"(a[0]), "r"(a[1]), "r"(a[2]), "r"(a[3]), "r"(b[0]), "r"(b[1]));
}
__device__ __forceinline__ void cpasync16(uint32_t s, const void* g) {
    asm volatile("cp.async.cg.shared.global [%0], [%1], 16;" :: "r"(s), "l"(g));
}
#define CP_COMMIT() asm volatile("cp.async.commit_group;" ::: "memory")
#define CP_WAIT(n)  asm volatile("cp.async.wait_group %0;" :: "n"(n) : "memory")

__device__ __forceinline__ uint32_t pack_bf2(float x, float y) {
    __nv_bfloat162 h = __halves2bfloat162(__float2bfloat16(x), __float2bfloat16(y));
    return *(uint32_t*)&h;
}

// ---------------------------------------------------------------------------
// Conversion kernels
// ---------------------------------------------------------------------------
__global__ void split_kernel(const float4* __restrict__ src,
                             __nv_bfloat162* __restrict__ dh,
                             __nv_bfloat162* __restrict__ dl, int n4)
{
    int i = blockIdx.x * blockDim.x + threadIdx.x;
    if (i >= n4) return;
    float4 v = src[i];
    __nv_bfloat16 hx = __float2bfloat16(v.x), hy = __float2bfloat16(v.y);
    __nv_bfloat16 hz = __float2bfloat16(v.z), hw = __float2bfloat16(v.w);
    __nv_bfloat16 lx = __float2bfloat16(v.x - __bfloat162float(hx));
    __nv_bfloat16 ly = __float2bfloat16(v.y - __bfloat162float(hy));
    __nv_bfloat16 lz = __float2bfloat16(v.z - __bfloat162float(hz));
    __nv_bfloat16 lw = __float2bfloat16(v.w - __bfloat162float(hw));
    dh[2 * i]     = __halves2bfloat162(hx, hy);
    dh[2 * i + 1] = __halves2bfloat162(hz, hw);
    dl[2 * i]     = __halves2bfloat162(lx, ly);
    dl[2 * i + 1] = __halves2bfloat162(lz, lw);
}

// W{q,k,v}[h][d][e] -> g_wq{h,l}[(mat*16+h)*64+e][d]  (K-major, split), + bias concat
__global__ void qkv_w_transpose(const float* __restrict__ Wq, const float* __restrict__ Wk,
                                const float* __restrict__ Wv, const float* __restrict__ bq,
                                const float* __restrict__ bk, const float* __restrict__ bv)
{
    __shared__ float sm[32][33];
    int z = blockIdx.z, mat = z >> 4, h = z & 15;
    const float* W = (mat == 0 ? Wq : mat == 1 ? Wk : Wv) + (size_t)h * NDIM * NHD;
    const float* bias = (mat == 0 ? bq : mat == 1 ? bk : bv) + h * NHD;
    int d0 = blockIdx.x * 32, e0 = blockIdx.y * 32;
    int tx = threadIdx.x, ty = threadIdx.y;
    sm[ty][tx] = W[(size_t)(d0 + ty) * NHD + e0 + tx];
    __syncthreads();
    float v = sm[tx][ty];
    __nv_bfloat16 hv = __float2bfloat16(v);
    __nv_bfloat16 lv = __float2bfloat16(v - __bfloat162float(hv));
    size_t row = (size_t)z * 64 + e0 + ty;
    g_wqh[row * NDIM + d0 + tx] = hv;
    g_wql[row * NDIM + d0 + tx] = lv;
    if (blockIdx.x == 0 && tx == 0) g_bqkv[z * 64 + e0 + ty] = bias[e0 + ty];
}

// Wo[k][n] -> g_wo{h,l}[n][k]
__global__ void wo_transpose(const float* __restrict__ Wo)
{
    __shared__ float sm[32][33];
    int k0 = blockIdx.x * 32, n0 = blockIdx.y * 32;
    int tx = threadIdx.x, ty = threadIdx.y;
    sm[ty][tx] = Wo[(size_t)(k0 + ty) * NDIM + n0 + tx];
    __syncthreads();
    float v = sm[tx][ty];
    __nv_bfloat16 hv = __float2bfloat16(v);
    __nv_bfloat16 lv = __float2bfloat16(v - __bfloat162float(hv));
    g_woh[(size_t)(n0 + ty) * NDIM + k0 + tx] = hv;
    g_wol[(size_t)(n0 + ty) * NDIM + k0 + tx] = lv;
}

// ---------------------------------------------------------------------------
// HMMA split GEMM: 3-stage cp.async ring, ONE barrier per k-iteration,
// XOR-swizzled 64B-row smem layout (no padding; 16B-aligned cp.async).
//   tile = 128 rows x 32 bf16 (64B/row, 4x16B chunks)
//   physical_chunk = chunk ^ ((row>>1)&3)   — conflict-free ldsm + stores
// Invariant: at top of iter t, pending cp.async groups = {t, t+1};
// CP_WAIT(1) certifies stage t; the barrier certifies all warps left iter
// t-1, so issuing stage t+2 into buf[(t+2)%3] == buf[(t-1)%3] is race-free.
// ---------------------------------------------------------------------------
#define KT     32
#define TILE_B (128 * 64)   // 8192 bytes per tile
#define BUF_B  (4 * TILE_B) // 32768 bytes per stage
#define GSMEM  (3 * BUF_B)  // 98304 bytes

__global__ __launch_bounds__(256, 2) void gemm_mma_kernel(const float* __restrict__ bias,
                                                          float* __restrict__ out, int mode)
{
    extern __shared__ __align__(16) char smg[];
    const uint32_t smb = smem_to_u32(smg);

    const int tid = threadIdx.x, wid = tid >> 5, lane = tid & 31;
    const int m0 = blockIdx.x * 128, n0 = blockIdx.y * 128;
    const int warp_m0 = (wid >> 2) * 64;
    const int warp_n0 = (wid & 3) * 32;

    const __nv_bfloat16 *Ah, *Al, *Bh, *Bl;
    if (mode == 0) { Ah = g_xh; Al = g_xl; Bh = g_wqh; Bl = g_wql; }
    else           { Ah = g_oh; Al = g_ol; Bh = g_woh; Bl = g_wol; }

    // ---- cp.async store mapping (swizzled) ----
    const int rowA  = tid >> 2;                    // 0..63 (and +64)
    const int chunk = tid & 3;                     // 16B chunk within row
    const int col8  = chunk * 8;                   // gmem element offset
    const uint32_t st0 = rowA * 64 + ((chunk ^ ((rowA >> 1) & 3)) * 16);
    const uint32_t st1 = st0 + 64 * 64;            // row+64: same swizzle bits

    const __nv_bfloat16* gA0h = Ah + (size_t)(m0 + rowA) * NDIM + col8;
    const __nv_bfloat16* gA1h = Ah + (size_t)(m0 + rowA + 64) * NDIM + col8;
    const __nv_bfloat16* gA0l = Al + (size_t)(m0 + rowA) * NDIM + col8;
    const __nv_bfloat16* gA1l = Al + (size_t)(m0 + rowA + 64) * NDIM + col8;
    const __nv_bfloat16* gB0h = Bh + (size_t)(n0 + rowA) * NDIM + col8;
    const __nv_bfloat16* gB1h = Bh + (size_t)(n0 + rowA + 64) * NDIM + col8;
    const __nv_bfloat16* gB0l = Bl + (size_t)(n0 + rowA) * NDIM + col8;
    const __nv_bfloat16* gB1l = Bl + (size_t)(n0 + rowA + 64) * NDIM + col8;

    // ---- ldmatrix address mapping (swizzled; swizzle bits lane-invariant
    //      under mt*16 / nt*8 row steps since (row>>1) shifts by multiples of 4) ----
    const int lm = lane & 15, lq = lane >> 4;
    const int l8 = lane & 7,  lb = (lane >> 3) & 1;
    const int swA = ((warp_m0 + lm) >> 1) & 3;
    const int swB = ((warp_n0 + l8) >> 1) & 3;
    const uint32_t aRow = (warp_m0 + lm) * 64;     // byte offset of lane's A row
    const uint32_t bRow = (warp_n0 + l8) * 64;
    uint32_t chA[2], chB[2];
    #pragma unroll
    for (int kk = 0; kk < 2; ++kk) {
        chA[kk] = (uint32_t)(((lq + 2 * kk) ^ swA) * 16);
        chB[kk] = (uint32_t)(((lb + 2 * kk) ^ swB) * 16);
    }

    float acc[4][4][4];
    #pragma unroll
    for (int i = 0; i < 4; i++)
        #pragma unroll
        for (int j = 0; j < 4; j++)
            #pragma unroll
            for (int q = 0; q < 4; q++) acc[i][j][q] = 0.0f;

    const int NT = NDIM / KT;   // 32

    // prologue: stages 0 and 1
    #pragma unroll
    for (int p = 0; p < 2; ++p) {
        const uint32_t b = smb + p * BUF_B;
        const int k1 = p * KT;
        cpasync16(b + st0, gA0h + k1);               cpasync16(b + st1, gA1h + k1);
        cpasync16(b + TILE_B + st0, gA0l + k1);      cpasync16(b + TILE_B + st1, gA1l + k1);
        cpasync16(b + 2 * TILE_B + st0, gB0h + k1);  cpasync16(b + 2 * TILE_B + st1, gB1h + k1);
        cpasync16(b + 3 * TILE_B + st0, gB0l + k1);  cpasync16(b + 3 * TILE_B + st1, gB1l + k1);
        CP_COMMIT();
    }

    int bufIdx = 0, nextIdx = 2;
    for (int t = 0; t < NT; ++t) {
        CP_WAIT(1);          // stage t landed (pending was {t, t+1})
        __syncthreads();     // all warps done with iter t-1 (frees buf[(t+2)%3])

        if (t + 2 < NT) {
            const uint32_t b = smb + nextIdx * BUF_B;
            const int k1 = (t + 2) * KT;
            cpasync16(b + st0, gA0h + k1);               cpasync16(b + st1, gA1h + k1);
            cpasync16(b + TILE_B + st0, gA0l + k1);      cpasync16(b + TILE_B + st1, gA1l + k1);
            cpasync16(b + 2 * TILE_B + st0, gB0h + k1);  cpasync16(b + 2 * TILE_B + st1, gB1h + k1);
            cpasync16(b + 3 * TILE_B + st0, gB0l + k1);  cpasync16(b + 3 * TILE_B + st1, gB1l + k1);
        }
        CP_COMMIT();         // unconditional: keeps pending-group invariant exact

        const uint32_t buf = smb + bufIdx * BUF_B;
        const uint32_t aHr = buf + aRow;                       // Ah tile
        const uint32_t aLr = aHr + TILE_B;                     // Al tile
        const uint32_t bHr = buf + 2 * TILE_B + bRow;          // Bh tile
        const uint32_t bLr = bHr + TILE_B;                     // Bl tile

        #pragma unroll
        for (int kk = 0; kk < 2; ++kk) {
            uint32_t bh2[4][2], bl2[4][2];
            #pragma unroll
            for (int nt = 0; nt < 4; ++nt) {
                ldsm_x2(bh2[nt], bHr + nt * 512 + chB[kk]);
                ldsm_x2(bl2[nt], bLr + nt * 512 + chB[kk]);
            }
            uint32_t a[4][4];
            #pragma unroll
            for (int mt = 0; mt < 4; ++mt)
                ldsm_x4(a[mt], aHr + mt * 1024 + chA[kk]);
            #pragma unroll
            for (int nt = 0; nt < 4; ++nt)
                #pragma unroll
                for (int mt = 0; mt < 4; ++mt) {
                    mma_bf16(acc[mt][nt], a[mt], bh2[nt]);
                    mma_bf16(acc[mt][nt], a[mt], bl2[nt]);
                }
            #pragma unroll
            for (int mt = 0; mt < 4; ++mt)
                ldsm_x4(a[mt], aLr + mt * 1024 + chA[kk]);
            #pragma unroll
            for (int nt = 0; nt < 4; ++nt)
                #pragma unroll
                for (int mt = 0; mt < 4; ++mt)
                    mma_bf16(acc[mt][nt], a[mt], bh2[nt]);
        }

        bufIdx = (bufIdx == 2) ? 0 : bufIdx + 1;
        nextIdx = (nextIdx == 2) ? 0 : nextIdx + 1;
    }

    // ---- epilogue ----
    const int mrow = lane >> 2;
    const int ncol = (lane & 3) * 2;
    #pragma unroll
    for (int nt = 0; nt < 4; ++nt) {
        const int gn = n0 + warp_n0 + nt * 8 + ncol;
        float2 bb;
        if (mode == 0) bb = *(const float2*)&g_bqkv[gn];
        else           bb = *(const float2*)&bias[gn];
        #pragma unroll
        for (int mt = 0; mt < 4; ++mt) {
            #pragma unroll
            for (int half = 0; half < 2; ++half) {
                const int m = m0 + warp_m0 + mt * 16 + mrow + half * 8;
                float vx = acc[mt][nt][half * 2 + 0] + bb.x;
                float vy = acc[mt][nt][half * 2 + 1] + bb.y;
                if (mode == 0) {
                    const int slot = gn >> 6;
                    const int mat = slot >> 4, h = slot & 15, e = gn & 63;
                    const int b_ = m >> 11, s_ = m & (NS - 1);
                    if (mat == 0) { vx *= 0.125f; vy *= 0.125f; }
                    __nv_bfloat16* dh_ = (mat == 0 ? g_qh : mat == 1 ? g_kh : g_vh);
                    __nv_bfloat16* dl_ = (mat == 0 ? g_ql : mat == 1 ? g_kl : g_vl);
                    __nv_bfloat16 hx = __float2bfloat16(vx);
                    __nv_bfloat16 hy = __float2bfloat16(vy);
                    float lxf = vx - __bfloat162float(hx);
                    float lyf = vy - __bfloat162float(hy);
                    size_t idx = (((size_t)(b_ * NH + h)) * NS + s_) * NHD + e;
                    __nv_bfloat162 hp = __halves2bfloat162(hx, hy);
                    __nv_bfloat162 lp = __halves2bfloat162(__float2bfloat16(lxf),
                                                           __float2bfloat16(lyf));
                    *(uint32_t*)&dh_[idx] = *(uint32_t*)&hp;
                    *(uint32_t*)&dl_[idx] = *(uint32_t*)&lp;
                } else {
                    float2 v = make_float2(vx, vy);
                    *(float2*)&out[(size_t)m * NDIM + gn] = v;
                }
            }
        }
    }
}

// ---------------------------------------------------------------------------
// Flash attention, split-bf16 HMMA + cp.async double-buffered K/V stages.
// (unchanged from R7 — passing at ~its tensor roofline)
// ---------------------------------------------------------------------------
#define FPAD 72
#define FT   (64 * FPAD)
#define FTB  (FT * 2)                 // 9216 bytes per tile
#define FSTAGE (4 * FTB)              // 36864 bytes per KV stage
#define FSMEM  (2 * FTB + 2 * FSTAGE) // 92160 bytes

__global__ __launch_bounds__(128) void flash_mma_kernel()
{
    extern __shared__ __align__(16) char smfc[];
    const uint32_t smb = smem_to_u32(smfc);
    const uint32_t qBase0 = smb;
    const uint32_t kvBase = smb + 2 * FTB;

    const int tid = threadIdx.x, wid = tid >> 5, lane = tid & 31;
    const int qt = (int)gridDim.x - 1 - (int)blockIdx.x;
    const int bh = blockIdx.y;
    const size_t base = (size_t)bh * NS * NHD;

    int cr[4], cc[4];
    uint32_t cs[4];
    #pragma unroll
    for (int it = 0; it < 4; it++) {
        int ch = tid + it * 128;
        cr[it] = ch >> 3;
        cc[it] = (ch & 7) * 8;
        cs[it] = (cr[it] * FPAD + cc[it]) * 2;
    }

    {
        const __nv_bfloat16* qh = g_qh + base + (size_t)qt * 64 * NHD;
        const __nv_bfloat16* ql = g_ql + base + (size_t)qt * 64 * NHD;
        #pragma unroll
        for (int it = 0; it < 4; it++) {
            cpasync16(qBase0 + cs[it],       qh + cr[it] * 64 + cc[it]);
            cpasync16(qBase0 + FTB + cs[it], ql + cr[it] * 64 + cc[it]);
        }
        const __nv_bfloat16* src[4] = {g_kh + base, g_kl + base, g_vh + base, g_vl + base};
        #pragma unroll
        for (int a = 0; a < 4; a++)
            #pragma unroll
            for (int it = 0; it < 4; it++)
                cpasync16(kvBase + a * FTB + cs[it], src[a] + cr[it] * 64 + cc[it]);
        CP_COMMIT();
    }

    const int lm = lane & 15, lq = lane >> 4;
    const int l8 = lane & 7;
    const int sel1 = (lane >> 3) & 1;
    const int sel2 = lane >> 4;
    const int r_  = lane >> 2;
    const int qc  = lane & 3;

    const uint32_t aBaseH = qBase0 + ((wid * 16 + lm) * FPAD + lq * 8) * 2;
    const uint32_t aBaseL = aBaseH + FTB;
    const uint32_t kOff = ((sel2 * 8 + l8) * FPAD + sel1 * 8) * 2;
    const uint32_t vOff = ((sel1 * 8 + l8) * FPAD + sel2 * 8) * 2;

    float cO[8][4];
    #pragma unroll
    for (int i = 0; i < 8; i++)
        #pragma unroll
        for (int j = 0; j < 4; j++) cO[i][j] = 0.0f;
    float m0r = -1e30f, m1r = -1e30f, l0 = 0.0f, l1 = 0.0f;

    for (int j = 0; j <= qt; ++j) {
        CP_WAIT(0);
        __syncthreads();

        if (j < qt) {
            const uint32_t sb = kvBase + ((j + 1) & 1) * FSTAGE;
            const size_t off = base + (size_t)(j + 1) * 64 * NHD;
            const __nv_bfloat16* src[4] = {g_kh + off, g_kl + off, g_vh + off, g_vl + off};
            #pragma unroll
            for (int a = 0; a < 4; a++)
                #pragma unroll
                for (int it = 0; it < 4; it++)
                    cpasync16(sb + a * FTB + cs[it], src[a] + cr[it] * 64 + cc[it]);
            CP_COMMIT();
        }

        const uint32_t stage = kvBase + (j & 1) * FSTAGE;
        const uint32_t kBaseH = stage + kOff;
        const uint32_t kBaseL = stage + FTB + kOff;
        const uint32_t vBaseH = stage + 2 * FTB + vOff;
        const uint32_t vBaseL = stage + 3 * FTB + vOff;

        float c[8][4];
        #pragma unroll
        for (int i = 0; i < 8; i++)
            #pragma unroll
            for (int q = 0; q < 4; q++) c[i][q] = 0.0f;

        #pragma unroll
        for (int kt = 0; kt < 4; ++kt) {
            uint32_t aH[4], aL[4];
            ldsm_x4(aH, aBaseH + kt * 16 * 2);
            ldsm_x4(aL, aBaseL + kt * 16 * 2);
            #pragma unroll
            for (int np = 0; np < 4; ++np) {
                uint32_t b[4];
                ldsm_x4(b, kBaseH + (np * 16 * FPAD + kt * 16) * 2);
                mma_bf16(c[2 * np],     aH, b);
                mma_bf16(c[2 * np + 1], aH, b + 2);
                mma_bf16(c[2 * np],     aL, b);
                mma_bf16(c[2 * np + 1], aL, b + 2);
            }
            #pragma unroll
            for (int np = 0; np < 4; ++np) {
                uint32_t b[4];
                ldsm_x4(b, kBaseL + (np * 16 * FPAD + kt * 16) * 2);
                mma_bf16(c[2 * np],     aH, b);
                mma_bf16(c[2 * np + 1], aH, b + 2);
            }
        }

        if (j == qt) {
            const int row0 = wid * 16 + r_;
            #pragma unroll
            for (int n8 = 0; n8 < 8; ++n8) {
                const int col = n8 * 8 + qc * 2;
                if (col     > row0)     c[n8][0] = -1e30f;
                if (col + 1 > row0)     c[n8][1] = -1e30f;
                if (col     > row0 + 8) c[n8][2] = -1e30f;
                if (col + 1 > row0 + 8) c[n8][3] = -1e30f;
            }
        }

        float mt0 = -1e30f, mt1 = -1e30f;
        #pragma unroll
        for (int n8 = 0; n8 < 8; ++n8) {
            mt0 = fmaxf(mt0, fmaxf(c[n8][0], c[n8][1]));
            mt1 = fmaxf(mt1, fmaxf(c[n8][2], c[n8][3]));
        }
        mt0 = fmaxf(mt0, __shfl_xor_sync(0xffffffffu, mt0, 1));
        mt0 = fmaxf(mt0, __shfl_xor_sync(0xffffffffu, mt0, 2));
        mt1 = fmaxf(mt1, __shfl_xor_sync(0xffffffffu, mt1, 1));
        mt1 = fmaxf(mt1, __shfl_xor_sync(0xffffffffu, mt1, 2));
        const float mn0 = fmaxf(m0r, mt0);
        const float mn1 = fmaxf(m1r, mt1);
        const float al0 = __expf(m0r - mn0);
        const float al1 = __expf(m1r - mn1);
        float s0 = 0.0f, s1 = 0.0f;
        #pragma unroll
        for (int n8 = 0; n8 < 8; ++n8) {
            c[n8][0] = __expf(c[n8][0] - mn0); s0 += c[n8][0];
            c[n8][1] = __expf(c[n8][1] - mn0); s0 += c[n8][1];
            c[n8][2] = __expf(c[n8][2] - mn1); s1 += c[n8][2];
            c[n8][3] = __expf(c[n8][3] - mn1); s1 += c[n8][3];
        }
        s0 += __shfl_xor_sync(0xffffffffu, s0, 1);
        s0 += __shfl_xor_sync(0xffffffffu, s0, 2);
        s1 += __shfl_xor_sync(0xffffffffu, s1, 1);
        s1 += __shfl_xor_sync(0xffffffffu, s1, 2);
        l0 = l0 * al0 + s0;  m0r = mn0;
        l1 = l1 * al1 + s1;  m1r = mn1;
        #pragma unroll
        for (int n8 = 0; n8 < 8; ++n8) {
            cO[n8][0] *= al0; cO[n8][1] *= al0;
            cO[n8][2] *= al1; cO[n8][3] *= al1;
        }

        uint32_t pH[4][4], pL[4][4];
        #pragma unroll
        for (int kt = 0; kt < 4; ++kt) {
            const int ja = 2 * kt, jb = 2 * kt + 1;
            float h00, h01, h10, h11;
            h00 = __bfloat162float(__float2bfloat16(c[ja][0]));
            h01 = __bfloat162float(__float2bfloat16(c[ja][1]));
            pH[kt][0] = pack_bf2(c[ja][0], c[ja][1]);
            pL[kt][0] = pack_bf2(c[ja][0] - h00, c[ja][1] - h01);
            h10 = __bfloat162float(__float2bfloat16(c[ja][2]));
            h11 = __bfloat162float(__float2bfloat16(c[ja][3]));
            pH[kt][1] = pack_bf2(c[ja][2], c[ja][3]);
            pL[kt][1] = pack_bf2(c[ja][2] - h10, c[ja][3] - h11);
            h00 = __bfloat162float(__float2bfloat16(c[jb][0]));
            h01 = __bfloat162float(__float2bfloat16(c[jb][1]));
            pH[kt][2] = pack_bf2(c[jb][0], c[jb][1]);
            pL[kt][2] = pack_bf2(c[jb][0] - h00, c[jb][1] - h01);
            h10 = __bfloat162float(__float2bfloat16(c[jb][2]));
            h11 = __bfloat162float(__float2bfloat16(c[jb][3]));
            pH[kt][3] = pack_bf2(c[jb][2], c[jb][3]);
            pL[kt][3] = pack_bf2(c[jb][2] - h10, c[jb][3] - h11);
        }

        #pragma unroll
        for (int kt = 0; kt < 4; ++kt) {
            #pragma unroll
            for (int np = 0; np < 4; ++np) {
                uint32_t b[4];
                ldsm_x4_t(b, vBaseH + (kt * 16 * FPAD + np * 16) * 2);
                mma_bf16(cO[2 * np],     pH[kt], b);
                mma_bf16(cO[2 * np + 1], pH[kt], b + 2);
                mma_bf16(cO[2 * np],     pL[kt], b);
                mma_bf16(cO[2 * np + 1], pL[kt], b + 2);
            }
        }
        #pragma unroll
        for (int kt = 0; kt < 4; ++kt) {
            #pragma unroll
            for (int np = 0; np < 4; ++np) {
                uint32_t b[4];
                ldsm_x4_t(b, vBaseL + (kt * 16 * FPAD + np * 16) * 2);
                mma_bf16(cO[2 * np],     pH[kt], b);
                mma_bf16(cO[2 * np + 1], pH[kt], b + 2);
            }
        }
    }

    const int b_ = bh >> 4, h = bh & 15;
    const float i0 = 1.0f / l0, i1 = 1.0f / l1;
    const int mrow0 = qt * 64 + wid * 16 + r_;
    #pragma unroll
    for (int n8 = 0; n8 < 8; ++n8) {
        const int e = n8 * 8 + qc * 2;
        #pragma unroll
        for (int half = 0; half < 2; ++half) {
            const float inv = half ? i1 : i0;
            const float vx = cO[n8][half * 2 + 0] * inv;
            const float vy = cO[n8][half * 2 + 1] * inv;
            const int m = mrow0 + half * 8;
            __nv_bfloat16 hx = __float2bfloat16(vx);
            __nv_bfloat16 hy = __float2bfloat16(vy);
            __nv_bfloat162 hp = __halves2bfloat162(hx, hy);
            __nv_bfloat162 lp = __halves2bfloat162(
                __float2bfloat16(vx - __bfloat162float(hx)),
                __float2bfloat16(vy - __bfloat162float(hy)));
            size_t idx = ((size_t)b_ * NS + m) * NDIM + h * 64 + e;
            *(uint32_t*)&g_oh[idx] = *(uint32_t*)&hp;
            *(uint32_t*)&g_ol[idx] = *(uint32_t*)&lp;
        }
    }
}

// ---------------------------------------------------------------------------
extern "C" void kernel_launch(void* const* d_in, const int* in_sizes, int n_in,
                              void* d_out, int out_size)
{
    const float* x  = (const float*)d_in[0];
    const float* Wq = (const float*)d_in[1];
    const float* bq = (const float*)d_in[2];
    const float* Wk = (const float*)d_in[3];
    const float* bk = (const float*)d_in[4];
    const float* Wv = (const float*)d_in[5];
    const float* bv = (const float*)d_in[6];
    const float* Wo = (const float*)d_in[7];
    const float* bo = (const float*)d_in[8];
    float* out = (float*)d_out;

    cudaFuncSetAttribute(flash_mma_kernel,
                         cudaFuncAttributeMaxDynamicSharedMemorySize, FSMEM);
    cudaFuncSetAttribute(gemm_mma_kernel,
                         cudaFuncAttributeMaxDynamicSharedMemorySize, GSMEM);

    __nv_bfloat162 *xh2, *xl2;
    cudaGetSymbolAddress((void**)&xh2, g_xh);
    cudaGetSymbolAddress((void**)&xl2, g_xl);

    const int n4 = NM * NDIM / 4;
    split_kernel<<<n4 / 256, 256>>>((const float4*)x, xh2, xl2, n4);
    qkv_w_transpose<<<dim3(32, 2, 48), dim3(32, 32)>>>(Wq, Wk, Wv, bq, bk, bv);
    wo_transpose<<<dim3(32, 32), dim3(32, 32)>>>(Wo);

    gemm_mma_kernel<<<dim3(NM / 128, NQKV / 128), 256, GSMEM>>>(nullptr, nullptr, 0);
    flash_mma_kernel<<<dim3(NS / 64, NB * NH), 128, FSMEM>>>();
    gemm_mma_kernel<<<dim3(NM / 128, NDIM / 128), 256, GSMEM>>>(bo, out, 1);
}

// round 10
// speedup vs baseline: 3.1149x; 1.0218x over previous
#include <cuda_runtime.h>
#include <cuda_bf16.h>
#include <cstdint>

#define NB   2
#define NS   2048
#define NDIM 1024
#define NH   16
#define NHD  64
#define NM   (NB * NS)     // 4096
#define NQKV 3072          // 3 * NH * NHD

// ---------------------------------------------------------------------------
// Scratch (__device__ globals; allocation-free rule)
// ---------------------------------------------------------------------------
__device__ __nv_bfloat16 g_qh[NB * NH * NS * NHD];
__device__ __nv_bfloat16 g_ql[NB * NH * NS * NHD];
__device__ __nv_bfloat16 g_kh[NB * NH * NS * NHD];
__device__ __nv_bfloat16 g_kl[NB * NH * NS * NHD];
__device__ __nv_bfloat16 g_vh[NB * NH * NS * NHD];
__device__ __nv_bfloat16 g_vl[NB * NH * NS * NHD];

__device__ __nv_bfloat16 g_xh[(size_t)NM * NDIM];
__device__ __nv_bfloat16 g_xl[(size_t)NM * NDIM];
__device__ __nv_bfloat16 g_oh[(size_t)NM * NDIM];
__device__ __nv_bfloat16 g_ol[(size_t)NM * NDIM];
__device__ __nv_bfloat16 g_wqh[(size_t)NQKV * NDIM];   // QKV weights, K-major [3072][1024]
__device__ __nv_bfloat16 g_wql[(size_t)NQKV * NDIM];
__device__ __nv_bfloat16 g_woh[(size_t)NDIM * NDIM];   // Wo transposed, K-major [1024][1024]
__device__ __nv_bfloat16 g_wol[(size_t)NDIM * NDIM];
__device__ float g_bqkv[NQKV];

__device__ __forceinline__ uint32_t smem_to_u32(const void* p) {
    uint32_t a;
    asm("{ .reg .u64 t; cvta.to.shared.u64 t, %1; cvt.u32.u64 %0, t; }"
        : "=r"(a) : "l"(p));
    return a;
}

__device__ __forceinline__ void ldsm_x4(uint32_t* r, uint32_t addr) {
    asm volatile("ldmatrix.sync.aligned.m8n8.x4.shared.b16 {%0,%1,%2,%3}, [%4];"
        : "=r"(r[0]), "=r"(r[1]), "=r"(r[2]), "=r"(r[3]) : "r"(addr));
}
__device__ __forceinline__ void ldsm_x4_t(uint32_t* r, uint32_t addr) {
    asm volatile("ldmatrix.sync.aligned.m8n8.x4.trans.shared.b16 {%0,%1,%2,%3}, [%4];"
        : "=r"(r[0]), "=r"(r[1]), "=r"(r[2]), "=r"(r[3]) : "r"(addr));
}
__device__ __forceinline__ void mma_bf16(float* c, const uint32_t* a, const uint32_t* b) {
    asm volatile(
        "mma.sync.aligned.m16n8k16.row.col.f32.bf16.bf16.f32 "
        "{%0,%1,%2,%3}, {%4,%5,%6,%7}, {%8,%9}, {%0,%1,%2,%3};"
        : "+f"(c[0]), "+f"(c[1]), "+f"(c[2]), "+f"(c[3])
        : "r"(a[0]), "r"(a[1]), "r"(a[2]), "r"(a[3]), "r"(b[0]), "r"(b[1]));
}
__device__ __forceinline__ void cpasync16(uint32_t s, const void* g) {
    asm volatile("cp.async.cg.shared.global [%0], [%1], 16;" :: "r"(s), "l"(g));
}
#define CP_COMMIT() asm volatile("cp.async.commit_group;" ::: "memory")
#define CP_WAIT(n)  asm volatile("cp.async.wait_group %0;" :: "n"(n) : "memory")

__device__ __forceinline__ uint32_t pack_bf2(float x, float y) {
    __nv_bfloat162 h = __halves2bfloat162(__float2bfloat16(x), __float2bfloat16(y));
    return *(uint32_t*)&h;
}

// ---------------------------------------------------------------------------
// Conversion kernels
// ---------------------------------------------------------------------------
__global__ void split_kernel(const float4* __restrict__ src,
                             __nv_bfloat162* __restrict__ dh,
                             __nv_bfloat162* __restrict__ dl, int n4)
{
    int i = blockIdx.x * blockDim.x + threadIdx.x;
    if (i >= n4) return;
    float4 v = src[i];
    __nv_bfloat16 hx = __float2bfloat16(v.x), hy = __float2bfloat16(v.y);
    __nv_bfloat16 hz = __float2bfloat16(v.z), hw = __float2bfloat16(v.w);
    __nv_bfloat16 lx = __float2bfloat16(v.x - __bfloat162float(hx));
    __nv_bfloat16 ly = __float2bfloat16(v.y - __bfloat162float(hy));
    __nv_bfloat16 lz = __float2bfloat16(v.z - __bfloat162float(hz));
    __nv_bfloat16 lw = __float2bfloat16(v.w - __bfloat162float(hw));
    dh[2 * i]     = __halves2bfloat162(hx, hy);
    dh[2 * i + 1] = __halves2bfloat162(hz, hw);
    dl[2 * i]     = __halves2bfloat162(lx, ly);
    dl[2 * i + 1] = __halves2bfloat162(lz, lw);
}

// W{q,k,v}[h][d][e] -> g_wq{h,l}[(mat*16+h)*64+e][d]  (K-major, split), + bias concat
__global__ void qkv_w_transpose(const float* __restrict__ Wq, const float* __restrict__ Wk,
                                const float* __restrict__ Wv, const float* __restrict__ bq,
                                const float* __restrict__ bk, const float* __restrict__ bv)
{
    __shared__ float sm[32][33];
    int z = blockIdx.z, mat = z >> 4, h = z & 15;
    const float* W = (mat == 0 ? Wq : mat == 1 ? Wk : Wv) + (size_t)h * NDIM * NHD;
    const float* bias = (mat == 0 ? bq : mat == 1 ? bk : bv) + h * NHD;
    int d0 = blockIdx.x * 32, e0 = blockIdx.y * 32;
    int tx = threadIdx.x, ty = threadIdx.y;
    sm[ty][tx] = W[(size_t)(d0 + ty) * NHD + e0 + tx];
    __syncthreads();
    float v = sm[tx][ty];
    __nv_bfloat16 hv = __float2bfloat16(v);
    __nv_bfloat16 lv = __float2bfloat16(v - __bfloat162float(hv));
    size_t row = (size_t)z * 64 + e0 + ty;
    g_wqh[row * NDIM + d0 + tx] = hv;
    g_wql[row * NDIM + d0 + tx] = lv;
    if (blockIdx.x == 0 && tx == 0) g_bqkv[z * 64 + e0 + ty] = bias[e0 + ty];
}

// Wo[k][n] -> g_wo{h,l}[n][k]
__global__ void wo_transpose(const float* __restrict__ Wo)
{
    __shared__ float sm[32][33];
    int k0 = blockIdx.x * 32, n0 = blockIdx.y * 32;
    int tx = threadIdx.x, ty = threadIdx.y;
    sm[ty][tx] = Wo[(size_t)(k0 + ty) * NDIM + n0 + tx];
    __syncthreads();
    float v = sm[tx][ty];
    __nv_bfloat16 hv = __float2bfloat16(v);
    __nv_bfloat16 lv = __float2bfloat16(v - __bfloat162float(hv));
    g_woh[(size_t)(n0 + ty) * NDIM + k0 + tx] = hv;
    g_wol[(size_t)(n0 + ty) * NDIM + k0 + tx] = lv;
}

// ---------------------------------------------------------------------------
// HMMA split GEMM: 3-stage cp.async ring, ONE barrier per k-iteration,
// XOR-swizzled 64B-row smem. NEW in R10: accumulator-distance scheduling —
// three full 16-MMA sweeps per kk (Ah*Bh, Ah*Bl, Al*Bh), and B loaded as
// ldmatrix.x4 pairs (nt 0,1 / 2,3).
// ---------------------------------------------------------------------------
#define KT     32
#define TILE_B (128 * 64)   // 8192 bytes per tile
#define BUF_B  (4 * TILE_B) // 32768 bytes per stage
#define GSMEM  (3 * BUF_B)  // 98304 bytes

__global__ __launch_bounds__(256, 2) void gemm_mma_kernel(const float* __restrict__ bias,
                                                          float* __restrict__ out, int mode)
{
    extern __shared__ __align__(16) char smg[];
    const uint32_t smb = smem_to_u32(smg);

    const int tid = threadIdx.x, wid = tid >> 5, lane = tid & 31;
    const int m0 = blockIdx.x * 128, n0 = blockIdx.y * 128;
    const int warp_m0 = (wid >> 2) * 64;
    const int warp_n0 = (wid & 3) * 32;

    const __nv_bfloat16 *Ah, *Al, *Bh, *Bl;
    if (mode == 0) { Ah = g_xh; Al = g_xl; Bh = g_wqh; Bl = g_wql; }
    else           { Ah = g_oh; Al = g_ol; Bh = g_woh; Bl = g_wol; }

    // ---- cp.async store mapping (swizzled) ----
    const int rowA  = tid >> 2;
    const int chunk = tid & 3;
    const int col8  = chunk * 8;
    const uint32_t st0 = rowA * 64 + ((chunk ^ ((rowA >> 1) & 3)) * 16);
    const uint32_t st1 = st0 + 64 * 64;

    const __nv_bfloat16* gA0h = Ah + (size_t)(m0 + rowA) * NDIM + col8;
    const __nv_bfloat16* gA1h = Ah + (size_t)(m0 + rowA + 64) * NDIM + col8;
    const __nv_bfloat16* gA0l = Al + (size_t)(m0 + rowA) * NDIM + col8;
    const __nv_bfloat16* gA1l = Al + (size_t)(m0 + rowA + 64) * NDIM + col8;
    const __nv_bfloat16* gB0h = Bh + (size_t)(n0 + rowA) * NDIM + col8;
    const __nv_bfloat16* gB1h = Bh + (size_t)(n0 + rowA + 64) * NDIM + col8;
    const __nv_bfloat16* gB0l = Bl + (size_t)(n0 + rowA) * NDIM + col8;
    const __nv_bfloat16* gB1l = Bl + (size_t)(n0 + rowA + 64) * NDIM + col8;

    // ---- A ldmatrix mapping (x4, 16 rows) ----
    const int lm = lane & 15, lq = lane >> 4;
    const int swA = ((warp_m0 + lm) >> 1) & 3;
    const uint32_t aRow = (warp_m0 + lm) * 64;
    uint32_t chA[2];
    #pragma unroll
    for (int kk = 0; kk < 2; ++kk)
        chA[kk] = (uint32_t)(((lq + 2 * kk) ^ swA) * 16);

    // ---- B ldmatrix mapping (x4 over nt pairs):
    //      matrix = lane>>3: {nt_local = lane>>4, k_sel = (lane>>3)&1} ----
    const int bl8 = lane & 7;
    const int brow_local = (lane >> 4) * 8 + bl8;      // 0..15 within pair
    const int bksel = (lane >> 3) & 1;
    const int swB = ((warp_n0 + brow_local) >> 1) & 3; // invariant under +16 (pair step)
    uint32_t bRowP[2];
    #pragma unroll
    for (int p = 0; p < 2; ++p)
        bRowP[p] = (uint32_t)(warp_n0 + p * 16 + brow_local) * 64;
    uint32_t chB[2];
    #pragma unroll
    for (int kk = 0; kk < 2; ++kk)
        chB[kk] = (uint32_t)(((bksel + 2 * kk) ^ swB) * 16);

    float acc[4][4][4];
    #pragma unroll
    for (int i = 0; i < 4; i++)
        #pragma unroll
        for (int j = 0; j < 4; j++)
            #pragma unroll
            for (int q = 0; q < 4; q++) acc[i][j][q] = 0.0f;

    const int NT = NDIM / KT;   // 32

    // prologue: stages 0 and 1
    #pragma unroll
    for (int p = 0; p < 2; ++p) {
        const uint32_t b = smb + p * BUF_B;
        const int k1 = p * KT;
        cpasync16(b + st0, gA0h + k1);               cpasync16(b + st1, gA1h + k1);
        cpasync16(b + TILE_B + st0, gA0l + k1);      cpasync16(b + TILE_B + st1, gA1l + k1);
        cpasync16(b + 2 * TILE_B + st0, gB0h + k1);  cpasync16(b + 2 * TILE_B + st1, gB1h + k1);
        cpasync16(b + 3 * TILE_B + st0, gB0l + k1);  cpasync16(b + 3 * TILE_B + st1, gB1l + k1);
        CP_COMMIT();
    }

    int bufIdx = 0, nextIdx = 2;
    for (int t = 0; t < NT; ++t) {
        CP_WAIT(1);
        __syncthreads();

        if (t + 2 < NT) {
            const uint32_t b = smb + nextIdx * BUF_B;
            const int k1 = (t + 2) * KT;
            cpasync16(b + st0, gA0h + k1);               cpasync16(b + st1, gA1h + k1);
            cpasync16(b + TILE_B + st0, gA0l + k1);      cpasync16(b + TILE_B + st1, gA1l + k1);
            cpasync16(b + 2 * TILE_B + st0, gB0h + k1);  cpasync16(b + 2 * TILE_B + st1, gB1h + k1);
            cpasync16(b + 3 * TILE_B + st0, gB0l + k1);  cpasync16(b + 3 * TILE_B + st1, gB1l + k1);
        }
        CP_COMMIT();

        const uint32_t buf = smb + bufIdx * BUF_B;
        const uint32_t aHr = buf + aRow;
        const uint32_t aLr = aHr + TILE_B;
        const uint32_t bHr = buf + 2 * TILE_B;
        const uint32_t bLr = buf + 3 * TILE_B;

        #pragma unroll
        for (int kk = 0; kk < 2; ++kk) {
            uint32_t bh4[2][4], bl4[2][4];
            #pragma unroll
            for (int p = 0; p < 2; ++p) {
                ldsm_x4(bh4[p], bHr + bRowP[p] + chB[kk]);
                ldsm_x4(bl4[p], bLr + bRowP[p] + chB[kk]);
            }
            uint32_t a[4][4];
            #pragma unroll
            for (int mt = 0; mt < 4; ++mt)
                ldsm_x4(a[mt], aHr + mt * 1024 + chA[kk]);

            // sweep 1: Ah * Bh  (each acc touched once per sweep)
            #pragma unroll
            for (int nt = 0; nt < 4; ++nt) {
                const uint32_t* bp = &bh4[nt >> 1][(nt & 1) * 2];
                #pragma unroll
                for (int mt = 0; mt < 4; ++mt)
                    mma_bf16(acc[mt][nt], a[mt], bp);
            }
            // sweep 2: Ah * Bl
            #pragma unroll
            for (int nt = 0; nt < 4; ++nt) {
                const uint32_t* bp = &bl4[nt >> 1][(nt & 1) * 2];
                #pragma unroll
                for (int mt = 0; mt < 4; ++mt)
                    mma_bf16(acc[mt][nt], a[mt], bp);
            }
            // sweep 3: Al * Bh
            #pragma unroll
            for (int mt = 0; mt < 4; ++mt)
                ldsm_x4(a[mt], aLr + mt * 1024 + chA[kk]);
            #pragma unroll
            for (int nt = 0; nt < 4; ++nt) {
                const uint32_t* bp = &bh4[nt >> 1][(nt & 1) * 2];
                #pragma unroll
                for (int mt = 0; mt < 4; ++mt)
                    mma_bf16(acc[mt][nt], a[mt], bp);
            }
        }

        bufIdx = (bufIdx == 2) ? 0 : bufIdx + 1;
        nextIdx = (nextIdx == 2) ? 0 : nextIdx + 1;
    }

    // ---- epilogue ----
    const int mrow = lane >> 2;
    const int ncol = (lane & 3) * 2;
    #pragma unroll
    for (int nt = 0; nt < 4; ++nt) {
        const int gn = n0 + warp_n0 + nt * 8 + ncol;
        float2 bb;
        if (mode == 0) bb = *(const float2*)&g_bqkv[gn];
        else           bb = *(const float2*)&bias[gn];
        #pragma unroll
        for (int mt = 0; mt < 4; ++mt) {
            #pragma unroll
            for (int half = 0; half < 2; ++half) {
                const int m = m0 + warp_m0 + mt * 16 + mrow + half * 8;
                float vx = acc[mt][nt][half * 2 + 0] + bb.x;
                float vy = acc[mt][nt][half * 2 + 1] + bb.y;
                if (mode == 0) {
                    const int slot = gn >> 6;
                    const int mat = slot >> 4, h = slot & 15, e = gn & 63;
                    const int b_ = m >> 11, s_ = m & (NS - 1);
                    if (mat == 0) { vx *= 0.125f; vy *= 0.125f; }
                    __nv_bfloat16* dh_ = (mat == 0 ? g_qh : mat == 1 ? g_kh : g_vh);
                    __nv_bfloat16* dl_ = (mat == 0 ? g_ql : mat == 1 ? g_kl : g_vl);
                    __nv_bfloat16 hx = __float2bfloat16(vx);
                    __nv_bfloat16 hy = __float2bfloat16(vy);
                    float lxf = vx - __bfloat162float(hx);
                    float lyf = vy - __bfloat162float(hy);
                    size_t idx = (((size_t)(b_ * NH + h)) * NS + s_) * NHD + e;
                    __nv_bfloat162 hp = __halves2bfloat162(hx, hy);
                    __nv_bfloat162 lp = __halves2bfloat162(__float2bfloat16(lxf),
                                                           __float2bfloat16(lyf));
                    *(uint32_t*)&dh_[idx] = *(uint32_t*)&hp;
                    *(uint32_t*)&dl_[idx] = *(uint32_t*)&lp;
                } else {
                    float2 v = make_float2(vx, vy);
                    *(float2*)&out[(size_t)m * NDIM + gn] = v;
                }
            }
        }
    }
}

// ---------------------------------------------------------------------------
// Flash attention, split-bf16 HMMA + cp.async double-buffered K/V stages.
// NEW in R10: accumulator-distance scheduling (held K/V frags, full sweeps),
// per-kt P packing (lower register pressure).
// ---------------------------------------------------------------------------
#define FPAD 72
#define FT   (64 * FPAD)
#define FTB  (FT * 2)                 // 9216 bytes per tile
#define FSTAGE (4 * FTB)              // 36864 bytes per KV stage
#define FSMEM  (2 * FTB + 2 * FSTAGE) // 92160 bytes

__global__ __launch_bounds__(128) void flash_mma_kernel()
{
    extern __shared__ __align__(16) char smfc[];
    const uint32_t smb = smem_to_u32(smfc);
    const uint32_t qBase0 = smb;
    const uint32_t kvBase = smb + 2 * FTB;

    const int tid = threadIdx.x, wid = tid >> 5, lane = tid & 31;
    const int qt = (int)gridDim.x - 1 - (int)blockIdx.x;
    const int bh = blockIdx.y;
    const size_t base = (size_t)bh * NS * NHD;

    int cr[4], cc[4];
    uint32_t cs[4];
    #pragma unroll
    for (int it = 0; it < 4; it++) {
        int ch = tid + it * 128;
        cr[it] = ch >> 3;
        cc[it] = (ch & 7) * 8;
        cs[it] = (cr[it] * FPAD + cc[it]) * 2;
    }

    {
        const __nv_bfloat16* qh = g_qh + base + (size_t)qt * 64 * NHD;
        const __nv_bfloat16* ql = g_ql + base + (size_t)qt * 64 * NHD;
        #pragma unroll
        for (int it = 0; it < 4; it++) {
            cpasync16(qBase0 + cs[it],       qh + cr[it] * 64 + cc[it]);
            cpasync16(qBase0 + FTB + cs[it], ql + cr[it] * 64 + cc[it]);
        }
        const __nv_bfloat16* src[4] = {g_kh + base, g_kl + base, g_vh + base, g_vl + base};
        #pragma unroll
        for (int a = 0; a < 4; a++)
            #pragma unroll
            for (int it = 0; it < 4; it++)
                cpasync16(kvBase + a * FTB + cs[it], src[a] + cr[it] * 64 + cc[it]);
        CP_COMMIT();
    }

    const int lm = lane & 15, lq = lane >> 4;
    const int l8 = lane & 7;
    const int sel1 = (lane >> 3) & 1;
    const int sel2 = lane >> 4;
    const int r_  = lane >> 2;
    const int qc  = lane & 3;

    const uint32_t aBaseH = qBase0 + ((wid * 16 + lm) * FPAD + lq * 8) * 2;
    const uint32_t aBaseL = aBaseH + FTB;
    const uint32_t kOff = ((sel2 * 8 + l8) * FPAD + sel1 * 8) * 2;
    const uint32_t vOff = ((sel1 * 8 + l8) * FPAD + sel2 * 8) * 2;

    float cO[8][4];
    #pragma unroll
    for (int i = 0; i < 8; i++)
        #pragma unroll
        for (int j = 0; j < 4; j++) cO[i][j] = 0.0f;
    float m0r = -1e30f, m1r = -1e30f, l0 = 0.0f, l1 = 0.0f;

    for (int j = 0; j <= qt; ++j) {
        CP_WAIT(0);
        __syncthreads();

        if (j < qt) {
            const uint32_t sb = kvBase + ((j + 1) & 1) * FSTAGE;
            const size_t off = base + (size_t)(j + 1) * 64 * NHD;
            const __nv_bfloat16* src[4] = {g_kh + off, g_kl + off, g_vh + off, g_vl + off};
            #pragma unroll
            for (int a = 0; a < 4; a++)
                #pragma unroll
                for (int it = 0; it < 4; it++)
                    cpasync16(sb + a * FTB + cs[it], src[a] + cr[it] * 64 + cc[it]);
            CP_COMMIT();
        }

        const uint32_t stage = kvBase + (j & 1) * FSTAGE;
        const uint32_t kBaseH = stage + kOff;
        const uint32_t kBaseL = stage + FTB + kOff;
        const uint32_t vBaseH = stage + 2 * FTB + vOff;
        const uint32_t vBaseL = stage + 3 * FTB + vOff;

        float c[8][4];
        #pragma unroll
        for (int i = 0; i < 8; i++)
            #pragma unroll
            for (int q = 0; q < 4; q++) c[i][q] = 0.0f;

        // ---- scores: sweeps (aH*Kh, aL*Kh, aH*Kl), K frags held ----
        #pragma unroll
        for (int kt = 0; kt < 4; ++kt) {
            uint32_t aH[4], aL[4], bK[4][4];
            ldsm_x4(aH, aBaseH + kt * 16 * 2);
            ldsm_x4(aL, aBaseL + kt * 16 * 2);
            #pragma unroll
            for (int np = 0; np < 4; ++np)
                ldsm_x4(bK[np], kBaseH + (np * 16 * FPAD + kt * 16) * 2);
            #pragma unroll
            for (int np = 0; np < 4; ++np) {
                mma_bf16(c[2 * np],     aH, bK[np]);
                mma_bf16(c[2 * np + 1], aH, bK[np] + 2);
            }
            #pragma unroll
            for (int np = 0; np < 4; ++np) {
                mma_bf16(c[2 * np],     aL, bK[np]);
                mma_bf16(c[2 * np + 1], aL, bK[np] + 2);
            }
            #pragma unroll
            for (int np = 0; np < 4; ++np)
                ldsm_x4(bK[np], kBaseL + (np * 16 * FPAD + kt * 16) * 2);
            #pragma unroll
            for (int np = 0; np < 4; ++np) {
                mma_bf16(c[2 * np],     aH, bK[np]);
                mma_bf16(c[2 * np + 1], aH, bK[np] + 2);
            }
        }

        if (j == qt) {
            const int row0 = wid * 16 + r_;
            #pragma unroll
            for (int n8 = 0; n8 < 8; ++n8) {
                const int col = n8 * 8 + qc * 2;
                if (col     > row0)     c[n8][0] = -1e30f;
                if (col + 1 > row0)     c[n8][1] = -1e30f;
                if (col     > row0 + 8) c[n8][2] = -1e30f;
                if (col + 1 > row0 + 8) c[n8][3] = -1e30f;
            }
        }

        float mt0 = -1e30f, mt1 = -1e30f;
        #pragma unroll
        for (int n8 = 0; n8 < 8; ++n8) {
            mt0 = fmaxf(mt0, fmaxf(c[n8][0], c[n8][1]));
            mt1 = fmaxf(mt1, fmaxf(c[n8][2], c[n8][3]));
        }
        mt0 = fmaxf(mt0, __shfl_xor_sync(0xffffffffu, mt0, 1));
        mt0 = fmaxf(mt0, __shfl_xor_sync(0xffffffffu, mt0, 2));
        mt1 = fmaxf(mt1, __shfl_xor_sync(0xffffffffu, mt1, 1));
        mt1 = fmaxf(mt1, __shfl_xor_sync(0xffffffffu, mt1, 2));
        const float mn0 = fmaxf(m0r, mt0);
        const float mn1 = fmaxf(m1r, mt1);
        const float al0 = __expf(m0r - mn0);
        const float al1 = __expf(m1r - mn1);
        float s0 = 0.0f, s1 = 0.0f;
        #pragma unroll
        for (int n8 = 0; n8 < 8; ++n8) {
            c[n8][0] = __expf(c[n8][0] - mn0); s0 += c[n8][0];
            c[n8][1] = __expf(c[n8][1] - mn0); s0 += c[n8][1];
            c[n8][2] = __expf(c[n8][2] - mn1); s1 += c[n8][2];
            c[n8][3] = __expf(c[n8][3] - mn1); s1 += c[n8][3];
        }
        s0 += __shfl_xor_sync(0xffffffffu, s0, 1);
        s0 += __shfl_xor_sync(0xffffffffu, s0, 2);
        s1 += __shfl_xor_sync(0xffffffffu, s1, 1);
        s1 += __shfl_xor_sync(0xffffffffu, s1, 2);
        l0 = l0 * al0 + s0;  m0r = mn0;
        l1 = l1 * al1 + s1;  m1r = mn1;
        #pragma unroll
        for (int n8 = 0; n8 < 8; ++n8) {
            cO[n8][0] *= al0; cO[n8][1] *= al0;
            cO[n8][2] *= al1; cO[n8][3] *= al1;
        }

        // ---- PV: per-kt P packing + sweep scheduling (pH*Vh, pL*Vh, pH*Vl) ----
        #pragma unroll
        for (int kt = 0; kt < 4; ++kt) {
            const int ja = 2 * kt, jb = 2 * kt + 1;
            uint32_t pH[4], pL[4];
            {
                float h00 = __bfloat162float(__float2bfloat16(c[ja][0]));
                float h01 = __bfloat162float(__float2bfloat16(c[ja][1]));
                pH[0] = pack_bf2(c[ja][0], c[ja][1]);
                pL[0] = pack_bf2(c[ja][0] - h00, c[ja][1] - h01);
                float h10 = __bfloat162float(__float2bfloat16(c[ja][2]));
                float h11 = __bfloat162float(__float2bfloat16(c[ja][3]));
                pH[1] = pack_bf2(c[ja][2], c[ja][3]);
                pL[1] = pack_bf2(c[ja][2] - h10, c[ja][3] - h11);
                float g00 = __bfloat162float(__float2bfloat16(c[jb][0]));
                float g01 = __bfloat162float(__float2bfloat16(c[jb][1]));
                pH[2] = pack_bf2(c[jb][0], c[jb][1]);
                pL[2] = pack_bf2(c[jb][0] - g00, c[jb][1] - g01);
                float g10 = __bfloat162float(__float2bfloat16(c[jb][2]));
                float g11 = __bfloat162float(__float2bfloat16(c[jb][3]));
                pH[3] = pack_bf2(c[jb][2], c[jb][3]);
                pL[3] = pack_bf2(c[jb][2] - g10, c[jb][3] - g11);
            }
            uint32_t bV[4][4];
            #pragma unroll
            for (int np = 0; np < 4; ++np)
                ldsm_x4_t(bV[np], vBaseH + (kt * 16 * FPAD + np * 16) * 2);
            #pragma unroll
            for (int np = 0; np < 4; ++np) {
                mma_bf16(cO[2 * np],     pH, bV[np]);
                mma_bf16(cO[2 * np + 1], pH, bV[np] + 2);
            }
            #pragma unroll
            for (int np = 0; np < 4; ++np) {
                mma_bf16(cO[2 * np],     pL, bV[np]);
                mma_bf16(cO[2 * np + 1], pL, bV[np] + 2);
            }
            #pragma unroll
            for (int np = 0; np < 4; ++np)
                ldsm_x4_t(bV[np], vBaseL + (kt * 16 * FPAD + np * 16) * 2);
            #pragma unroll
            for (int np = 0; np < 4; ++np) {
                mma_bf16(cO[2 * np],     pH, bV[np]);
                mma_bf16(cO[2 * np + 1], pH, bV[np] + 2);
            }
        }
    }

    const int b_ = bh >> 4, h = bh & 15;
    const float i0 = 1.0f / l0, i1 = 1.0f / l1;
    const int mrow0 = qt * 64 + wid * 16 + r_;
    #pragma unroll
    for (int n8 = 0; n8 < 8; ++n8) {
        const int e = n8 * 8 + qc * 2;
        #pragma unroll
        for (int half = 0; half < 2; ++half) {
            const float inv = half ? i1 : i0;
            const float vx = cO[n8][half * 2 + 0] * inv;
            const float vy = cO[n8][half * 2 + 1] * inv;
            const int m = mrow0 + half * 8;
            __nv_bfloat16 hx = __float2bfloat16(vx);
            __nv_bfloat16 hy = __float2bfloat16(vy);
            __nv_bfloat162 hp = __halves2bfloat162(hx, hy);
            __nv_bfloat162 lp = __halves2bfloat162(
                __float2bfloat16(vx - __bfloat162float(hx)),
                __float2bfloat16(vy - __bfloat162float(hy)));
            size_t idx = ((size_t)b_ * NS + m) * NDIM + h * 64 + e;
            *(uint32_t*)&g_oh[idx] = *(uint32_t*)&hp;
            *(uint32_t*)&g_ol[idx] = *(uint32_t*)&lp;
        }
    }
}

// ---------------------------------------------------------------------------
extern "C" void kernel_launch(void* const* d_in, const int* in_sizes, int n_in,
                              void* d_out, int out_size)
{
    const float* x  = (const float*)d_in[0];
    const float* Wq = (const float*)d_in[1];
    const float* bq = (const float*)d_in[2];
    const float* Wk = (const float*)d_in[3];
    const float* bk = (const float*)d_in[4];
    const float* Wv = (const float*)d_in[5];
    const float* bv = (const float*)d_in[6];
    const float* Wo = (const float*)d_in[7];
    const float* bo = (const float*)d_in[8];
    float* out = (float*)d_out;

    cudaFuncSetAttribute(flash_mma_kernel,
                         cudaFuncAttributeMaxDynamicSharedMemorySize, FSMEM);
    cudaFuncSetAttribute(gemm_mma_kernel,
                         cudaFuncAttributeMaxDynamicSharedMemorySize, GSMEM);

    __nv_bfloat162 *xh2, *xl2;
    cudaGetSymbolAddress((void**)&xh2, g_xh);
    cudaGetSymbolAddress((void**)&xl2, g_xl);

    const int n4 = NM * NDIM / 4;
    split_kernel<<<n4 / 256, 256>>>((const float4*)x, xh2, xl2, n4);
    qkv_w_transpose<<<dim3(32, 2, 48), dim3(32, 32)>>>(Wq, Wk, Wv, bq, bk, bv);
    wo_transpose<<<dim3(32, 32), dim3(32, 32)>>>(Wo);

    gemm_mma_kernel<<<dim3(NM / 128, NQKV / 128), 256, GSMEM>>>(nullptr, nullptr, 0);
    flash_mma_kernel<<<dim3(NS / 64, NB * NH), 128, FSMEM>>>();
    gemm_mma_kernel<<<dim3(NM / 128, NDIM / 128), 256, GSMEM>>>(bo, out, 1);
}